// round 11
// baseline (speedup 1.0000x reference)
#include <cuda_runtime.h>
#include <cuda_fp16.h>
#include <math.h>
#include <stdint.h>

#define EPSF 1e-6f

// Problem constants: B=4, S=1024, D=1024, H=16, DH=64, F=4096, M=B*S=4096
__device__ float g_xn  [4096 * 1024 / 2];    // xn (half)
__device__ float g_qkv [6 * 1024 * 1024];    // q|k|v (half, 3 x 4M halves); v->attn_out
__device__ float g_att [2 * 1024 * 1024];    // attn_out (half)
__device__ float g_res [4096 * 1024];        // residual after attention (f32)
__device__ float g_big [16 * 1024 * 1024];   // h1/h2 (half, 2 x 16M halves)
__device__ float g_wt  [8 * 1024 * 1024];    // transposed half weights (16M halves)
__device__ float g_bias[16384];              // b_qkv (3072) @0, b12 (8192) @4096

// ---------------------------------------------------------------------------
// Helpers
// ---------------------------------------------------------------------------
__device__ __forceinline__ void cp_async16(uint32_t dst, const void* src)
{
    asm volatile("cp.async.cg.shared.global [%0], [%1], 16;\n" :: "r"(dst), "l"(src));
}
__device__ __forceinline__ void cp_commit() { asm volatile("cp.async.commit_group;\n"); }
__device__ __forceinline__ void cp_wait0()  { asm volatile("cp.async.wait_group 0;\n"); }

__device__ __forceinline__ uint32_t smem_u32(const void* p)
{
    uint32_t a;
    asm("{ .reg .u64 t; cvta.to.shared.u64 t, %1; cvt.u32.u64 %0, t; }" : "=r"(a) : "l"(p));
    return a;
}
__device__ __forceinline__ void ldsm4(uint32_t& r0, uint32_t& r1, uint32_t& r2, uint32_t& r3,
                                      uint32_t a)
{
    asm volatile("ldmatrix.sync.aligned.m8n8.x4.shared.b16 {%0,%1,%2,%3}, [%4];"
                 : "=r"(r0), "=r"(r1), "=r"(r2), "=r"(r3) : "r"(a));
}
__device__ __forceinline__ void ldsm4_t(uint32_t& r0, uint32_t& r1, uint32_t& r2, uint32_t& r3,
                                        uint32_t a)
{
    asm volatile("ldmatrix.sync.aligned.m8n8.x4.trans.shared.b16 {%0,%1,%2,%3}, [%4];"
                 : "=r"(r0), "=r"(r1), "=r"(r2), "=r"(r3) : "r"(a));
}
__device__ __forceinline__ void mma_h(float c[4], const uint32_t a[4], const uint32_t b[2])
{
    asm volatile(
        "mma.sync.aligned.m16n8k16.row.col.f32.f16.f16.f32 "
        "{%0,%1,%2,%3}, {%4,%5,%6,%7}, {%8,%9}, {%0,%1,%2,%3};\n"
        : "+f"(c[0]), "+f"(c[1]), "+f"(c[2]), "+f"(c[3])
        : "r"(a[0]), "r"(a[1]), "r"(a[2]), "r"(a[3]), "r"(b[0]), "r"(b[1]));
}

// ---------------------------------------------------------------------------
// fp16 tensor-core GEMM (round-10 proven: BM=128 BN=128 BK=64, 8 warps,
// 64x32 warp tiles, double buffer, wait_group 0, stride 72 halves).
// MODE 0: half out, segmented columns (fused QKV / fused FFN).
// MODE 1: float out = acc + bias + Res (ldc = segStride).
// ---------------------------------------------------------------------------
#define GE_STAGE (128 * 72 * 2)                  // 18432 B per matrix per stage
#define GE_SMEM  (4 * GE_STAGE)                  // 73728 B

template <int MODE>
__global__ __launch_bounds__(256) void gemm_h(
    const __half* __restrict__ A, const __half* __restrict__ B,
    const float* __restrict__ bias, const float* __restrict__ Res,
    void* __restrict__ Cv, int K, int lda, int ldb, int segW, int segStride)
{
    extern __shared__ __half gsm[];
    const uint32_t sA = smem_u32(gsm);
    const uint32_t sB = sA + 2 * GE_STAGE;

    const int t    = threadIdx.x;
    const int lane = t & 31;
    const int warp = t >> 5;
    const size_t m0 = (size_t)blockIdx.y * 128;
    const size_t n0 = (size_t)blockIdx.x * 128;
    const int wm = (warp >> 2) * 64;
    const int wn = (warp & 3) * 32;

    uint32_t dOff[4];
    const __half* aS[4];
    const __half* bS[4];
    #pragma unroll
    for (int i = 0; i < 4; i++) {
        const int idx = t + 256 * i;
        const int row = idx >> 3, c = idx & 7;
        dOff[i] = (uint32_t)(row * 72 + c * 8) * 2;
        aS[i] = A + (m0 + row) * lda + c * 8;
        bS[i] = B + (n0 + row) * ldb + c * 8;
    }

    const int lq = lane >> 3, lr = lane & 7;
    uint32_t aAddr[4], bAddr[2];
    #pragma unroll
    for (int mt = 0; mt < 4; mt++)
        aAddr[mt] = sA + (uint32_t)((wm + mt * 16 + ((lq & 1) << 3) + lr) * 72 + ((lq >> 1) << 3)) * 2;
    #pragma unroll
    for (int p = 0; p < 2; p++)
        bAddr[p] = sB + (uint32_t)((wn + p * 16 + ((lq >> 1) << 3) + lr) * 72 + ((lq & 1) << 3)) * 2;

    float acc[4][4][4];
    #pragma unroll
    for (int mt = 0; mt < 4; mt++)
        #pragma unroll
        for (int nt = 0; nt < 4; nt++)
            #pragma unroll
            for (int i = 0; i < 4; i++) acc[mt][nt][i] = 0.f;

    #pragma unroll
    for (int i = 0; i < 4; i++) {
        cp_async16(sA + dOff[i], aS[i]);
        cp_async16(sB + dOff[i], bS[i]);
    }
    cp_commit();

    const int nIter = K >> 6;
    for (int it = 0; it < nIter; ++it) {
        cp_wait0();
        __syncthreads();
        const int buf = it & 1;
        if (it + 1 < nIter) {
            const int k0 = (it + 1) << 6;
            const uint32_t off = (buf ^ 1) * GE_STAGE;
            #pragma unroll
            for (int i = 0; i < 4; i++) {
                cp_async16(sA + off + dOff[i], aS[i] + k0);
                cp_async16(sB + off + dOff[i], bS[i] + k0);
            }
            cp_commit();
        }
        const uint32_t off = buf * GE_STAGE;
        #pragma unroll
        for (int ks = 0; ks < 4; ks++) {
            const uint32_t kB = ks * 32;
            uint32_t af[4][4];
            #pragma unroll
            for (int mt = 0; mt < 4; mt++)
                ldsm4(af[mt][0], af[mt][1], af[mt][2], af[mt][3], aAddr[mt] + off + kB);
            uint32_t bf[4][2];
            #pragma unroll
            for (int p = 0; p < 2; p++)
                ldsm4(bf[2 * p][0], bf[2 * p][1], bf[2 * p + 1][0], bf[2 * p + 1][1],
                      bAddr[p] + off + kB);
            #pragma unroll
            for (int mt = 0; mt < 4; mt++)
                #pragma unroll
                for (int nt = 0; nt < 4; nt++)
                    mma_h(acc[mt][nt], af[mt], bf[nt]);
        }
        __syncthreads();
    }

    if (MODE == 0) {
        const int seg  = (int)(n0 / segW);
        const int ncol = (int)(n0 % segW);
        __half* Cb = (__half*)Cv + (size_t)seg * segStride + m0 * segW + ncol;
        #pragma unroll
        for (int mt = 0; mt < 4; mt++) {
            const int r0 = wm + mt * 16 + (lane >> 2);
            #pragma unroll
            for (int nt = 0; nt < 4; nt++) {
                const int c = wn + nt * 8 + (lane & 3) * 2;
                const float b0 = bias[n0 + c], b1 = bias[n0 + c + 1];
                *(__half2*)(Cb + (size_t)r0 * segW + c) =
                    __floats2half2_rn(acc[mt][nt][0] + b0, acc[mt][nt][1] + b1);
                *(__half2*)(Cb + (size_t)(r0 + 8) * segW + c) =
                    __floats2half2_rn(acc[mt][nt][2] + b0, acc[mt][nt][3] + b1);
            }
        }
    } else {
        const int ldc = segStride;
        float* Cb = (float*)Cv + m0 * ldc + n0;
        const float* Rb = Res + m0 * ldc + n0;
        #pragma unroll
        for (int mt = 0; mt < 4; mt++) {
            const int r0 = wm + mt * 16 + (lane >> 2);
            #pragma unroll
            for (int nt = 0; nt < 4; nt++) {
                const int c = wn + nt * 8 + (lane & 3) * 2;
                const float b0 = bias[n0 + c], b1 = bias[n0 + c + 1];
                float2 ra = *(const float2*)(Rb + (size_t)r0 * ldc + c);
                float2 rb = *(const float2*)(Rb + (size_t)(r0 + 8) * ldc + c);
                *(float2*)(Cb + (size_t)r0 * ldc + c) =
                    make_float2(acc[mt][nt][0] + b0 + ra.x, acc[mt][nt][1] + b1 + ra.y);
                *(float2*)(Cb + (size_t)(r0 + 8) * ldc + c) =
                    make_float2(acc[mt][nt][2] + b0 + rb.x, acc[mt][nt][3] + b1 + rb.y);
            }
        }
    }
}

// ---------------------------------------------------------------------------
// Bias concat
// ---------------------------------------------------------------------------
__global__ __launch_bounds__(256) void concat_bias(
    float* __restrict__ dst, const float* __restrict__ bq, const float* __restrict__ bk,
    const float* __restrict__ bv, const float* __restrict__ b1, const float* __restrict__ b2)
{
    const int i = blockIdx.x * 256 + threadIdx.x;
    if (i < 1024)       dst[i] = bq[i];
    else if (i < 2048)  dst[i] = bk[i - 1024];
    else if (i < 3072)  dst[i] = bv[i - 2048];
    else if (i < 3072 + 4096)  dst[1024 + i] = b1[i - 3072];
    else if (i < 3072 + 8192)  dst[1024 + i] = b2[i - 7168];
}

// ---------------------------------------------------------------------------
// Batched transpose f32 -> half: 4 independent sources, z selects source.
// ---------------------------------------------------------------------------
__global__ __launch_bounds__(256) void trans_f2h4(
    const float* __restrict__ i0, const float* __restrict__ i1,
    const float* __restrict__ i2, const float* __restrict__ i3,
    __half* __restrict__ o0, __half* __restrict__ o1,
    __half* __restrict__ o2, __half* __restrict__ o3, int R, int C)
{
    __shared__ float tile[32][33];
    const float* in;
    __half* out;
    switch (blockIdx.z) {
        case 0: in = i0; out = o0; break;
        case 1: in = i1; out = o1; break;
        case 2: in = i2; out = o2; break;
        default: in = i3; out = o3; break;
    }
    const int c0 = blockIdx.x * 32, r0 = blockIdx.y * 32;
    const int tx = threadIdx.x & 31, ty = threadIdx.x >> 5;
    #pragma unroll
    for (int i = 0; i < 4; i++)
        tile[ty + 8 * i][tx] = in[(size_t)(r0 + ty + 8 * i) * C + c0 + tx];
    __syncthreads();
    #pragma unroll
    for (int i = 0; i < 4; i++)
        out[(size_t)(c0 + ty + 8 * i) * R + r0 + tx] = __float2half_rn(tile[tx][ty + 8 * i]);
}

// ---------------------------------------------------------------------------
// Flash attention fp16: V consumed directly from [s][d] layout via
// ldmatrix.trans (no pre-transpose pass).
// smem: K[128][72]h | V[128][72]h | P[128][136]h (P doubles as Q staging)
// ---------------------------------------------------------------------------
#define FL_SMEM ((128 * 72 + 128 * 72 + 128 * 136) * 2)

__global__ __launch_bounds__(256) void flash_h(
    const __half* __restrict__ q, const __half* __restrict__ k,
    const __half* __restrict__ v, __half* __restrict__ out)
{
    extern __shared__ __half smh[];
    const uint32_t sK = smem_u32(smh);
    const uint32_t sV = sK + 128 * 72 * 2;
    const uint32_t sP = sV + 128 * 72 * 2;
    __half* sPh = smh + 128 * 72 + 128 * 72;

    const int t = threadIdx.x;
    const int lane = t & 31, warp = t >> 5;
    const int lq = lane >> 3, lr = lane & 7;
    const int bh = blockIdx.y, b = bh >> 4, h = bh & 15;
    const int q0 = blockIdx.x * 128;
    const int wm = warp * 16;

    const __half* qb = q + ((size_t)b * 1024 + q0) * 1024 + h * 64;
    const __half* kb = k + ((size_t)b << 20) + h * 64;
    const __half* vb = v + ((size_t)b << 20) + h * 64;

    {
        #pragma unroll
        for (int i = 0; i < 4; i++) {
            const int idx = t + 256 * i;
            const int row = idx >> 3, c = idx & 7;
            cp_async16(sP + (uint32_t)(row * 72 + c * 8) * 2, qb + (size_t)row * 1024 + c * 8);
        }
    }
    cp_commit(); cp_wait0(); __syncthreads();

    uint32_t qf[4][4];
    {
        const uint32_t a0 = sP + (uint32_t)((wm + ((lq & 1) << 3) + lr) * 72 + ((lq >> 1) << 3)) * 2;
        #pragma unroll
        for (int ks = 0; ks < 4; ks++)
            ldsm4(qf[ks][0], qf[ks][1], qf[ks][2], qf[ks][3], a0 + ks * 32);
    }
    __syncthreads();

    float o[8][4];
    #pragma unroll
    for (int i = 0; i < 8; i++)
        #pragma unroll
        for (int j = 0; j < 4; j++) o[i][j] = 0.f;
    float m0 = -1e30f, m1 = -1e30f, l0 = 0.f, l1 = 0.f;

    const uint32_t aP = sP + (uint32_t)((wm + ((lq & 1) << 3) + lr) * 136 + ((lq >> 1) << 3)) * 2;

    for (int it = 0; it < 8; ++it) {
        const int kt0 = it * 128;
        #pragma unroll
        for (int i = 0; i < 4; i++) {
            const int idx = t + 256 * i;
            const int row = idx >> 3, c = idx & 7;
            cp_async16(sK + (uint32_t)(row * 72 + c * 8) * 2,
                       kb + (size_t)(kt0 + row) * 1024 + c * 8);
            cp_async16(sV + (uint32_t)(row * 72 + c * 8) * 2,
                       vb + (size_t)(kt0 + row) * 1024 + c * 8);
        }
        cp_commit(); cp_wait0(); __syncthreads();

        float s[16][4];
        #pragma unroll
        for (int i = 0; i < 16; i++)
            #pragma unroll
            for (int j = 0; j < 4; j++) s[i][j] = 0.f;
        #pragma unroll
        for (int ks = 0; ks < 4; ks++) {
            uint32_t bf[16][2];
            #pragma unroll
            for (int p = 0; p < 8; p++) {
                const uint32_t addr =
                    sK + (uint32_t)((p * 16 + ((lq >> 1) << 3) + lr) * 72 + ((lq & 1) << 3)) * 2
                       + ks * 32;
                ldsm4(bf[2 * p][0], bf[2 * p][1], bf[2 * p + 1][0], bf[2 * p + 1][1], addr);
            }
            #pragma unroll
            for (int nt = 0; nt < 16; nt++)
                mma_h(s[nt], qf[ks], bf[nt]);
        }

        float c0v = -1e30f, c1v = -1e30f;
        #pragma unroll
        for (int nt = 0; nt < 16; nt++) {
            c0v = fmaxf(c0v, fmaxf(s[nt][0], s[nt][1]));
            c1v = fmaxf(c1v, fmaxf(s[nt][2], s[nt][3]));
        }
        c0v = fmaxf(c0v, __shfl_xor_sync(0xffffffffu, c0v, 1));
        c0v = fmaxf(c0v, __shfl_xor_sync(0xffffffffu, c0v, 2));
        c1v = fmaxf(c1v, __shfl_xor_sync(0xffffffffu, c1v, 1));
        c1v = fmaxf(c1v, __shfl_xor_sync(0xffffffffu, c1v, 2));
        const float m0n = fmaxf(m0, c0v * 0.125f);
        const float m1n = fmaxf(m1, c1v * 0.125f);
        const float cor0 = __expf(m0 - m0n);
        const float cor1 = __expf(m1 - m1n);
        m0 = m0n; m1 = m1n;
        float sum0 = 0.f, sum1 = 0.f;
        {
            __half* pr0 = sPh + (size_t)(wm + (lane >> 2)) * 136 + 2 * (lane & 3);
            __half* pr1 = pr0 + 8 * 136;
            #pragma unroll
            for (int nt = 0; nt < 16; nt++) {
                float p0 = __expf(fmaf(0.125f, s[nt][0], -m0n));
                float p1 = __expf(fmaf(0.125f, s[nt][1], -m0n));
                float p2 = __expf(fmaf(0.125f, s[nt][2], -m1n));
                float p3 = __expf(fmaf(0.125f, s[nt][3], -m1n));
                sum0 += p0 + p1; sum1 += p2 + p3;
                *(__half2*)(pr0 + nt * 8) = __floats2half2_rn(p0, p1);
                *(__half2*)(pr1 + nt * 8) = __floats2half2_rn(p2, p3);
            }
        }
        sum0 += __shfl_xor_sync(0xffffffffu, sum0, 1);
        sum0 += __shfl_xor_sync(0xffffffffu, sum0, 2);
        sum1 += __shfl_xor_sync(0xffffffffu, sum1, 1);
        sum1 += __shfl_xor_sync(0xffffffffu, sum1, 2);
        l0 = l0 * cor0 + sum0;
        l1 = l1 * cor1 + sum1;
        #pragma unroll
        for (int nt = 0; nt < 8; nt++) {
            o[nt][0] *= cor0; o[nt][1] *= cor0;
            o[nt][2] *= cor1; o[nt][3] *= cor1;
        }
        __syncwarp();

        // P @ V with V in [s][d] layout via ldmatrix.trans.
        // For each k16 slice ks2 and each 16-wide d-block p:
        //   m(lq): k = ks2*16 + (lq&1)*8 + lr,  d = p*16 + (lq>>1)*8
        #pragma unroll
        for (int ks2 = 0; ks2 < 8; ks2++) {
            uint32_t af[4];
            ldsm4(af[0], af[1], af[2], af[3], aP + ks2 * 32);
            uint32_t bf2[8][2];
            #pragma unroll
            for (int p = 0; p < 4; p++) {
                const uint32_t addr =
                    sV + (uint32_t)((ks2 * 16 + ((lq & 1) << 3) + lr) * 72
                                    + p * 16 + ((lq >> 1) << 3)) * 2;
                ldsm4_t(bf2[2 * p][0], bf2[2 * p][1], bf2[2 * p + 1][0], bf2[2 * p + 1][1], addr);
            }
            #pragma unroll
            for (int nt = 0; nt < 8; nt++)
                mma_h(o[nt], af, bf2[nt]);
        }
        __syncthreads();
    }

    const float inv0 = 1.f / l0, inv1 = 1.f / l1;
    __half* ob = out + ((size_t)b * 1024 + q0 + wm + (lane >> 2)) * 1024 + h * 64 + 2 * (lane & 3);
    #pragma unroll
    for (int nt = 0; nt < 8; nt++) {
        *(__half2*)(ob + nt * 8) = __floats2half2_rn(o[nt][0] * inv0, o[nt][1] * inv0);
        *(__half2*)(ob + 8 * 1024 + nt * 8) = __floats2half2_rn(o[nt][2] * inv1, o[nt][3] * inv1);
    }
}

// ---------------------------------------------------------------------------
// LayerNorm over D=1024, f32 in -> half out.
// ---------------------------------------------------------------------------
__global__ __launch_bounds__(256) void ln_kernel(
    const float* __restrict__ in, const float* __restrict__ sc,
    const float* __restrict__ bi, __half* __restrict__ out)
{
    const int row = blockIdx.x;
    const int t = threadIdx.x;
    const float4* x4 = (const float4*)(in + (size_t)row * 1024);
    float4 v = x4[t];
    float s  = v.x + v.y + v.z + v.w;
    float ss = v.x * v.x + v.y * v.y + v.z * v.z + v.w * v.w;
    #pragma unroll
    for (int o = 16; o; o >>= 1) {
        s  += __shfl_xor_sync(0xffffffffu, s,  o);
        ss += __shfl_xor_sync(0xffffffffu, ss, o);
    }
    __shared__ float sred[8], ssred[8];
    if ((t & 31) == 0) { sred[t >> 5] = s; ssred[t >> 5] = ss; }
    __syncthreads();
    float tot = 0.f, tots = 0.f;
    #pragma unroll
    for (int w = 0; w < 8; w++) { tot += sred[w]; tots += ssred[w]; }
    const float mean = tot * (1.f / 1024.f);
    const float var  = tots * (1.f / 1024.f) - mean * mean;
    const float inv  = rsqrtf(var + EPSF);
    float4 sv = ((const float4*)sc)[t];
    float4 bv = ((const float4*)bi)[t];
    __half2* o2 = (__half2*)(out + (size_t)row * 1024);
    o2[t * 2 + 0] = __floats2half2_rn((v.x - mean) * inv * sv.x + bv.x,
                                      (v.y - mean) * inv * sv.y + bv.y);
    o2[t * 2 + 1] = __floats2half2_rn((v.z - mean) * inv * sv.z + bv.z,
                                      (v.w - mean) * inv * sv.w + bv.w);
}

// ---------------------------------------------------------------------------
// QK-norm for q AND k in one launch (blockIdx.y selects tensor).
// ---------------------------------------------------------------------------
__global__ __launch_bounds__(256) void qknorm2_kernel(
    __half* __restrict__ q, __half* __restrict__ k,
    const float* __restrict__ qs, const float* __restrict__ qb,
    const float* __restrict__ ks, const float* __restrict__ kb)
{
    __half* base = blockIdx.y ? k : q;
    const float* sc = blockIdx.y ? ks : qs;
    const float* bi = blockIdx.y ? kb : qb;
    const int gw   = (blockIdx.x * 256 + threadIdx.x) >> 5;
    const int lane = threadIdx.x & 31;
    const int h  = gw & 15;
    const int bs = gw >> 4;
    __half2* p = (__half2*)(base + (size_t)bs * 1024 + h * 64) + lane;
    float2 v = __half22float2(*p);
    float s  = v.x + v.y;
    float ss = v.x * v.x + v.y * v.y;
    #pragma unroll
    for (int o = 16; o; o >>= 1) {
        s  += __shfl_xor_sync(0xffffffffu, s,  o);
        ss += __shfl_xor_sync(0xffffffffu, ss, o);
    }
    const float mean = s * (1.f / 64.f);
    const float var  = ss * (1.f / 64.f) - mean * mean;
    const float inv  = rsqrtf(var + EPSF);
    const float* scp = sc + h * 64 + lane * 2;
    const float* bip = bi + h * 64 + lane * 2;
    *p = __floats2half2_rn((v.x - mean) * inv * scp[0] + bip[0],
                           (v.y - mean) * inv * scp[1] + bip[1]);
}

// ---------------------------------------------------------------------------
// GeGLU: h1 <- h1 * gelu_tanh(h2), half, 4 halves/thread.
// ---------------------------------------------------------------------------
__device__ __forceinline__ float gelu_t(float x)
{
    return 0.5f * x * (1.f + tanhf(0.7978845608028654f * (x + 0.044715f * x * x * x)));
}

__global__ __launch_bounds__(256) void geglu_kernel(
    __half* __restrict__ g1, const __half* __restrict__ g2)
{
    const size_t i = (size_t)blockIdx.x * 256 + threadIdx.x;
    __half2 a0 = ((const __half2*)g1)[i * 2 + 0];
    __half2 a1 = ((const __half2*)g1)[i * 2 + 1];
    __half2 c0 = ((const __half2*)g2)[i * 2 + 0];
    __half2 c1 = ((const __half2*)g2)[i * 2 + 1];
    float2 af0 = __half22float2(a0), af1 = __half22float2(a1);
    float2 cf0 = __half22float2(c0), cf1 = __half22float2(c1);
    ((__half2*)g1)[i * 2 + 0] =
        __floats2half2_rn(af0.x * gelu_t(cf0.x), af0.y * gelu_t(cf0.y));
    ((__half2*)g1)[i * 2 + 1] =
        __floats2half2_rn(af1.x * gelu_t(cf1.x), af1.y * gelu_t(cf1.y));
}

// ---------------------------------------------------------------------------
// Launch
// ---------------------------------------------------------------------------
extern "C" void kernel_launch(void* const* d_in, const int* in_sizes, int n_in,
                              void* d_out, int out_size)
{
    (void)in_sizes; (void)n_in; (void)out_size;
    const float* x     = (const float*)d_in[0];
    const float* ln1_s = (const float*)d_in[2];
    const float* ln1_b = (const float*)d_in[3];
    const float* Wq    = (const float*)d_in[4];
    const float* bq    = (const float*)d_in[5];
    const float* Wk    = (const float*)d_in[6];
    const float* bk    = (const float*)d_in[7];
    const float* Wv    = (const float*)d_in[8];
    const float* bv    = (const float*)d_in[9];
    const float* qn_s  = (const float*)d_in[10];
    const float* qn_b  = (const float*)d_in[11];
    const float* kn_s  = (const float*)d_in[12];
    const float* kn_b  = (const float*)d_in[13];
    const float* Wo    = (const float*)d_in[14];
    const float* bo    = (const float*)d_in[15];
    const float* ln2_s = (const float*)d_in[16];
    const float* ln2_b = (const float*)d_in[17];
    const float* W1    = (const float*)d_in[18];
    const float* b1    = (const float*)d_in[19];
    const float* W2    = (const float*)d_in[20];
    const float* b2    = (const float*)d_in[21];
    const float* W3    = (const float*)d_in[22];
    const float* b3    = (const float*)d_in[23];

    void *p_xn, *p_qkv, *p_att, *p_res, *p_big, *p_wt, *p_bias;
    cudaGetSymbolAddress(&p_xn,   g_xn);
    cudaGetSymbolAddress(&p_qkv,  g_qkv);
    cudaGetSymbolAddress(&p_att,  g_att);
    cudaGetSymbolAddress(&p_res,  g_res);
    cudaGetSymbolAddress(&p_big,  g_big);
    cudaGetSymbolAddress(&p_wt,   g_wt);
    cudaGetSymbolAddress(&p_bias, g_bias);

    __half* xn  = (__half*)p_xn;
    __half* qkv = (__half*)p_qkv;
    __half* qh  = qkv;
    __half* kh  = qkv + (size_t)4194304;
    __half* vh  = qkv + (size_t)8388608;
    __half* att = (__half*)p_att;
    float*  res = (float*)p_res;
    __half* wt  = (__half*)p_wt;
    __half* h1  = (__half*)p_big;
    __half* h2  = h1 + (size_t)16777216;
    float*  bsc = (float*)p_bias;
    float* out = (float*)d_out;

    cudaFuncSetAttribute(flash_h, cudaFuncAttributeMaxDynamicSharedMemorySize, FL_SMEM);
    cudaFuncSetAttribute(gemm_h<0>, cudaFuncAttributeMaxDynamicSharedMemorySize, GE_SMEM);
    cudaFuncSetAttribute(gemm_h<1>, cudaFuncAttributeMaxDynamicSharedMemorySize, GE_SMEM);

    const size_t MB1 = 1024 * 1024;
    __half* wqt = wt;                 // [3072][1024] concatenated q|k|v
    __half* wot = wt + 3 * MB1;
    __half* w1t = wt + 4 * MB1;       // [8192][1024] concatenated w1|w2
    __half* w3t = wt + 12 * MB1;

    // 0. weight transposes -> half, batched; bias concat
    trans_f2h4<<<dim3(32, 32, 4), 256>>>(Wq, Wk, Wv, Wo,
                                         wqt, wqt + 1 * MB1, wqt + 2 * MB1, wot, 1024, 1024);
    trans_f2h4<<<dim3(128, 32, 2), 256>>>(W1, W2, W1, W2,
                                          w1t, w1t + 4 * MB1, w1t, w1t + 4 * MB1, 1024, 4096);
    trans_f2h4<<<dim3(32, 128, 1), 256>>>(W3, W3, W3, W3, w3t, w3t, w3t, w3t, 4096, 1024);
    concat_bias<<<44, 256>>>(bsc, bq, bk, bv, b1, b2);

    // 1. LN1 -> xn (half)
    ln_kernel<<<4096, 256>>>(x, ln1_s, ln1_b, xn);

    // 2. fused QKV projection (M=4096, N=3072, K=1024) -> q|k|v segments
    gemm_h<0><<<dim3(24, 32), 256, GE_SMEM>>>(xn, wqt, bsc, nullptr, qkv,
                                              1024, 1024, 1024, 1024, 4194304);

    // 3. QK-norm for q and k (one launch)
    qknorm2_kernel<<<dim3(8192, 2), 256>>>(qh, kh, qn_s, qn_b, kn_s, kn_b);

    // 4. flash attention (V consumed in-place) -> att
    flash_h<<<dim3(8, 64), 256, FL_SMEM>>>(qh, kh, vh, att);

    // 5. O projection + residual (f32 out)
    gemm_h<1><<<dim3(8, 32), 256, GE_SMEM>>>(att, wot, bo, x, res, 1024, 1024, 1024, 0, 1024);

    // 6. LN2 -> xn (half)
    ln_kernel<<<4096, 256>>>(res, ln2_s, ln2_b, xn);

    // 7. fused FFN up (M=4096, N=8192, K=1024) -> h1 | h2
    gemm_h<0><<<dim3(64, 32), 256, GE_SMEM>>>(xn, w1t, bsc + 4096, nullptr, h1,
                                              1024, 1024, 1024, 4096, 16777216);

    // 8. GeGLU
    geglu_kernel<<<16384, 256>>>(h1, h2);

    // 9. Down projection + residual -> d_out (M=4096, N=1024, K=4096)
    gemm_h<1><<<dim3(8, 32), 256, GE_SMEM>>>(h1, w3t, b3, res, out, 4096, 4096, 4096, 0, 1024);
}

// round 13
// speedup vs baseline: 1.0179x; 1.0179x over previous
#include <cuda_runtime.h>
#include <cuda_fp16.h>
#include <math.h>
#include <stdint.h>

#define EPSF 1e-6f

// Problem constants: B=4, S=1024, D=1024, H=16, DH=64, F=4096, M=B*S=4096
__device__ float g_xn  [4096 * 1024 / 2];    // xn (half)
__device__ float g_qkv [6 * 1024 * 1024];    // q|k|v (half, 3 x 4M halves)
__device__ float g_att [2 * 1024 * 1024];    // attn_out (half)
__device__ float g_res [4096 * 1024];        // residual after attention (f32)
__device__ float g_big [16 * 1024 * 1024];   // h1/h2 (half, 2 x 16M halves)
__device__ float g_wt  [8 * 1024 * 1024];    // half weights, native [K][N] (16M halves)
__device__ float g_bias[16384];              // b_qkv (3072) @0, b12 (8192) @4096

// ---------------------------------------------------------------------------
// Helpers
// ---------------------------------------------------------------------------
__device__ __forceinline__ void cp_async16(uint32_t dst, const void* src)
{
    asm volatile("cp.async.cg.shared.global [%0], [%1], 16;\n" :: "r"(dst), "l"(src));
}
__device__ __forceinline__ void cp_commit() { asm volatile("cp.async.commit_group;\n"); }
__device__ __forceinline__ void cp_wait0()  { asm volatile("cp.async.wait_group 0;\n"); }

__device__ __forceinline__ uint32_t smem_u32(const void* p)
{
    uint32_t a;
    asm("{ .reg .u64 t; cvta.to.shared.u64 t, %1; cvt.u32.u64 %0, t; }" : "=r"(a) : "l"(p));
    return a;
}
__device__ __forceinline__ void ldsm4(uint32_t& r0, uint32_t& r1, uint32_t& r2, uint32_t& r3,
                                      uint32_t a)
{
    asm volatile("ldmatrix.sync.aligned.m8n8.x4.shared.b16 {%0,%1,%2,%3}, [%4];"
                 : "=r"(r0), "=r"(r1), "=r"(r2), "=r"(r3) : "r"(a));
}
__device__ __forceinline__ void ldsm4_t(uint32_t& r0, uint32_t& r1, uint32_t& r2, uint32_t& r3,
                                        uint32_t a)
{
    asm volatile("ldmatrix.sync.aligned.m8n8.x4.trans.shared.b16 {%0,%1,%2,%3}, [%4];"
                 : "=r"(r0), "=r"(r1), "=r"(r2), "=r"(r3) : "r"(a));
}
__device__ __forceinline__ void mma_h(float c[4], const uint32_t a[4], const uint32_t b[2])
{
    asm volatile(
        "mma.sync.aligned.m16n8k16.row.col.f32.f16.f16.f32 "
        "{%0,%1,%2,%3}, {%4,%5,%6,%7}, {%8,%9}, {%0,%1,%2,%3};\n"
        : "+f"(c[0]), "+f"(c[1]), "+f"(c[2]), "+f"(c[3])
        : "r"(a[0]), "r"(a[1]), "r"(a[2]), "r"(a[3]), "r"(b[0]), "r"(b[1]));
}

// ---------------------------------------------------------------------------
// fp16 tensor-core GEMM: BM=128 BN=128 BK=64, 8 warps (64x32 warp tiles),
// double buffer, wait_group 0. A [M][K] (stride-72 smem rows, plain ldsm);
// B native [K][N] (stride-136 smem rows, fragments via ldmatrix.trans).
// MODE 0: half out, segmented columns (fused QKV / fused FFN).
// MODE 1: float out = acc + bias + Res (ldc = segStride).
// ---------------------------------------------------------------------------
#define GE_A_STAGE (128 * 72 * 2)                // 18432 B
#define GE_B_STAGE (64 * 136 * 2)                // 17408 B
#define GE_SMEM (2 * (GE_A_STAGE + GE_B_STAGE))  // 71680 B

template <int MODE>
__global__ __launch_bounds__(256) void gemm_h(
    const __half* __restrict__ A, const __half* __restrict__ B,
    const float* __restrict__ bias, const float* __restrict__ Res,
    void* __restrict__ Cv, int K, int lda, int ldb, int segW, int segStride)
{
    extern __shared__ __half gsm[];
    const uint32_t sA = smem_u32(gsm);
    const uint32_t sB = sA + 2 * GE_A_STAGE;

    const int t    = threadIdx.x;
    const int lane = t & 31;
    const int warp = t >> 5;
    const size_t m0 = (size_t)blockIdx.y * 128;
    const size_t n0 = (size_t)blockIdx.x * 128;
    const int wm = (warp >> 2) * 64;
    const int wn = (warp & 3) * 32;

    // cp.async maps:
    // A: 128 rows x 8 chunks (16B each) -> 4 chunks/thread
    // B: 64 rows x 16 chunks (16B each) -> 4 chunks/thread  (FIXED from round 12)
    uint32_t dA[4], dB[4];
    const __half* aS[4];
    const __half* bS[4];
    #pragma unroll
    for (int i = 0; i < 4; i++) {
        const int ia = t + 256 * i;
        const int rowA = ia >> 3, cA = ia & 7;
        dA[i] = (uint32_t)(rowA * 72 + cA * 8) * 2;
        aS[i] = A + (m0 + rowA) * lda + cA * 8;
        const int ib = t + 256 * i;
        const int rowB = ib >> 4, cB = ib & 15;
        dB[i] = (uint32_t)(rowB * 136 + cB * 8) * 2;
        bS[i] = B + (size_t)rowB * ldb + n0 + cB * 8;
    }

    const int lq = lane >> 3, lr = lane & 7;
    uint32_t aAddr[4];
    #pragma unroll
    for (int mt = 0; mt < 4; mt++)
        aAddr[mt] = sA + (uint32_t)((wm + mt * 16 + ((lq & 1) << 3) + lr) * 72 + ((lq >> 1) << 3)) * 2;
    // B trans-frag base: k-row = (lq&1)*8 + lr, n-col = wn + (lq>>1)*8
    const uint32_t bBase = sB + (uint32_t)((((lq & 1) << 3) + lr) * 136 + wn + ((lq >> 1) << 3)) * 2;

    float acc[4][4][4];
    #pragma unroll
    for (int mt = 0; mt < 4; mt++)
        #pragma unroll
        for (int nt = 0; nt < 4; nt++)
            #pragma unroll
            for (int i = 0; i < 4; i++) acc[mt][nt][i] = 0.f;

    #pragma unroll
    for (int i = 0; i < 4; i++) {
        cp_async16(sA + dA[i], aS[i]);
        cp_async16(sB + dB[i], bS[i]);
    }
    cp_commit();

    const int nIter = K >> 6;
    for (int it = 0; it < nIter; ++it) {
        cp_wait0();
        __syncthreads();
        const int buf = it & 1;
        if (it + 1 < nIter) {
            const int k0 = (it + 1) << 6;
            const uint32_t offA = (buf ^ 1) * GE_A_STAGE;
            const uint32_t offB = (buf ^ 1) * GE_B_STAGE;
            #pragma unroll
            for (int i = 0; i < 4; i++) {
                cp_async16(sA + offA + dA[i], aS[i] + k0);
                cp_async16(sB + offB + dB[i], bS[i] + (size_t)k0 * ldb);
            }
            cp_commit();
        }
        const uint32_t offA = buf * GE_A_STAGE;
        const uint32_t offB = buf * GE_B_STAGE;
        #pragma unroll
        for (int ks = 0; ks < 4; ks++) {
            uint32_t af[4][4];
            #pragma unroll
            for (int mt = 0; mt < 4; mt++)
                ldsm4(af[mt][0], af[mt][1], af[mt][2], af[mt][3], aAddr[mt] + offA + ks * 32);
            uint32_t bf[4][2];
            #pragma unroll
            for (int p = 0; p < 2; p++)
                ldsm4_t(bf[2 * p][0], bf[2 * p][1], bf[2 * p + 1][0], bf[2 * p + 1][1],
                        bBase + offB + (uint32_t)(ks * 16 * 136 + p * 16) * 2);
            #pragma unroll
            for (int mt = 0; mt < 4; mt++)
                #pragma unroll
                for (int nt = 0; nt < 4; nt++)
                    mma_h(acc[mt][nt], af[mt], bf[nt]);
        }
        __syncthreads();
    }

    if (MODE == 0) {
        const int seg  = (int)(n0 / segW);
        const int ncol = (int)(n0 % segW);
        __half* Cb = (__half*)Cv + (size_t)seg * segStride + m0 * segW + ncol;
        #pragma unroll
        for (int mt = 0; mt < 4; mt++) {
            const int r0 = wm + mt * 16 + (lane >> 2);
            #pragma unroll
            for (int nt = 0; nt < 4; nt++) {
                const int c = wn + nt * 8 + (lane & 3) * 2;
                const float b0 = bias[n0 + c], b1 = bias[n0 + c + 1];
                *(__half2*)(Cb + (size_t)r0 * segW + c) =
                    __floats2half2_rn(acc[mt][nt][0] + b0, acc[mt][nt][1] + b1);
                *(__half2*)(Cb + (size_t)(r0 + 8) * segW + c) =
                    __floats2half2_rn(acc[mt][nt][2] + b0, acc[mt][nt][3] + b1);
            }
        }
    } else {
        const int ldc = segStride;
        float* Cb = (float*)Cv + m0 * ldc + n0;
        const float* Rb = Res + m0 * ldc + n0;
        #pragma unroll
        for (int mt = 0; mt < 4; mt++) {
            const int r0 = wm + mt * 16 + (lane >> 2);
            #pragma unroll
            for (int nt = 0; nt < 4; nt++) {
                const int c = wn + nt * 8 + (lane & 3) * 2;
                const float b0 = bias[n0 + c], b1 = bias[n0 + c + 1];
                float2 ra = *(const float2*)(Rb + (size_t)r0 * ldc + c);
                float2 rb = *(const float2*)(Rb + (size_t)(r0 + 8) * ldc + c);
                *(float2*)(Cb + (size_t)r0 * ldc + c) =
                    make_float2(acc[mt][nt][0] + b0 + ra.x, acc[mt][nt][1] + b1 + ra.y);
                *(float2*)(Cb + (size_t)(r0 + 8) * ldc + c) =
                    make_float2(acc[mt][nt][2] + b0 + rb.x, acc[mt][nt][3] + b1 + rb.y);
            }
        }
    }
}

// ---------------------------------------------------------------------------
// f32 -> f16 straight copy into [K][N]-fused destinations, 4-way batched.
// Each thread: 8 elems (2x float4 read, one 16B write).
// ---------------------------------------------------------------------------
__global__ __launch_bounds__(256) void f2h_copy4(
    const float* __restrict__ s0, const float* __restrict__ s1,
    const float* __restrict__ s2, const float* __restrict__ s3,
    __half* __restrict__ d0, __half* __restrict__ d1,
    __half* __restrict__ d2, __half* __restrict__ d3,
    int C, int ld0, int ld1, int ld2, int ld3)
{
    const float* src;
    __half* dst;
    int ld;
    switch (blockIdx.z) {
        case 0: src = s0; dst = d0; ld = ld0; break;
        case 1: src = s1; dst = d1; ld = ld1; break;
        case 2: src = s2; dst = d2; ld = ld2; break;
        default: src = s3; dst = d3; ld = ld3; break;
    }
    const size_t i = ((size_t)blockIdx.x * 256 + threadIdx.x) * 8;
    const int r = (int)(i / C);
    const int c = (int)(i % C);
    float4 v0 = *(const float4*)(src + i);
    float4 v1 = *(const float4*)(src + i + 4);
    __half2 h[4];
    h[0] = __floats2half2_rn(v0.x, v0.y);
    h[1] = __floats2half2_rn(v0.z, v0.w);
    h[2] = __floats2half2_rn(v1.x, v1.y);
    h[3] = __floats2half2_rn(v1.z, v1.w);
    *(uint4*)(dst + (size_t)r * ld + c) = *(uint4*)h;
}

// ---------------------------------------------------------------------------
// Bias concat
// ---------------------------------------------------------------------------
__global__ __launch_bounds__(256) void concat_bias(
    float* __restrict__ dst, const float* __restrict__ bq, const float* __restrict__ bk,
    const float* __restrict__ bv, const float* __restrict__ b1, const float* __restrict__ b2)
{
    const int i = blockIdx.x * 256 + threadIdx.x;
    if (i < 1024)       dst[i] = bq[i];
    else if (i < 2048)  dst[i] = bk[i - 1024];
    else if (i < 3072)  dst[i] = bv[i - 2048];
    else if (i < 3072 + 4096)  dst[1024 + i] = b1[i - 3072];
    else if (i < 3072 + 8192)  dst[1024 + i] = b2[i - 7168];
}

// ---------------------------------------------------------------------------
// Flash attention fp16 (round-11 proven: V via ldmatrix.trans, no pre-pass).
// ---------------------------------------------------------------------------
#define FL_SMEM ((128 * 72 + 128 * 72 + 128 * 136) * 2)

__global__ __launch_bounds__(256) void flash_h(
    const __half* __restrict__ q, const __half* __restrict__ k,
    const __half* __restrict__ v, __half* __restrict__ out)
{
    extern __shared__ __half smh[];
    const uint32_t sK = smem_u32(smh);
    const uint32_t sV = sK + 128 * 72 * 2;
    const uint32_t sP = sV + 128 * 72 * 2;
    __half* sPh = smh + 128 * 72 + 128 * 72;

    const int t = threadIdx.x;
    const int lane = t & 31, warp = t >> 5;
    const int lq = lane >> 3, lr = lane & 7;
    const int bh = blockIdx.y, b = bh >> 4, h = bh & 15;
    const int q0 = blockIdx.x * 128;
    const int wm = warp * 16;

    const __half* qb = q + ((size_t)b * 1024 + q0) * 1024 + h * 64;
    const __half* kb = k + ((size_t)b << 20) + h * 64;
    const __half* vb = v + ((size_t)b << 20) + h * 64;

    {
        #pragma unroll
        for (int i = 0; i < 4; i++) {
            const int idx = t + 256 * i;
            const int row = idx >> 3, c = idx & 7;
            cp_async16(sP + (uint32_t)(row * 72 + c * 8) * 2, qb + (size_t)row * 1024 + c * 8);
        }
    }
    cp_commit(); cp_wait0(); __syncthreads();

    uint32_t qf[4][4];
    {
        const uint32_t a0 = sP + (uint32_t)((wm + ((lq & 1) << 3) + lr) * 72 + ((lq >> 1) << 3)) * 2;
        #pragma unroll
        for (int ks = 0; ks < 4; ks++)
            ldsm4(qf[ks][0], qf[ks][1], qf[ks][2], qf[ks][3], a0 + ks * 32);
    }
    __syncthreads();

    float o[8][4];
    #pragma unroll
    for (int i = 0; i < 8; i++)
        #pragma unroll
        for (int j = 0; j < 4; j++) o[i][j] = 0.f;
    float m0 = -1e30f, m1 = -1e30f, l0 = 0.f, l1 = 0.f;

    const uint32_t aP = sP + (uint32_t)((wm + ((lq & 1) << 3) + lr) * 136 + ((lq >> 1) << 3)) * 2;

    for (int it = 0; it < 8; ++it) {
        const int kt0 = it * 128;
        #pragma unroll
        for (int i = 0; i < 4; i++) {
            const int idx = t + 256 * i;
            const int row = idx >> 3, c = idx & 7;
            cp_async16(sK + (uint32_t)(row * 72 + c * 8) * 2,
                       kb + (size_t)(kt0 + row) * 1024 + c * 8);
            cp_async16(sV + (uint32_t)(row * 72 + c * 8) * 2,
                       vb + (size_t)(kt0 + row) * 1024 + c * 8);
        }
        cp_commit(); cp_wait0(); __syncthreads();

        float s[16][4];
        #pragma unroll
        for (int i = 0; i < 16; i++)
            #pragma unroll
            for (int j = 0; j < 4; j++) s[i][j] = 0.f;
        #pragma unroll
        for (int ks = 0; ks < 4; ks++) {
            uint32_t bf[16][2];
            #pragma unroll
            for (int p = 0; p < 8; p++) {
                const uint32_t addr =
                    sK + (uint32_t)((p * 16 + ((lq >> 1) << 3) + lr) * 72 + ((lq & 1) << 3)) * 2
                       + ks * 32;
                ldsm4(bf[2 * p][0], bf[2 * p][1], bf[2 * p + 1][0], bf[2 * p + 1][1], addr);
            }
            #pragma unroll
            for (int nt = 0; nt < 16; nt++)
                mma_h(s[nt], qf[ks], bf[nt]);
        }

        float c0v = -1e30f, c1v = -1e30f;
        #pragma unroll
        for (int nt = 0; nt < 16; nt++) {
            c0v = fmaxf(c0v, fmaxf(s[nt][0], s[nt][1]));
            c1v = fmaxf(c1v, fmaxf(s[nt][2], s[nt][3]));
        }
        c0v = fmaxf(c0v, __shfl_xor_sync(0xffffffffu, c0v, 1));
        c0v = fmaxf(c0v, __shfl_xor_sync(0xffffffffu, c0v, 2));
        c1v = fmaxf(c1v, __shfl_xor_sync(0xffffffffu, c1v, 1));
        c1v = fmaxf(c1v, __shfl_xor_sync(0xffffffffu, c1v, 2));
        const float m0n = fmaxf(m0, c0v * 0.125f);
        const float m1n = fmaxf(m1, c1v * 0.125f);
        const float cor0 = __expf(m0 - m0n);
        const float cor1 = __expf(m1 - m1n);
        m0 = m0n; m1 = m1n;
        float sum0 = 0.f, sum1 = 0.f;
        {
            __half* pr0 = sPh + (size_t)(wm + (lane >> 2)) * 136 + 2 * (lane & 3);
            __half* pr1 = pr0 + 8 * 136;
            #pragma unroll
            for (int nt = 0; nt < 16; nt++) {
                float p0 = __expf(fmaf(0.125f, s[nt][0], -m0n));
                float p1 = __expf(fmaf(0.125f, s[nt][1], -m0n));
                float p2 = __expf(fmaf(0.125f, s[nt][2], -m1n));
                float p3 = __expf(fmaf(0.125f, s[nt][3], -m1n));
                sum0 += p0 + p1; sum1 += p2 + p3;
                *(__half2*)(pr0 + nt * 8) = __floats2half2_rn(p0, p1);
                *(__half2*)(pr1 + nt * 8) = __floats2half2_rn(p2, p3);
            }
        }
        sum0 += __shfl_xor_sync(0xffffffffu, sum0, 1);
        sum0 += __shfl_xor_sync(0xffffffffu, sum0, 2);
        sum1 += __shfl_xor_sync(0xffffffffu, sum1, 1);
        sum1 += __shfl_xor_sync(0xffffffffu, sum1, 2);
        l0 = l0 * cor0 + sum0;
        l1 = l1 * cor1 + sum1;
        #pragma unroll
        for (int nt = 0; nt < 8; nt++) {
            o[nt][0] *= cor0; o[nt][1] *= cor0;
            o[nt][2] *= cor1; o[nt][3] *= cor1;
        }
        __syncwarp();

        #pragma unroll
        for (int ks2 = 0; ks2 < 8; ks2++) {
            uint32_t af[4];
            ldsm4(af[0], af[1], af[2], af[3], aP + ks2 * 32);
            uint32_t bf2[8][2];
            #pragma unroll
            for (int p = 0; p < 4; p++) {
                const uint32_t addr =
                    sV + (uint32_t)((ks2 * 16 + ((lq & 1) << 3) + lr) * 72
                                    + p * 16 + ((lq >> 1) << 3)) * 2;
                ldsm4_t(bf2[2 * p][0], bf2[2 * p][1], bf2[2 * p + 1][0], bf2[2 * p + 1][1], addr);
            }
            #pragma unroll
            for (int nt = 0; nt < 8; nt++)
                mma_h(o[nt], af, bf2[nt]);
        }
        __syncthreads();
    }

    const float inv0 = 1.f / l0, inv1 = 1.f / l1;
    __half* ob = out + ((size_t)b * 1024 + q0 + wm + (lane >> 2)) * 1024 + h * 64 + 2 * (lane & 3);
    #pragma unroll
    for (int nt = 0; nt < 8; nt++) {
        *(__half2*)(ob + nt * 8) = __floats2half2_rn(o[nt][0] * inv0, o[nt][1] * inv0);
        *(__half2*)(ob + 8 * 1024 + nt * 8) = __floats2half2_rn(o[nt][2] * inv1, o[nt][3] * inv1);
    }
}

// ---------------------------------------------------------------------------
// LayerNorm over D=1024, f32 in -> half out.
// ---------------------------------------------------------------------------
__global__ __launch_bounds__(256) void ln_kernel(
    const float* __restrict__ in, const float* __restrict__ sc,
    const float* __restrict__ bi, __half* __restrict__ out)
{
    const int row = blockIdx.x;
    const int t = threadIdx.x;
    const float4* x4 = (const float4*)(in + (size_t)row * 1024);
    float4 v = x4[t];
    float s  = v.x + v.y + v.z + v.w;
    float ss = v.x * v.x + v.y * v.y + v.z * v.z + v.w * v.w;
    #pragma unroll
    for (int o = 16; o; o >>= 1) {
        s  += __shfl_xor_sync(0xffffffffu, s,  o);
        ss += __shfl_xor_sync(0xffffffffu, ss, o);
    }
    __shared__ float sred[8], ssred[8];
    if ((t & 31) == 0) { sred[t >> 5] = s; ssred[t >> 5] = ss; }
    __syncthreads();
    float tot = 0.f, tots = 0.f;
    #pragma unroll
    for (int w = 0; w < 8; w++) { tot += sred[w]; tots += ssred[w]; }
    const float mean = tot * (1.f / 1024.f);
    const float var  = tots * (1.f / 1024.f) - mean * mean;
    const float inv  = rsqrtf(var + EPSF);
    float4 sv = ((const float4*)sc)[t];
    float4 bv = ((const float4*)bi)[t];
    __half2* o2 = (__half2*)(out + (size_t)row * 1024);
    o2[t * 2 + 0] = __floats2half2_rn((v.x - mean) * inv * sv.x + bv.x,
                                      (v.y - mean) * inv * sv.y + bv.y);
    o2[t * 2 + 1] = __floats2half2_rn((v.z - mean) * inv * sv.z + bv.z,
                                      (v.w - mean) * inv * sv.w + bv.w);
}

// ---------------------------------------------------------------------------
// QK-norm for q AND k in one launch (blockIdx.y selects tensor).
// ---------------------------------------------------------------------------
__global__ __launch_bounds__(256) void qknorm2_kernel(
    __half* __restrict__ q, __half* __restrict__ k,
    const float* __restrict__ qs, const float* __restrict__ qb,
    const float* __restrict__ ks, const float* __restrict__ kb)
{
    __half* base = blockIdx.y ? k : q;
    const float* sc = blockIdx.y ? ks : qs;
    const float* bi = blockIdx.y ? kb : qb;
    const int gw   = (blockIdx.x * 256 + threadIdx.x) >> 5;
    const int lane = threadIdx.x & 31;
    const int h  = gw & 15;
    const int bs = gw >> 4;
    __half2* p = (__half2*)(base + (size_t)bs * 1024 + h * 64) + lane;
    float2 v = __half22float2(*p);
    float s  = v.x + v.y;
    float ss = v.x * v.x + v.y * v.y;
    #pragma unroll
    for (int o = 16; o; o >>= 1) {
        s  += __shfl_xor_sync(0xffffffffu, s,  o);
        ss += __shfl_xor_sync(0xffffffffu, ss, o);
    }
    const float mean = s * (1.f / 64.f);
    const float var  = ss * (1.f / 64.f) - mean * mean;
    const float inv  = rsqrtf(var + EPSF);
    const float* scp = sc + h * 64 + lane * 2;
    const float* bip = bi + h * 64 + lane * 2;
    *p = __floats2half2_rn((v.x - mean) * inv * scp[0] + bip[0],
                           (v.y - mean) * inv * scp[1] + bip[1]);
}

// ---------------------------------------------------------------------------
// GeGLU: h1 <- h1 * gelu_tanh(h2), half, 4 halves/thread.
// ---------------------------------------------------------------------------
__device__ __forceinline__ float gelu_t(float x)
{
    return 0.5f * x * (1.f + tanhf(0.7978845608028654f * (x + 0.044715f * x * x * x)));
}

__global__ __launch_bounds__(256) void geglu_kernel(
    __half* __restrict__ g1, const __half* __restrict__ g2)
{
    const size_t i = (size_t)blockIdx.x * 256 + threadIdx.x;
    __half2 a0 = ((const __half2*)g1)[i * 2 + 0];
    __half2 a1 = ((const __half2*)g1)[i * 2 + 1];
    __half2 c0 = ((const __half2*)g2)[i * 2 + 0];
    __half2 c1 = ((const __half2*)g2)[i * 2 + 1];
    float2 af0 = __half22float2(a0), af1 = __half22float2(a1);
    float2 cf0 = __half22float2(c0), cf1 = __half22float2(c1);
    ((__half2*)g1)[i * 2 + 0] =
        __floats2half2_rn(af0.x * gelu_t(cf0.x), af0.y * gelu_t(cf0.y));
    ((__half2*)g1)[i * 2 + 1] =
        __floats2half2_rn(af1.x * gelu_t(cf1.x), af1.y * gelu_t(cf1.y));
}

// ---------------------------------------------------------------------------
// Launch
// ---------------------------------------------------------------------------
extern "C" void kernel_launch(void* const* d_in, const int* in_sizes, int n_in,
                              void* d_out, int out_size)
{
    (void)in_sizes; (void)n_in; (void)out_size;
    const float* x     = (const float*)d_in[0];
    const float* ln1_s = (const float*)d_in[2];
    const float* ln1_b = (const float*)d_in[3];
    const float* Wq    = (const float*)d_in[4];
    const float* bq    = (const float*)d_in[5];
    const float* Wk    = (const float*)d_in[6];
    const float* bk    = (const float*)d_in[7];
    const float* Wv    = (const float*)d_in[8];
    const float* bv    = (const float*)d_in[9];
    const float* qn_s  = (const float*)d_in[10];
    const float* qn_b  = (const float*)d_in[11];
    const float* kn_s  = (const float*)d_in[12];
    const float* kn_b  = (const float*)d_in[13];
    const float* Wo    = (const float*)d_in[14];
    const float* bo    = (const float*)d_in[15];
    const float* ln2_s = (const float*)d_in[16];
    const float* ln2_b = (const float*)d_in[17];
    const float* W1    = (const float*)d_in[18];
    const float* b1    = (const float*)d_in[19];
    const float* W2    = (const float*)d_in[20];
    const float* b2    = (const float*)d_in[21];
    const float* W3    = (const float*)d_in[22];
    const float* b3    = (const float*)d_in[23];

    void *p_xn, *p_qkv, *p_att, *p_res, *p_big, *p_wt, *p_bias;
    cudaGetSymbolAddress(&p_xn,   g_xn);
    cudaGetSymbolAddress(&p_qkv,  g_qkv);
    cudaGetSymbolAddress(&p_att,  g_att);
    cudaGetSymbolAddress(&p_res,  g_res);
    cudaGetSymbolAddress(&p_big,  g_big);
    cudaGetSymbolAddress(&p_wt,   g_wt);
    cudaGetSymbolAddress(&p_bias, g_bias);

    __half* xn  = (__half*)p_xn;
    __half* qkv = (__half*)p_qkv;
    __half* qh  = qkv;
    __half* kh  = qkv + (size_t)4194304;
    __half* vh  = qkv + (size_t)8388608;
    __half* att = (__half*)p_att;
    float*  res = (float*)p_res;
    __half* wt  = (__half*)p_wt;
    __half* h1  = (__half*)p_big;
    __half* h2  = h1 + (size_t)16777216;
    float*  bsc = (float*)p_bias;
    float* out = (float*)d_out;

    cudaFuncSetAttribute(flash_h, cudaFuncAttributeMaxDynamicSharedMemorySize, FL_SMEM);
    cudaFuncSetAttribute(gemm_h<0>, cudaFuncAttributeMaxDynamicSharedMemorySize, GE_SMEM);
    cudaFuncSetAttribute(gemm_h<1>, cudaFuncAttributeMaxDynamicSharedMemorySize, GE_SMEM);

    const size_t MB1 = 1024 * 1024;
    // native-layout half weights:
    __half* wqkv = wt;                 // [1024][3072]  (q|k|v columns)
    __half* wo   = wt + 3 * MB1;       // [1024][1024]
    __half* w12  = wt + 4 * MB1;       // [1024][8192]  (w1|w2 columns)
    __half* w3   = wt + 12 * MB1;      // [4096][1024]

    // 0. weight conversions (straight f32->f16 copies) + bias concat
    f2h_copy4<<<dim3(512, 1, 4), 256>>>(Wq, Wk, Wv, Wo,
                                        wqkv, wqkv + 1024, wqkv + 2048, wo,
                                        1024, 3072, 3072, 3072, 1024);
    f2h_copy4<<<dim3(2048, 1, 2), 256>>>(W1, W2, W1, W2,
                                         w12, w12 + 4096, w12, w12 + 4096,
                                         4096, 8192, 8192, 8192, 8192);
    f2h_copy4<<<dim3(2048, 1, 1), 256>>>(W3, W3, W3, W3, w3, w3, w3, w3,
                                         1024, 1024, 1024, 1024, 1024);
    concat_bias<<<44, 256>>>(bsc, bq, bk, bv, b1, b2);

    // 1. LN1 -> xn (half)
    ln_kernel<<<4096, 256>>>(x, ln1_s, ln1_b, xn);

    // 2. fused QKV projection (M=4096, N=3072, K=1024) -> q|k|v segments
    gemm_h<0><<<dim3(24, 32), 256, GE_SMEM>>>(xn, wqkv, bsc, nullptr, qkv,
                                              1024, 1024, 3072, 1024, 4194304);

    // 3. QK-norm for q and k (one launch)
    qknorm2_kernel<<<dim3(8192, 2), 256>>>(qh, kh, qn_s, qn_b, kn_s, kn_b);

    // 4. flash attention -> att
    flash_h<<<dim3(8, 64), 256, FL_SMEM>>>(qh, kh, vh, att);

    // 5. O projection + residual (f32 out)
    gemm_h<1><<<dim3(8, 32), 256, GE_SMEM>>>(att, wo, bo, x, res, 1024, 1024, 1024, 0, 1024);

    // 6. LN2 -> xn (half)
    ln_kernel<<<4096, 256>>>(res, ln2_s, ln2_b, xn);

    // 7. fused FFN up (M=4096, N=8192, K=1024) -> h1 | h2
    gemm_h<0><<<dim3(64, 32), 256, GE_SMEM>>>(xn, w12, bsc + 4096, nullptr, h1,
                                              1024, 1024, 8192, 4096, 16777216);

    // 8. GeGLU
    geglu_kernel<<<16384, 256>>>(h1, h2);

    // 9. Down projection + residual -> d_out (M=4096, N=1024, K=4096)
    gemm_h<1><<<dim3(8, 32), 256, GE_SMEM>>>(h1, w3, b3, res, out, 4096, 4096, 1024, 0, 1024);
}

// round 14
// speedup vs baseline: 1.0531x; 1.0346x over previous
#include <cuda_runtime.h>
#include <cuda_fp16.h>
#include <math.h>
#include <stdint.h>

#define EPSF 1e-6f

// Problem constants: B=4, S=1024, D=1024, H=16, DH=64, F=4096, M=B*S=4096
__device__ float g_xn  [4096 * 1024 / 2];    // xn (half)
__device__ float g_qkv [6 * 1024 * 1024];    // q|k|v (half, 3 x 4M halves)
__device__ float g_att [2 * 1024 * 1024];    // attn_out (half)
__device__ float g_res [4096 * 1024];        // residual after attention (f32)
__device__ float g_big [16 * 1024 * 1024];   // h (half, 16M halves) + spare
__device__ float g_wt  [8 * 1024 * 1024];    // half weights, native [K][N] (16M halves)
__device__ float g_bias[16384];              // b_qkv (3072) @0, b12 (8192) @4096

// ---------------------------------------------------------------------------
// Helpers
// ---------------------------------------------------------------------------
__device__ __forceinline__ void cp_async16(uint32_t dst, const void* src)
{
    asm volatile("cp.async.cg.shared.global [%0], [%1], 16;\n" :: "r"(dst), "l"(src));
}
__device__ __forceinline__ void cp_commit() { asm volatile("cp.async.commit_group;\n"); }
__device__ __forceinline__ void cp_wait0()  { asm volatile("cp.async.wait_group 0;\n"); }

__device__ __forceinline__ uint32_t smem_u32(const void* p)
{
    uint32_t a;
    asm("{ .reg .u64 t; cvta.to.shared.u64 t, %1; cvt.u32.u64 %0, t; }" : "=r"(a) : "l"(p));
    return a;
}
__device__ __forceinline__ void ldsm4(uint32_t& r0, uint32_t& r1, uint32_t& r2, uint32_t& r3,
                                      uint32_t a)
{
    asm volatile("ldmatrix.sync.aligned.m8n8.x4.shared.b16 {%0,%1,%2,%3}, [%4];"
                 : "=r"(r0), "=r"(r1), "=r"(r2), "=r"(r3) : "r"(a));
}
__device__ __forceinline__ void ldsm4_t(uint32_t& r0, uint32_t& r1, uint32_t& r2, uint32_t& r3,
                                        uint32_t a)
{
    asm volatile("ldmatrix.sync.aligned.m8n8.x4.trans.shared.b16 {%0,%1,%2,%3}, [%4];"
                 : "=r"(r0), "=r"(r1), "=r"(r2), "=r"(r3) : "r"(a));
}
__device__ __forceinline__ void mma_h(float c[4], const uint32_t a[4], const uint32_t b[2])
{
    asm volatile(
        "mma.sync.aligned.m16n8k16.row.col.f32.f16.f16.f32 "
        "{%0,%1,%2,%3}, {%4,%5,%6,%7}, {%8,%9}, {%0,%1,%2,%3};\n"
        : "+f"(c[0]), "+f"(c[1]), "+f"(c[2]), "+f"(c[3])
        : "r"(a[0]), "r"(a[1]), "r"(a[2]), "r"(a[3]), "r"(b[0]), "r"(b[1]));
}

__device__ __forceinline__ float gelu_t(float x)
{
    return 0.5f * x * (1.f + tanhf(0.7978845608028654f * (x + 0.044715f * x * x * x)));
}

// ---------------------------------------------------------------------------
// Dense fp16 GEMM (round-13 proven): BM=128 BN=128 BK=64, 8 warps (64x32),
// double buffer. A [M][K] stride-72; B native [K][N] stride-136 + ldsm.trans.
// MODE 0: half out, segmented columns. MODE 1: float out = acc + bias + Res.
// ---------------------------------------------------------------------------
#define GE_A_STAGE (128 * 72 * 2)                // 18432 B
#define GE_B_STAGE (64 * 136 * 2)                // 17408 B
#define GE_SMEM (2 * (GE_A_STAGE + GE_B_STAGE))  // 71680 B

template <int MODE>
__global__ __launch_bounds__(256) void gemm_h(
    const __half* __restrict__ A, const __half* __restrict__ B,
    const float* __restrict__ bias, const float* __restrict__ Res,
    void* __restrict__ Cv, int K, int lda, int ldb, int segW, int segStride)
{
    extern __shared__ __half gsm[];
    const uint32_t sA = smem_u32(gsm);
    const uint32_t sB = sA + 2 * GE_A_STAGE;

    const int t    = threadIdx.x;
    const int lane = t & 31;
    const int warp = t >> 5;
    const size_t m0 = (size_t)blockIdx.y * 128;
    const size_t n0 = (size_t)blockIdx.x * 128;
    const int wm = (warp >> 2) * 64;
    const int wn = (warp & 3) * 32;

    uint32_t dA[4], dB[4];
    const __half* aS[4];
    const __half* bS[4];
    #pragma unroll
    for (int i = 0; i < 4; i++) {
        const int ia = t + 256 * i;
        const int rowA = ia >> 3, cA = ia & 7;
        dA[i] = (uint32_t)(rowA * 72 + cA * 8) * 2;
        aS[i] = A + (m0 + rowA) * lda + cA * 8;
        const int rowB = ia >> 4, cB = ia & 15;
        dB[i] = (uint32_t)(rowB * 136 + cB * 8) * 2;
        bS[i] = B + (size_t)rowB * ldb + n0 + cB * 8;
    }

    const int lq = lane >> 3, lr = lane & 7;
    uint32_t aAddr[4];
    #pragma unroll
    for (int mt = 0; mt < 4; mt++)
        aAddr[mt] = sA + (uint32_t)((wm + mt * 16 + ((lq & 1) << 3) + lr) * 72 + ((lq >> 1) << 3)) * 2;
    const uint32_t bBase = sB + (uint32_t)((((lq & 1) << 3) + lr) * 136 + wn + ((lq >> 1) << 3)) * 2;

    float acc[4][4][4];
    #pragma unroll
    for (int mt = 0; mt < 4; mt++)
        #pragma unroll
        for (int nt = 0; nt < 4; nt++)
            #pragma unroll
            for (int i = 0; i < 4; i++) acc[mt][nt][i] = 0.f;

    #pragma unroll
    for (int i = 0; i < 4; i++) {
        cp_async16(sA + dA[i], aS[i]);
        cp_async16(sB + dB[i], bS[i]);
    }
    cp_commit();

    const int nIter = K >> 6;
    for (int it = 0; it < nIter; ++it) {
        cp_wait0();
        __syncthreads();
        const int buf = it & 1;
        if (it + 1 < nIter) {
            const int k0 = (it + 1) << 6;
            const uint32_t offA = (buf ^ 1) * GE_A_STAGE;
            const uint32_t offB = (buf ^ 1) * GE_B_STAGE;
            #pragma unroll
            for (int i = 0; i < 4; i++) {
                cp_async16(sA + offA + dA[i], aS[i] + k0);
                cp_async16(sB + offB + dB[i], bS[i] + (size_t)k0 * ldb);
            }
            cp_commit();
        }
        const uint32_t offA = buf * GE_A_STAGE;
        const uint32_t offB = buf * GE_B_STAGE;
        #pragma unroll
        for (int ks = 0; ks < 4; ks++) {
            uint32_t af[4][4];
            #pragma unroll
            for (int mt = 0; mt < 4; mt++)
                ldsm4(af[mt][0], af[mt][1], af[mt][2], af[mt][3], aAddr[mt] + offA + ks * 32);
            uint32_t bf[4][2];
            #pragma unroll
            for (int p = 0; p < 2; p++)
                ldsm4_t(bf[2 * p][0], bf[2 * p][1], bf[2 * p + 1][0], bf[2 * p + 1][1],
                        bBase + offB + (uint32_t)(ks * 16 * 136 + p * 16) * 2);
            #pragma unroll
            for (int mt = 0; mt < 4; mt++)
                #pragma unroll
                for (int nt = 0; nt < 4; nt++)
                    mma_h(acc[mt][nt], af[mt], bf[nt]);
        }
        __syncthreads();
    }

    if (MODE == 0) {
        const int seg  = (int)(n0 / segW);
        const int ncol = (int)(n0 % segW);
        __half* Cb = (__half*)Cv + (size_t)seg * segStride + m0 * segW + ncol;
        #pragma unroll
        for (int mt = 0; mt < 4; mt++) {
            const int r0 = wm + mt * 16 + (lane >> 2);
            #pragma unroll
            for (int nt = 0; nt < 4; nt++) {
                const int c = wn + nt * 8 + (lane & 3) * 2;
                const float b0 = bias[n0 + c], b1 = bias[n0 + c + 1];
                *(__half2*)(Cb + (size_t)r0 * segW + c) =
                    __floats2half2_rn(acc[mt][nt][0] + b0, acc[mt][nt][1] + b1);
                *(__half2*)(Cb + (size_t)(r0 + 8) * segW + c) =
                    __floats2half2_rn(acc[mt][nt][2] + b0, acc[mt][nt][3] + b1);
            }
        }
    } else {
        const int ldc = segStride;
        float* Cb = (float*)Cv + m0 * ldc + n0;
        const float* Rb = Res + m0 * ldc + n0;
        #pragma unroll
        for (int mt = 0; mt < 4; mt++) {
            const int r0 = wm + mt * 16 + (lane >> 2);
            #pragma unroll
            for (int nt = 0; nt < 4; nt++) {
                const int c = wn + nt * 8 + (lane & 3) * 2;
                const float b0 = bias[n0 + c], b1 = bias[n0 + c + 1];
                float2 ra = *(const float2*)(Rb + (size_t)r0 * ldc + c);
                float2 rb = *(const float2*)(Rb + (size_t)(r0 + 8) * ldc + c);
                *(float2*)(Cb + (size_t)r0 * ldc + c) =
                    make_float2(acc[mt][nt][0] + b0 + ra.x, acc[mt][nt][1] + b1 + ra.y);
                *(float2*)(Cb + (size_t)(r0 + 8) * ldc + c) =
                    make_float2(acc[mt][nt][2] + b0 + rb.x, acc[mt][nt][3] + b1 + rb.y);
            }
        }
    }
}

// ---------------------------------------------------------------------------
// Fused FFN-up + GeGLU: h[m][n] = (xn@w1 + b1) * gelu(xn@w2 + b2).
// BM=128, BN=64 (per matrix), BK=64. 8 warps as 4m x 2n (32x32 per matrix).
// B smem: two 64x72-stride tiles per stage (w1 @ n0, w2 @ n0+4096).
// acc = 2x4x4 x 2 matrices = 64 floats/thread (same as dense kernel).
// ---------------------------------------------------------------------------
#define FF_A_STAGE (128 * 72 * 2)                // 18432 B
#define FF_B_STAGE (2 * 64 * 72 * 2)             // 18432 B
#define FF_SMEM (2 * (FF_A_STAGE + FF_B_STAGE))  // 73728 B

__global__ __launch_bounds__(256) void ffn_gemm(
    const __half* __restrict__ A, const __half* __restrict__ W12,
    const float* __restrict__ b12, __half* __restrict__ Hout)
{
    extern __shared__ __half fsm[];
    const uint32_t sA = smem_u32(fsm);
    const uint32_t sB = sA + 2 * FF_A_STAGE;

    const int t    = threadIdx.x;
    const int lane = t & 31;
    const int warp = t >> 5;
    const size_t m0 = (size_t)blockIdx.y * 128;
    const size_t n0 = (size_t)blockIdx.x * 64;
    const int wm = (warp >> 1) * 32;
    const int wn = (warp & 1) * 32;

    // A: 1024 chunks -> 4/thread. B: 2 tiles x 512 chunks -> 4/thread.
    uint32_t dA[4], dB[4];
    const __half* aS[4];
    const __half* bS[4];
    #pragma unroll
    for (int i = 0; i < 4; i++) {
        const int ia = t + 256 * i;
        const int rowA = ia >> 3, cA = ia & 7;
        dA[i] = (uint32_t)(rowA * 72 + cA * 8) * 2;
        aS[i] = A + (m0 + rowA) * 1024 + cA * 8;
        const int tile = ia >> 9;            // 0 -> w1, 1 -> w2
        const int i9 = ia & 511;
        const int rowB = i9 >> 3, cB = i9 & 7;
        dB[i] = (uint32_t)(tile * 64 * 72 + rowB * 72 + cB * 8) * 2;
        bS[i] = W12 + (size_t)rowB * 8192 + n0 + tile * 4096 + cB * 8;
    }

    const int lq = lane >> 3, lr = lane & 7;
    uint32_t aAddr[2];
    #pragma unroll
    for (int mt = 0; mt < 2; mt++)
        aAddr[mt] = sA + (uint32_t)((wm + mt * 16 + ((lq & 1) << 3) + lr) * 72 + ((lq >> 1) << 3)) * 2;
    // trans-frag bases per matrix: k-row (lq&1)*8+lr, n-col wn + (lq>>1)*8
    const uint32_t bB0 = sB + (uint32_t)((((lq & 1) << 3) + lr) * 72 + wn + ((lq >> 1) << 3)) * 2;
    const uint32_t bB1 = bB0 + (uint32_t)(64 * 72) * 2;

    float acc1[2][4][4], acc2[2][4][4];
    #pragma unroll
    for (int mt = 0; mt < 2; mt++)
        #pragma unroll
        for (int nt = 0; nt < 4; nt++)
            #pragma unroll
            for (int i = 0; i < 4; i++) { acc1[mt][nt][i] = 0.f; acc2[mt][nt][i] = 0.f; }

    #pragma unroll
    for (int i = 0; i < 4; i++) {
        cp_async16(sA + dA[i], aS[i]);
        cp_async16(sB + dB[i], bS[i]);
    }
    cp_commit();

    const int nIter = 16;   // K = 1024
    for (int it = 0; it < nIter; ++it) {
        cp_wait0();
        __syncthreads();
        const int buf = it & 1;
        if (it + 1 < nIter) {
            const int k0 = (it + 1) << 6;
            const uint32_t offA = (buf ^ 1) * FF_A_STAGE;
            const uint32_t offB = (buf ^ 1) * FF_B_STAGE;
            #pragma unroll
            for (int i = 0; i < 4; i++) {
                cp_async16(sA + offA + dA[i], aS[i] + k0);
                cp_async16(sB + offB + dB[i], bS[i] + (size_t)k0 * 8192);
            }
            cp_commit();
        }
        const uint32_t offA = buf * FF_A_STAGE;
        const uint32_t offB = buf * FF_B_STAGE;
        #pragma unroll
        for (int ks = 0; ks < 4; ks++) {
            uint32_t af[2][4];
            #pragma unroll
            for (int mt = 0; mt < 2; mt++)
                ldsm4(af[mt][0], af[mt][1], af[mt][2], af[mt][3], aAddr[mt] + offA + ks * 32);
            uint32_t bf1[4][2], bf2[4][2];
            #pragma unroll
            for (int p = 0; p < 2; p++) {
                const uint32_t kOff = (uint32_t)(ks * 16 * 72 + p * 16) * 2;
                ldsm4_t(bf1[2 * p][0], bf1[2 * p][1], bf1[2 * p + 1][0], bf1[2 * p + 1][1],
                        bB0 + offB + kOff);
                ldsm4_t(bf2[2 * p][0], bf2[2 * p][1], bf2[2 * p + 1][0], bf2[2 * p + 1][1],
                        bB1 + offB + kOff);
            }
            #pragma unroll
            for (int mt = 0; mt < 2; mt++)
                #pragma unroll
                for (int nt = 0; nt < 4; nt++) {
                    mma_h(acc1[mt][nt], af[mt], bf1[nt]);
                    mma_h(acc2[mt][nt], af[mt], bf2[nt]);
                }
        }
        __syncthreads();
    }

    // Epilogue: h = (acc1 + b1) * gelu(acc2 + b2), write half
    __half* Hb = Hout + m0 * 4096 + n0;
    #pragma unroll
    for (int mt = 0; mt < 2; mt++) {
        const int r0 = wm + mt * 16 + (lane >> 2);
        #pragma unroll
        for (int nt = 0; nt < 4; nt++) {
            const int c = wn + nt * 8 + (lane & 3) * 2;
            const float p0 = b12[n0 + c], p1 = b12[n0 + c + 1];
            const float q0 = b12[4096 + n0 + c], q1 = b12[4096 + n0 + c + 1];
            float h00 = (acc1[mt][nt][0] + p0) * gelu_t(acc2[mt][nt][0] + q0);
            float h01 = (acc1[mt][nt][1] + p1) * gelu_t(acc2[mt][nt][1] + q1);
            float h10 = (acc1[mt][nt][2] + p0) * gelu_t(acc2[mt][nt][2] + q0);
            float h11 = (acc1[mt][nt][3] + p1) * gelu_t(acc2[mt][nt][3] + q1);
            *(__half2*)(Hb + (size_t)r0 * 4096 + c)       = __floats2half2_rn(h00, h01);
            *(__half2*)(Hb + (size_t)(r0 + 8) * 4096 + c) = __floats2half2_rn(h10, h11);
        }
    }
}

// ---------------------------------------------------------------------------
// f32 -> f16 straight copy, 4-way batched.
// ---------------------------------------------------------------------------
__global__ __launch_bounds__(256) void f2h_copy4(
    const float* __restrict__ s0, const float* __restrict__ s1,
    const float* __restrict__ s2, const float* __restrict__ s3,
    __half* __restrict__ d0, __half* __restrict__ d1,
    __half* __restrict__ d2, __half* __restrict__ d3,
    int C, int ld0, int ld1, int ld2, int ld3)
{
    const float* src;
    __half* dst;
    int ld;
    switch (blockIdx.z) {
        case 0: src = s0; dst = d0; ld = ld0; break;
        case 1: src = s1; dst = d1; ld = ld1; break;
        case 2: src = s2; dst = d2; ld = ld2; break;
        default: src = s3; dst = d3; ld = ld3; break;
    }
    const size_t i = ((size_t)blockIdx.x * 256 + threadIdx.x) * 8;
    const int r = (int)(i / C);
    const int c = (int)(i % C);
    float4 v0 = *(const float4*)(src + i);
    float4 v1 = *(const float4*)(src + i + 4);
    __half2 h[4];
    h[0] = __floats2half2_rn(v0.x, v0.y);
    h[1] = __floats2half2_rn(v0.z, v0.w);
    h[2] = __floats2half2_rn(v1.x, v1.y);
    h[3] = __floats2half2_rn(v1.z, v1.w);
    *(uint4*)(dst + (size_t)r * ld + c) = *(uint4*)h;
}

// ---------------------------------------------------------------------------
// Bias concat
// ---------------------------------------------------------------------------
__global__ __launch_bounds__(256) void concat_bias(
    float* __restrict__ dst, const float* __restrict__ bq, const float* __restrict__ bk,
    const float* __restrict__ bv, const float* __restrict__ b1, const float* __restrict__ b2)
{
    const int i = blockIdx.x * 256 + threadIdx.x;
    if (i < 1024)       dst[i] = bq[i];
    else if (i < 2048)  dst[i] = bk[i - 1024];
    else if (i < 3072)  dst[i] = bv[i - 2048];
    else if (i < 3072 + 4096)  dst[1024 + i] = b1[i - 3072];
    else if (i < 3072 + 8192)  dst[1024 + i] = b2[i - 7168];
}

// ---------------------------------------------------------------------------
// Flash attention fp16 (round-11/13 proven).
// ---------------------------------------------------------------------------
#define FL_SMEM ((128 * 72 + 128 * 72 + 128 * 136) * 2)

__global__ __launch_bounds__(256) void flash_h(
    const __half* __restrict__ q, const __half* __restrict__ k,
    const __half* __restrict__ v, __half* __restrict__ out)
{
    extern __shared__ __half smh[];
    const uint32_t sK = smem_u32(smh);
    const uint32_t sV = sK + 128 * 72 * 2;
    const uint32_t sP = sV + 128 * 72 * 2;
    __half* sPh = smh + 128 * 72 + 128 * 72;

    const int t = threadIdx.x;
    const int lane = t & 31, warp = t >> 5;
    const int lq = lane >> 3, lr = lane & 7;
    const int bh = blockIdx.y, b = bh >> 4, h = bh & 15;
    const int q0 = blockIdx.x * 128;
    const int wm = warp * 16;

    const __half* qb = q + ((size_t)b * 1024 + q0) * 1024 + h * 64;
    const __half* kb = k + ((size_t)b << 20) + h * 64;
    const __half* vb = v + ((size_t)b << 20) + h * 64;

    {
        #pragma unroll
        for (int i = 0; i < 4; i++) {
            const int idx = t + 256 * i;
            const int row = idx >> 3, c = idx & 7;
            cp_async16(sP + (uint32_t)(row * 72 + c * 8) * 2, qb + (size_t)row * 1024 + c * 8);
        }
    }
    cp_commit(); cp_wait0(); __syncthreads();

    uint32_t qf[4][4];
    {
        const uint32_t a0 = sP + (uint32_t)((wm + ((lq & 1) << 3) + lr) * 72 + ((lq >> 1) << 3)) * 2;
        #pragma unroll
        for (int ks = 0; ks < 4; ks++)
            ldsm4(qf[ks][0], qf[ks][1], qf[ks][2], qf[ks][3], a0 + ks * 32);
    }
    __syncthreads();

    float o[8][4];
    #pragma unroll
    for (int i = 0; i < 8; i++)
        #pragma unroll
        for (int j = 0; j < 4; j++) o[i][j] = 0.f;
    float m0 = -1e30f, m1 = -1e30f, l0 = 0.f, l1 = 0.f;

    const uint32_t aP = sP + (uint32_t)((wm + ((lq & 1) << 3) + lr) * 136 + ((lq >> 1) << 3)) * 2;

    for (int it = 0; it < 8; ++it) {
        const int kt0 = it * 128;
        #pragma unroll
        for (int i = 0; i < 4; i++) {
            const int idx = t + 256 * i;
            const int row = idx >> 3, c = idx & 7;
            cp_async16(sK + (uint32_t)(row * 72 + c * 8) * 2,
                       kb + (size_t)(kt0 + row) * 1024 + c * 8);
            cp_async16(sV + (uint32_t)(row * 72 + c * 8) * 2,
                       vb + (size_t)(kt0 + row) * 1024 + c * 8);
        }
        cp_commit(); cp_wait0(); __syncthreads();

        float s[16][4];
        #pragma unroll
        for (int i = 0; i < 16; i++)
            #pragma unroll
            for (int j = 0; j < 4; j++) s[i][j] = 0.f;
        #pragma unroll
        for (int ks = 0; ks < 4; ks++) {
            uint32_t bf[16][2];
            #pragma unroll
            for (int p = 0; p < 8; p++) {
                const uint32_t addr =
                    sK + (uint32_t)((p * 16 + ((lq >> 1) << 3) + lr) * 72 + ((lq & 1) << 3)) * 2
                       + ks * 32;
                ldsm4(bf[2 * p][0], bf[2 * p][1], bf[2 * p + 1][0], bf[2 * p + 1][1], addr);
            }
            #pragma unroll
            for (int nt = 0; nt < 16; nt++)
                mma_h(s[nt], qf[ks], bf[nt]);
        }

        float c0v = -1e30f, c1v = -1e30f;
        #pragma unroll
        for (int nt = 0; nt < 16; nt++) {
            c0v = fmaxf(c0v, fmaxf(s[nt][0], s[nt][1]));
            c1v = fmaxf(c1v, fmaxf(s[nt][2], s[nt][3]));
        }
        c0v = fmaxf(c0v, __shfl_xor_sync(0xffffffffu, c0v, 1));
        c0v = fmaxf(c0v, __shfl_xor_sync(0xffffffffu, c0v, 2));
        c1v = fmaxf(c1v, __shfl_xor_sync(0xffffffffu, c1v, 1));
        c1v = fmaxf(c1v, __shfl_xor_sync(0xffffffffu, c1v, 2));
        const float m0n = fmaxf(m0, c0v * 0.125f);
        const float m1n = fmaxf(m1, c1v * 0.125f);
        const float cor0 = __expf(m0 - m0n);
        const float cor1 = __expf(m1 - m1n);
        m0 = m0n; m1 = m1n;
        float sum0 = 0.f, sum1 = 0.f;
        {
            __half* pr0 = sPh + (size_t)(wm + (lane >> 2)) * 136 + 2 * (lane & 3);
            __half* pr1 = pr0 + 8 * 136;
            #pragma unroll
            for (int nt = 0; nt < 16; nt++) {
                float p0 = __expf(fmaf(0.125f, s[nt][0], -m0n));
                float p1 = __expf(fmaf(0.125f, s[nt][1], -m0n));
                float p2 = __expf(fmaf(0.125f, s[nt][2], -m1n));
                float p3 = __expf(fmaf(0.125f, s[nt][3], -m1n));
                sum0 += p0 + p1; sum1 += p2 + p3;
                *(__half2*)(pr0 + nt * 8) = __floats2half2_rn(p0, p1);
                *(__half2*)(pr1 + nt * 8) = __floats2half2_rn(p2, p3);
            }
        }
        sum0 += __shfl_xor_sync(0xffffffffu, sum0, 1);
        sum0 += __shfl_xor_sync(0xffffffffu, sum0, 2);
        sum1 += __shfl_xor_sync(0xffffffffu, sum1, 1);
        sum1 += __shfl_xor_sync(0xffffffffu, sum1, 2);
        l0 = l0 * cor0 + sum0;
        l1 = l1 * cor1 + sum1;
        #pragma unroll
        for (int nt = 0; nt < 8; nt++) {
            o[nt][0] *= cor0; o[nt][1] *= cor0;
            o[nt][2] *= cor1; o[nt][3] *= cor1;
        }
        __syncwarp();

        #pragma unroll
        for (int ks2 = 0; ks2 < 8; ks2++) {
            uint32_t af[4];
            ldsm4(af[0], af[1], af[2], af[3], aP + ks2 * 32);
            uint32_t bf2[8][2];
            #pragma unroll
            for (int p = 0; p < 4; p++) {
                const uint32_t addr =
                    sV + (uint32_t)((ks2 * 16 + ((lq & 1) << 3) + lr) * 72
                                    + p * 16 + ((lq >> 1) << 3)) * 2;
                ldsm4_t(bf2[2 * p][0], bf2[2 * p][1], bf2[2 * p + 1][0], bf2[2 * p + 1][1], addr);
            }
            #pragma unroll
            for (int nt = 0; nt < 8; nt++)
                mma_h(o[nt], af, bf2[nt]);
        }
        __syncthreads();
    }

    const float inv0 = 1.f / l0, inv1 = 1.f / l1;
    __half* ob = out + ((size_t)b * 1024 + q0 + wm + (lane >> 2)) * 1024 + h * 64 + 2 * (lane & 3);
    #pragma unroll
    for (int nt = 0; nt < 8; nt++) {
        *(__half2*)(ob + nt * 8) = __floats2half2_rn(o[nt][0] * inv0, o[nt][1] * inv0);
        *(__half2*)(ob + 8 * 1024 + nt * 8) = __floats2half2_rn(o[nt][2] * inv1, o[nt][3] * inv1);
    }
}

// ---------------------------------------------------------------------------
// LayerNorm over D=1024, f32 in -> half out.
// ---------------------------------------------------------------------------
__global__ __launch_bounds__(256) void ln_kernel(
    const float* __restrict__ in, const float* __restrict__ sc,
    const float* __restrict__ bi, __half* __restrict__ out)
{
    const int row = blockIdx.x;
    const int t = threadIdx.x;
    const float4* x4 = (const float4*)(in + (size_t)row * 1024);
    float4 v = x4[t];
    float s  = v.x + v.y + v.z + v.w;
    float ss = v.x * v.x + v.y * v.y + v.z * v.z + v.w * v.w;
    #pragma unroll
    for (int o = 16; o; o >>= 1) {
        s  += __shfl_xor_sync(0xffffffffu, s,  o);
        ss += __shfl_xor_sync(0xffffffffu, ss, o);
    }
    __shared__ float sred[8], ssred[8];
    if ((t & 31) == 0) { sred[t >> 5] = s; ssred[t >> 5] = ss; }
    __syncthreads();
    float tot = 0.f, tots = 0.f;
    #pragma unroll
    for (int w = 0; w < 8; w++) { tot += sred[w]; tots += ssred[w]; }
    const float mean = tot * (1.f / 1024.f);
    const float var  = tots * (1.f / 1024.f) - mean * mean;
    const float inv  = rsqrtf(var + EPSF);
    float4 sv = ((const float4*)sc)[t];
    float4 bv = ((const float4*)bi)[t];
    __half2* o2 = (__half2*)(out + (size_t)row * 1024);
    o2[t * 2 + 0] = __floats2half2_rn((v.x - mean) * inv * sv.x + bv.x,
                                      (v.y - mean) * inv * sv.y + bv.y);
    o2[t * 2 + 1] = __floats2half2_rn((v.z - mean) * inv * sv.z + bv.z,
                                      (v.w - mean) * inv * sv.w + bv.w);
}

// ---------------------------------------------------------------------------
// QK-norm for q AND k in one launch (blockIdx.y selects tensor).
// ---------------------------------------------------------------------------
__global__ __launch_bounds__(256) void qknorm2_kernel(
    __half* __restrict__ q, __half* __restrict__ k,
    const float* __restrict__ qs, const float* __restrict__ qb,
    const float* __restrict__ ks, const float* __restrict__ kb)
{
    __half* base = blockIdx.y ? k : q;
    const float* sc = blockIdx.y ? ks : qs;
    const float* bi = blockIdx.y ? kb : qb;
    const int gw   = (blockIdx.x * 256 + threadIdx.x) >> 5;
    const int lane = threadIdx.x & 31;
    const int h  = gw & 15;
    const int bs = gw >> 4;
    __half2* p = (__half2*)(base + (size_t)bs * 1024 + h * 64) + lane;
    float2 v = __half22float2(*p);
    float s  = v.x + v.y;
    float ss = v.x * v.x + v.y * v.y;
    #pragma unroll
    for (int o = 16; o; o >>= 1) {
        s  += __shfl_xor_sync(0xffffffffu, s,  o);
        ss += __shfl_xor_sync(0xffffffffu, ss, o);
    }
    const float mean = s * (1.f / 64.f);
    const float var  = ss * (1.f / 64.f) - mean * mean;
    const float inv  = rsqrtf(var + EPSF);
    const float* scp = sc + h * 64 + lane * 2;
    const float* bip = bi + h * 64 + lane * 2;
    *p = __floats2half2_rn((v.x - mean) * inv * scp[0] + bip[0],
                           (v.y - mean) * inv * scp[1] + bip[1]);
}

// ---------------------------------------------------------------------------
// Launch
// ---------------------------------------------------------------------------
extern "C" void kernel_launch(void* const* d_in, const int* in_sizes, int n_in,
                              void* d_out, int out_size)
{
    (void)in_sizes; (void)n_in; (void)out_size;
    const float* x     = (const float*)d_in[0];
    const float* ln1_s = (const float*)d_in[2];
    const float* ln1_b = (const float*)d_in[3];
    const float* Wq    = (const float*)d_in[4];
    const float* bq    = (const float*)d_in[5];
    const float* Wk    = (const float*)d_in[6];
    const float* bk    = (const float*)d_in[7];
    const float* Wv    = (const float*)d_in[8];
    const float* bv    = (const float*)d_in[9];
    const float* qn_s  = (const float*)d_in[10];
    const float* qn_b  = (const float*)d_in[11];
    const float* kn_s  = (const float*)d_in[12];
    const float* kn_b  = (const float*)d_in[13];
    const float* Wo    = (const float*)d_in[14];
    const float* bo    = (const float*)d_in[15];
    const float* ln2_s = (const float*)d_in[16];
    const float* ln2_b = (const float*)d_in[17];
    const float* W1    = (const float*)d_in[18];
    const float* b1    = (const float*)d_in[19];
    const float* W2    = (const float*)d_in[20];
    const float* b2    = (const float*)d_in[21];
    const float* W3    = (const float*)d_in[22];
    const float* b3    = (const float*)d_in[23];

    void *p_xn, *p_qkv, *p_att, *p_res, *p_big, *p_wt, *p_bias;
    cudaGetSymbolAddress(&p_xn,   g_xn);
    cudaGetSymbolAddress(&p_qkv,  g_qkv);
    cudaGetSymbolAddress(&p_att,  g_att);
    cudaGetSymbolAddress(&p_res,  g_res);
    cudaGetSymbolAddress(&p_big,  g_big);
    cudaGetSymbolAddress(&p_wt,   g_wt);
    cudaGetSymbolAddress(&p_bias, g_bias);

    __half* xn  = (__half*)p_xn;
    __half* qkv = (__half*)p_qkv;
    __half* qh  = qkv;
    __half* kh  = qkv + (size_t)4194304;
    __half* vh  = qkv + (size_t)8388608;
    __half* att = (__half*)p_att;
    float*  res = (float*)p_res;
    __half* wt  = (__half*)p_wt;
    __half* hbuf = (__half*)p_big;
    float*  bsc = (float*)p_bias;
    float* out = (float*)d_out;

    cudaFuncSetAttribute(flash_h, cudaFuncAttributeMaxDynamicSharedMemorySize, FL_SMEM);
    cudaFuncSetAttribute(gemm_h<0>, cudaFuncAttributeMaxDynamicSharedMemorySize, GE_SMEM);
    cudaFuncSetAttribute(gemm_h<1>, cudaFuncAttributeMaxDynamicSharedMemorySize, GE_SMEM);
    cudaFuncSetAttribute(ffn_gemm, cudaFuncAttributeMaxDynamicSharedMemorySize, FF_SMEM);

    const size_t MB1 = 1024 * 1024;
    __half* wqkv = wt;                 // [1024][3072]
    __half* wo   = wt + 3 * MB1;       // [1024][1024]
    __half* w12  = wt + 4 * MB1;       // [1024][8192]
    __half* w3   = wt + 12 * MB1;      // [4096][1024]

    // 0. weight conversions + bias concat
    f2h_copy4<<<dim3(512, 1, 4), 256>>>(Wq, Wk, Wv, Wo,
                                        wqkv, wqkv + 1024, wqkv + 2048, wo,
                                        1024, 3072, 3072, 3072, 1024);
    f2h_copy4<<<dim3(2048, 1, 2), 256>>>(W1, W2, W1, W2,
                                         w12, w12 + 4096, w12, w12 + 4096,
                                         4096, 8192, 8192, 8192, 8192);
    f2h_copy4<<<dim3(2048, 1, 1), 256>>>(W3, W3, W3, W3, w3, w3, w3, w3,
                                         1024, 1024, 1024, 1024, 1024);
    concat_bias<<<44, 256>>>(bsc, bq, bk, bv, b1, b2);

    // 1. LN1 -> xn
    ln_kernel<<<4096, 256>>>(x, ln1_s, ln1_b, xn);

    // 2. fused QKV projection
    gemm_h<0><<<dim3(24, 32), 256, GE_SMEM>>>(xn, wqkv, bsc, nullptr, qkv,
                                              1024, 1024, 3072, 1024, 4194304);

    // 3. QK-norm
    qknorm2_kernel<<<dim3(8192, 2), 256>>>(qh, kh, qn_s, qn_b, kn_s, kn_b);

    // 4. flash attention -> att
    flash_h<<<dim3(8, 64), 256, FL_SMEM>>>(qh, kh, vh, att);

    // 5. O projection + residual (f32 out)
    gemm_h<1><<<dim3(8, 32), 256, GE_SMEM>>>(att, wo, bo, x, res, 1024, 1024, 1024, 0, 1024);

    // 6. LN2 -> xn
    ln_kernel<<<4096, 256>>>(res, ln2_s, ln2_b, xn);

    // 7. fused FFN-up + GeGLU -> h (M=4096, N=4096)
    ffn_gemm<<<dim3(64, 32), 256, FF_SMEM>>>(xn, w12, bsc + 4096, hbuf);

    // 8. Down projection + residual -> d_out (M=4096, N=1024, K=4096)
    gemm_h<1><<<dim3(8, 32), 256, GE_SMEM>>>(hbuf, w3, b3, res, out, 4096, 4096, 1024, 0, 1024);
}

// round 15
// speedup vs baseline: 1.0780x; 1.0236x over previous
#include <cuda_runtime.h>
#include <cuda_fp16.h>
#include <math.h>
#include <stdint.h>

#define EPSF 1e-6f

// Problem constants: B=4, S=1024, D=1024, H=16, DH=64, F=4096, M=B*S=4096
__device__ float g_xn  [4096 * 1024 / 2];    // xn (half)
__device__ float g_qkv [6 * 1024 * 1024];    // q|k|v (half, 3 x 4M halves)
__device__ float g_att [2 * 1024 * 1024];    // attn_out (half)
__device__ float g_res [4096 * 1024];        // residual after attention (f32)
__device__ float g_big [16 * 1024 * 1024];   // h (half, 16M halves) + spare
__device__ float g_wt  [8 * 1024 * 1024];    // half weights, native [K][N] (16M halves)
__device__ float g_bias[16384];              // b_qkv (3072) @0, b12 (8192) @4096

// ---------------------------------------------------------------------------
// Helpers
// ---------------------------------------------------------------------------
__device__ __forceinline__ void cp_async16(uint32_t dst, const void* src)
{
    asm volatile("cp.async.cg.shared.global [%0], [%1], 16;\n" :: "r"(dst), "l"(src));
}
__device__ __forceinline__ void cp_commit() { asm volatile("cp.async.commit_group;\n"); }
__device__ __forceinline__ void cp_wait0()  { asm volatile("cp.async.wait_group 0;\n"); }

__device__ __forceinline__ uint32_t smem_u32(const void* p)
{
    uint32_t a;
    asm("{ .reg .u64 t; cvta.to.shared.u64 t, %1; cvt.u32.u64 %0, t; }" : "=r"(a) : "l"(p));
    return a;
}
__device__ __forceinline__ void ldsm4(uint32_t& r0, uint32_t& r1, uint32_t& r2, uint32_t& r3,
                                      uint32_t a)
{
    asm volatile("ldmatrix.sync.aligned.m8n8.x4.shared.b16 {%0,%1,%2,%3}, [%4];"
                 : "=r"(r0), "=r"(r1), "=r"(r2), "=r"(r3) : "r"(a));
}
__device__ __forceinline__ void ldsm4_t(uint32_t& r0, uint32_t& r1, uint32_t& r2, uint32_t& r3,
                                        uint32_t a)
{
    asm volatile("ldmatrix.sync.aligned.m8n8.x4.trans.shared.b16 {%0,%1,%2,%3}, [%4];"
                 : "=r"(r0), "=r"(r1), "=r"(r2), "=r"(r3) : "r"(a));
}
__device__ __forceinline__ void mma_h(float c[4], const uint32_t a[4], const uint32_t b[2])
{
    asm volatile(
        "mma.sync.aligned.m16n8k16.row.col.f32.f16.f16.f32 "
        "{%0,%1,%2,%3}, {%4,%5,%6,%7}, {%8,%9}, {%0,%1,%2,%3};\n"
        : "+f"(c[0]), "+f"(c[1]), "+f"(c[2]), "+f"(c[3])
        : "r"(a[0]), "r"(a[1]), "r"(a[2]), "r"(a[3]), "r"(b[0]), "r"(b[1]));
}

__device__ __forceinline__ float gelu_t(float x)
{
    return 0.5f * x * (1.f + tanhf(0.7978845608028654f * (x + 0.044715f * x * x * x)));
}

// ---------------------------------------------------------------------------
// Dense fp16 GEMM: BM=128 BN=128 BK=64, 8 warps (64x32), double buffer.
// A [M][K] stride-72; B native [K][N] stride-136 + ldsm.trans.
// ONE barrier per K-iteration (end-of-loop barrier removed: the top barrier
// after cp.wait already orders compute-before-overwrite across warps).
// MODE 0: half out, segmented columns. MODE 1: float out = acc + bias + Res.
// ---------------------------------------------------------------------------
#define GE_A_STAGE (128 * 72 * 2)                // 18432 B
#define GE_B_STAGE (64 * 136 * 2)                // 17408 B
#define GE_SMEM (2 * (GE_A_STAGE + GE_B_STAGE))  // 71680 B

template <int MODE>
__global__ __launch_bounds__(256) void gemm_h(
    const __half* __restrict__ A, const __half* __restrict__ B,
    const float* __restrict__ bias, const float* __restrict__ Res,
    void* __restrict__ Cv, int K, int lda, int ldb, int segW, int segStride)
{
    extern __shared__ __half gsm[];
    const uint32_t sA = smem_u32(gsm);
    const uint32_t sB = sA + 2 * GE_A_STAGE;

    const int t    = threadIdx.x;
    const int lane = t & 31;
    const int warp = t >> 5;
    const size_t m0 = (size_t)blockIdx.y * 128;
    const size_t n0 = (size_t)blockIdx.x * 128;
    const int wm = (warp >> 2) * 64;
    const int wn = (warp & 3) * 32;

    uint32_t dA[4], dB[4];
    const __half* aS[4];
    const __half* bS[4];
    #pragma unroll
    for (int i = 0; i < 4; i++) {
        const int ia = t + 256 * i;
        const int rowA = ia >> 3, cA = ia & 7;
        dA[i] = (uint32_t)(rowA * 72 + cA * 8) * 2;
        aS[i] = A + (m0 + rowA) * lda + cA * 8;
        const int rowB = ia >> 4, cB = ia & 15;
        dB[i] = (uint32_t)(rowB * 136 + cB * 8) * 2;
        bS[i] = B + (size_t)rowB * ldb + n0 + cB * 8;
    }

    const int lq = lane >> 3, lr = lane & 7;
    uint32_t aAddr[4];
    #pragma unroll
    for (int mt = 0; mt < 4; mt++)
        aAddr[mt] = sA + (uint32_t)((wm + mt * 16 + ((lq & 1) << 3) + lr) * 72 + ((lq >> 1) << 3)) * 2;
    const uint32_t bBase = sB + (uint32_t)((((lq & 1) << 3) + lr) * 136 + wn + ((lq >> 1) << 3)) * 2;

    float acc[4][4][4];
    #pragma unroll
    for (int mt = 0; mt < 4; mt++)
        #pragma unroll
        for (int nt = 0; nt < 4; nt++)
            #pragma unroll
            for (int i = 0; i < 4; i++) acc[mt][nt][i] = 0.f;

    #pragma unroll
    for (int i = 0; i < 4; i++) {
        cp_async16(sA + dA[i], aS[i]);
        cp_async16(sB + dB[i], bS[i]);
    }
    cp_commit();

    const int nIter = K >> 6;
    for (int it = 0; it < nIter; ++it) {
        cp_wait0();
        __syncthreads();
        const int buf = it & 1;
        if (it + 1 < nIter) {
            const int k0 = (it + 1) << 6;
            const uint32_t offA = (buf ^ 1) * GE_A_STAGE;
            const uint32_t offB = (buf ^ 1) * GE_B_STAGE;
            #pragma unroll
            for (int i = 0; i < 4; i++) {
                cp_async16(sA + offA + dA[i], aS[i] + k0);
                cp_async16(sB + offB + dB[i], bS[i] + (size_t)k0 * ldb);
            }
            cp_commit();
        }
        const uint32_t offA = buf * GE_A_STAGE;
        const uint32_t offB = buf * GE_B_STAGE;
        #pragma unroll
        for (int ks = 0; ks < 4; ks++) {
            uint32_t af[4][4];
            #pragma unroll
            for (int mt = 0; mt < 4; mt++)
                ldsm4(af[mt][0], af[mt][1], af[mt][2], af[mt][3], aAddr[mt] + offA + ks * 32);
            uint32_t bf[4][2];
            #pragma unroll
            for (int p = 0; p < 2; p++)
                ldsm4_t(bf[2 * p][0], bf[2 * p][1], bf[2 * p + 1][0], bf[2 * p + 1][1],
                        bBase + offB + (uint32_t)(ks * 16 * 136 + p * 16) * 2);
            #pragma unroll
            for (int mt = 0; mt < 4; mt++)
                #pragma unroll
                for (int nt = 0; nt < 4; nt++)
                    mma_h(acc[mt][nt], af[mt], bf[nt]);
        }
        // no trailing barrier: next iteration's top barrier provides ordering
    }

    if (MODE == 0) {
        const int seg  = (int)(n0 / segW);
        const int ncol = (int)(n0 % segW);
        __half* Cb = (__half*)Cv + (size_t)seg * segStride + m0 * segW + ncol;
        #pragma unroll
        for (int mt = 0; mt < 4; mt++) {
            const int r0 = wm + mt * 16 + (lane >> 2);
            #pragma unroll
            for (int nt = 0; nt < 4; nt++) {
                const int c = wn + nt * 8 + (lane & 3) * 2;
                const float b0 = bias[n0 + c], b1 = bias[n0 + c + 1];
                *(__half2*)(Cb + (size_t)r0 * segW + c) =
                    __floats2half2_rn(acc[mt][nt][0] + b0, acc[mt][nt][1] + b1);
                *(__half2*)(Cb + (size_t)(r0 + 8) * segW + c) =
                    __floats2half2_rn(acc[mt][nt][2] + b0, acc[mt][nt][3] + b1);
            }
        }
    } else {
        const int ldc = segStride;
        float* Cb = (float*)Cv + m0 * ldc + n0;
        const float* Rb = Res + m0 * ldc + n0;
        #pragma unroll
        for (int mt = 0; mt < 4; mt++) {
            const int r0 = wm + mt * 16 + (lane >> 2);
            #pragma unroll
            for (int nt = 0; nt < 4; nt++) {
                const int c = wn + nt * 8 + (lane & 3) * 2;
                const float b0 = bias[n0 + c], b1 = bias[n0 + c + 1];
                float2 ra = *(const float2*)(Rb + (size_t)r0 * ldc + c);
                float2 rb = *(const float2*)(Rb + (size_t)(r0 + 8) * ldc + c);
                *(float2*)(Cb + (size_t)r0 * ldc + c) =
                    make_float2(acc[mt][nt][0] + b0 + ra.x, acc[mt][nt][1] + b1 + ra.y);
                *(float2*)(Cb + (size_t)(r0 + 8) * ldc + c) =
                    make_float2(acc[mt][nt][2] + b0 + rb.x, acc[mt][nt][3] + b1 + rb.y);
            }
        }
    }
}

// ---------------------------------------------------------------------------
// Fused FFN-up + GeGLU (round-14 proven), one barrier per K-iteration.
// ---------------------------------------------------------------------------
#define FF_A_STAGE (128 * 72 * 2)                // 18432 B
#define FF_B_STAGE (2 * 64 * 72 * 2)             // 18432 B
#define FF_SMEM (2 * (FF_A_STAGE + FF_B_STAGE))  // 73728 B

__global__ __launch_bounds__(256) void ffn_gemm(
    const __half* __restrict__ A, const __half* __restrict__ W12,
    const float* __restrict__ b12, __half* __restrict__ Hout)
{
    extern __shared__ __half fsm[];
    const uint32_t sA = smem_u32(fsm);
    const uint32_t sB = sA + 2 * FF_A_STAGE;

    const int t    = threadIdx.x;
    const int lane = t & 31;
    const int warp = t >> 5;
    const size_t m0 = (size_t)blockIdx.y * 128;
    const size_t n0 = (size_t)blockIdx.x * 64;
    const int wm = (warp >> 1) * 32;
    const int wn = (warp & 1) * 32;

    uint32_t dA[4], dB[4];
    const __half* aS[4];
    const __half* bS[4];
    #pragma unroll
    for (int i = 0; i < 4; i++) {
        const int ia = t + 256 * i;
        const int rowA = ia >> 3, cA = ia & 7;
        dA[i] = (uint32_t)(rowA * 72 + cA * 8) * 2;
        aS[i] = A + (m0 + rowA) * 1024 + cA * 8;
        const int tile = ia >> 9;
        const int i9 = ia & 511;
        const int rowB = i9 >> 3, cB = i9 & 7;
        dB[i] = (uint32_t)(tile * 64 * 72 + rowB * 72 + cB * 8) * 2;
        bS[i] = W12 + (size_t)rowB * 8192 + n0 + tile * 4096 + cB * 8;
    }

    const int lq = lane >> 3, lr = lane & 7;
    uint32_t aAddr[2];
    #pragma unroll
    for (int mt = 0; mt < 2; mt++)
        aAddr[mt] = sA + (uint32_t)((wm + mt * 16 + ((lq & 1) << 3) + lr) * 72 + ((lq >> 1) << 3)) * 2;
    const uint32_t bB0 = sB + (uint32_t)((((lq & 1) << 3) + lr) * 72 + wn + ((lq >> 1) << 3)) * 2;
    const uint32_t bB1 = bB0 + (uint32_t)(64 * 72) * 2;

    float acc1[2][4][4], acc2[2][4][4];
    #pragma unroll
    for (int mt = 0; mt < 2; mt++)
        #pragma unroll
        for (int nt = 0; nt < 4; nt++)
            #pragma unroll
            for (int i = 0; i < 4; i++) { acc1[mt][nt][i] = 0.f; acc2[mt][nt][i] = 0.f; }

    #pragma unroll
    for (int i = 0; i < 4; i++) {
        cp_async16(sA + dA[i], aS[i]);
        cp_async16(sB + dB[i], bS[i]);
    }
    cp_commit();

    const int nIter = 16;   // K = 1024
    for (int it = 0; it < nIter; ++it) {
        cp_wait0();
        __syncthreads();
        const int buf = it & 1;
        if (it + 1 < nIter) {
            const int k0 = (it + 1) << 6;
            const uint32_t offA = (buf ^ 1) * FF_A_STAGE;
            const uint32_t offB = (buf ^ 1) * FF_B_STAGE;
            #pragma unroll
            for (int i = 0; i < 4; i++) {
                cp_async16(sA + offA + dA[i], aS[i] + k0);
                cp_async16(sB + offB + dB[i], bS[i] + (size_t)k0 * 8192);
            }
            cp_commit();
        }
        const uint32_t offA = buf * FF_A_STAGE;
        const uint32_t offB = buf * FF_B_STAGE;
        #pragma unroll
        for (int ks = 0; ks < 4; ks++) {
            uint32_t af[2][4];
            #pragma unroll
            for (int mt = 0; mt < 2; mt++)
                ldsm4(af[mt][0], af[mt][1], af[mt][2], af[mt][3], aAddr[mt] + offA + ks * 32);
            uint32_t bf1[4][2], bf2[4][2];
            #pragma unroll
            for (int p = 0; p < 2; p++) {
                const uint32_t kOff = (uint32_t)(ks * 16 * 72 + p * 16) * 2;
                ldsm4_t(bf1[2 * p][0], bf1[2 * p][1], bf1[2 * p + 1][0], bf1[2 * p + 1][1],
                        bB0 + offB + kOff);
                ldsm4_t(bf2[2 * p][0], bf2[2 * p][1], bf2[2 * p + 1][0], bf2[2 * p + 1][1],
                        bB1 + offB + kOff);
            }
            #pragma unroll
            for (int mt = 0; mt < 2; mt++)
                #pragma unroll
                for (int nt = 0; nt < 4; nt++) {
                    mma_h(acc1[mt][nt], af[mt], bf1[nt]);
                    mma_h(acc2[mt][nt], af[mt], bf2[nt]);
                }
        }
        // no trailing barrier (double-buffered; top barrier orders overwrite)
    }

    __half* Hb = Hout + m0 * 4096 + n0;
    #pragma unroll
    for (int mt = 0; mt < 2; mt++) {
        const int r0 = wm + mt * 16 + (lane >> 2);
        #pragma unroll
        for (int nt = 0; nt < 4; nt++) {
            const int c = wn + nt * 8 + (lane & 3) * 2;
            const float p0 = b12[n0 + c], p1 = b12[n0 + c + 1];
            const float q0 = b12[4096 + n0 + c], q1 = b12[4096 + n0 + c + 1];
            float h00 = (acc1[mt][nt][0] + p0) * gelu_t(acc2[mt][nt][0] + q0);
            float h01 = (acc1[mt][nt][1] + p1) * gelu_t(acc2[mt][nt][1] + q1);
            float h10 = (acc1[mt][nt][2] + p0) * gelu_t(acc2[mt][nt][2] + q0);
            float h11 = (acc1[mt][nt][3] + p1) * gelu_t(acc2[mt][nt][3] + q1);
            *(__half2*)(Hb + (size_t)r0 * 4096 + c)       = __floats2half2_rn(h00, h01);
            *(__half2*)(Hb + (size_t)(r0 + 8) * 4096 + c) = __floats2half2_rn(h10, h11);
        }
    }
}

// ---------------------------------------------------------------------------
// Unified prep: z = 0..6 -> f32->f16 weight copies; z = 7 -> bias concat.
// Copy slices sized for the largest source; small sources guard by total.
// ---------------------------------------------------------------------------
__global__ __launch_bounds__(256) void prep_all(
    const float* __restrict__ Wq, const float* __restrict__ Wk,
    const float* __restrict__ Wv, const float* __restrict__ Wo,
    const float* __restrict__ W1, const float* __restrict__ W2,
    const float* __restrict__ W3,
    __half* __restrict__ wqkv, __half* __restrict__ wo,
    __half* __restrict__ w12, __half* __restrict__ w3,
    float* __restrict__ bdst,
    const float* __restrict__ bq, const float* __restrict__ bk,
    const float* __restrict__ bv, const float* __restrict__ b1,
    const float* __restrict__ b2)
{
    const int z = blockIdx.z;
    if (z == 7) {
        const int i = blockIdx.x * 256 + threadIdx.x;
        if (i < 1024)       bdst[i] = bq[i];
        else if (i < 2048)  bdst[i] = bk[i - 1024];
        else if (i < 3072)  bdst[i] = bv[i - 2048];
        else if (i < 3072 + 4096) bdst[1024 + i] = b1[i - 3072];
        else if (i < 3072 + 8192) bdst[1024 + i] = b2[i - 7168];
        return;
    }
    const float* src;
    __half* dst;
    int C, ld;
    size_t total;
    switch (z) {
        case 0: src = Wq; dst = wqkv;        C = 1024; ld = 3072; total = 1048576; break;
        case 1: src = Wk; dst = wqkv + 1024; C = 1024; ld = 3072; total = 1048576; break;
        case 2: src = Wv; dst = wqkv + 2048; C = 1024; ld = 3072; total = 1048576; break;
        case 3: src = Wo; dst = wo;          C = 1024; ld = 1024; total = 1048576; break;
        case 4: src = W1; dst = w12;         C = 4096; ld = 8192; total = 4194304; break;
        case 5: src = W2; dst = w12 + 4096;  C = 4096; ld = 8192; total = 4194304; break;
        default: src = W3; dst = w3;         C = 1024; ld = 1024; total = 4194304; break;
    }
    const size_t i = ((size_t)blockIdx.x * 256 + threadIdx.x) * 8;
    if (i >= total) return;
    const int r = (int)(i / C);
    const int c = (int)(i % C);
    float4 v0 = *(const float4*)(src + i);
    float4 v1 = *(const float4*)(src + i + 4);
    __half2 h[4];
    h[0] = __floats2half2_rn(v0.x, v0.y);
    h[1] = __floats2half2_rn(v0.z, v0.w);
    h[2] = __floats2half2_rn(v1.x, v1.y);
    h[3] = __floats2half2_rn(v1.z, v1.w);
    *(uint4*)(dst + (size_t)r * ld + c) = *(uint4*)h;
}

// ---------------------------------------------------------------------------
// Flash attention fp16 (round-13 proven; barriers unchanged — K/V smem is
// reused every iteration so the end barrier is required here).
// ---------------------------------------------------------------------------
#define FL_SMEM ((128 * 72 + 128 * 72 + 128 * 136) * 2)

__global__ __launch_bounds__(256) void flash_h(
    const __half* __restrict__ q, const __half* __restrict__ k,
    const __half* __restrict__ v, __half* __restrict__ out)
{
    extern __shared__ __half smh[];
    const uint32_t sK = smem_u32(smh);
    const uint32_t sV = sK + 128 * 72 * 2;
    const uint32_t sP = sV + 128 * 72 * 2;
    __half* sPh = smh + 128 * 72 + 128 * 72;

    const int t = threadIdx.x;
    const int lane = t & 31, warp = t >> 5;
    const int lq = lane >> 3, lr = lane & 7;
    const int bh = blockIdx.y, b = bh >> 4, h = bh & 15;
    const int q0 = blockIdx.x * 128;
    const int wm = warp * 16;

    const __half* qb = q + ((size_t)b * 1024 + q0) * 1024 + h * 64;
    const __half* kb = k + ((size_t)b << 20) + h * 64;
    const __half* vb = v + ((size_t)b << 20) + h * 64;

    {
        #pragma unroll
        for (int i = 0; i < 4; i++) {
            const int idx = t + 256 * i;
            const int row = idx >> 3, c = idx & 7;
            cp_async16(sP + (uint32_t)(row * 72 + c * 8) * 2, qb + (size_t)row * 1024 + c * 8);
        }
    }
    cp_commit(); cp_wait0(); __syncthreads();

    uint32_t qf[4][4];
    {
        const uint32_t a0 = sP + (uint32_t)((wm + ((lq & 1) << 3) + lr) * 72 + ((lq >> 1) << 3)) * 2;
        #pragma unroll
        for (int ks = 0; ks < 4; ks++)
            ldsm4(qf[ks][0], qf[ks][1], qf[ks][2], qf[ks][3], a0 + ks * 32);
    }
    __syncthreads();

    float o[8][4];
    #pragma unroll
    for (int i = 0; i < 8; i++)
        #pragma unroll
        for (int j = 0; j < 4; j++) o[i][j] = 0.f;
    float m0 = -1e30f, m1 = -1e30f, l0 = 0.f, l1 = 0.f;

    const uint32_t aP = sP + (uint32_t)((wm + ((lq & 1) << 3) + lr) * 136 + ((lq >> 1) << 3)) * 2;

    for (int it = 0; it < 8; ++it) {
        const int kt0 = it * 128;
        #pragma unroll
        for (int i = 0; i < 4; i++) {
            const int idx = t + 256 * i;
            const int row = idx >> 3, c = idx & 7;
            cp_async16(sK + (uint32_t)(row * 72 + c * 8) * 2,
                       kb + (size_t)(kt0 + row) * 1024 + c * 8);
            cp_async16(sV + (uint32_t)(row * 72 + c * 8) * 2,
                       vb + (size_t)(kt0 + row) * 1024 + c * 8);
        }
        cp_commit(); cp_wait0(); __syncthreads();

        float s[16][4];
        #pragma unroll
        for (int i = 0; i < 16; i++)
            #pragma unroll
            for (int j = 0; j < 4; j++) s[i][j] = 0.f;
        #pragma unroll
        for (int ks = 0; ks < 4; ks++) {
            uint32_t bf[16][2];
            #pragma unroll
            for (int p = 0; p < 8; p++) {
                const uint32_t addr =
                    sK + (uint32_t)((p * 16 + ((lq >> 1) << 3) + lr) * 72 + ((lq & 1) << 3)) * 2
                       + ks * 32;
                ldsm4(bf[2 * p][0], bf[2 * p][1], bf[2 * p + 1][0], bf[2 * p + 1][1], addr);
            }
            #pragma unroll
            for (int nt = 0; nt < 16; nt++)
                mma_h(s[nt], qf[ks], bf[nt]);
        }

        float c0v = -1e30f, c1v = -1e30f;
        #pragma unroll
        for (int nt = 0; nt < 16; nt++) {
            c0v = fmaxf(c0v, fmaxf(s[nt][0], s[nt][1]));
            c1v = fmaxf(c1v, fmaxf(s[nt][2], s[nt][3]));
        }
        c0v = fmaxf(c0v, __shfl_xor_sync(0xffffffffu, c0v, 1));
        c0v = fmaxf(c0v, __shfl_xor_sync(0xffffffffu, c0v, 2));
        c1v = fmaxf(c1v, __shfl_xor_sync(0xffffffffu, c1v, 1));
        c1v = fmaxf(c1v, __shfl_xor_sync(0xffffffffu, c1v, 2));
        const float m0n = fmaxf(m0, c0v * 0.125f);
        const float m1n = fmaxf(m1, c1v * 0.125f);
        const float cor0 = __expf(m0 - m0n);
        const float cor1 = __expf(m1 - m1n);
        m0 = m0n; m1 = m1n;
        float sum0 = 0.f, sum1 = 0.f;
        {
            __half* pr0 = sPh + (size_t)(wm + (lane >> 2)) * 136 + 2 * (lane & 3);
            __half* pr1 = pr0 + 8 * 136;
            #pragma unroll
            for (int nt = 0; nt < 16; nt++) {
                float p0 = __expf(fmaf(0.125f, s[nt][0], -m0n));
                float p1 = __expf(fmaf(0.125f, s[nt][1], -m0n));
                float p2 = __expf(fmaf(0.125f, s[nt][2], -m1n));
                float p3 = __expf(fmaf(0.125f, s[nt][3], -m1n));
                sum0 += p0 + p1; sum1 += p2 + p3;
                *(__half2*)(pr0 + nt * 8) = __floats2half2_rn(p0, p1);
                *(__half2*)(pr1 + nt * 8) = __floats2half2_rn(p2, p3);
            }
        }
        sum0 += __shfl_xor_sync(0xffffffffu, sum0, 1);
        sum0 += __shfl_xor_sync(0xffffffffu, sum0, 2);
        sum1 += __shfl_xor_sync(0xffffffffu, sum1, 1);
        sum1 += __shfl_xor_sync(0xffffffffu, sum1, 2);
        l0 = l0 * cor0 + sum0;
        l1 = l1 * cor1 + sum1;
        #pragma unroll
        for (int nt = 0; nt < 8; nt++) {
            o[nt][0] *= cor0; o[nt][1] *= cor0;
            o[nt][2] *= cor1; o[nt][3] *= cor1;
        }
        __syncwarp();

        #pragma unroll
        for (int ks2 = 0; ks2 < 8; ks2++) {
            uint32_t af[4];
            ldsm4(af[0], af[1], af[2], af[3], aP + ks2 * 32);
            uint32_t bf2[8][2];
            #pragma unroll
            for (int p = 0; p < 4; p++) {
                const uint32_t addr =
                    sV + (uint32_t)((ks2 * 16 + ((lq & 1) << 3) + lr) * 72
                                    + p * 16 + ((lq >> 1) << 3)) * 2;
                ldsm4_t(bf2[2 * p][0], bf2[2 * p][1], bf2[2 * p + 1][0], bf2[2 * p + 1][1], addr);
            }
            #pragma unroll
            for (int nt = 0; nt < 8; nt++)
                mma_h(o[nt], af, bf2[nt]);
        }
        __syncthreads();
    }

    const float inv0 = 1.f / l0, inv1 = 1.f / l1;
    __half* ob = out + ((size_t)b * 1024 + q0 + wm + (lane >> 2)) * 1024 + h * 64 + 2 * (lane & 3);
    #pragma unroll
    for (int nt = 0; nt < 8; nt++) {
        *(__half2*)(ob + nt * 8) = __floats2half2_rn(o[nt][0] * inv0, o[nt][1] * inv0);
        *(__half2*)(ob + 8 * 1024 + nt * 8) = __floats2half2_rn(o[nt][2] * inv1, o[nt][3] * inv1);
    }
}

// ---------------------------------------------------------------------------
// LayerNorm over D=1024, f32 in -> half out.
// ---------------------------------------------------------------------------
__global__ __launch_bounds__(256) void ln_kernel(
    const float* __restrict__ in, const float* __restrict__ sc,
    const float* __restrict__ bi, __half* __restrict__ out)
{
    const int row = blockIdx.x;
    const int t = threadIdx.x;
    const float4* x4 = (const float4*)(in + (size_t)row * 1024);
    float4 v = x4[t];
    float s  = v.x + v.y + v.z + v.w;
    float ss = v.x * v.x + v.y * v.y + v.z * v.z + v.w * v.w;
    #pragma unroll
    for (int o = 16; o; o >>= 1) {
        s  += __shfl_xor_sync(0xffffffffu, s,  o);
        ss += __shfl_xor_sync(0xffffffffu, ss, o);
    }
    __shared__ float sred[8], ssred[8];
    if ((t & 31) == 0) { sred[t >> 5] = s; ssred[t >> 5] = ss; }
    __syncthreads();
    float tot = 0.f, tots = 0.f;
    #pragma unroll
    for (int w = 0; w < 8; w++) { tot += sred[w]; tots += ssred[w]; }
    const float mean = tot * (1.f / 1024.f);
    const float var  = tots * (1.f / 1024.f) - mean * mean;
    const float inv  = rsqrtf(var + EPSF);
    float4 sv = ((const float4*)sc)[t];
    float4 bv = ((const float4*)bi)[t];
    __half2* o2 = (__half2*)(out + (size_t)row * 1024);
    o2[t * 2 + 0] = __floats2half2_rn((v.x - mean) * inv * sv.x + bv.x,
                                      (v.y - mean) * inv * sv.y + bv.y);
    o2[t * 2 + 1] = __floats2half2_rn((v.z - mean) * inv * sv.z + bv.z,
                                      (v.w - mean) * inv * sv.w + bv.w);
}

// ---------------------------------------------------------------------------
// QK-norm for q AND k in one launch (blockIdx.y selects tensor).
// ---------------------------------------------------------------------------
__global__ __launch_bounds__(256) void qknorm2_kernel(
    __half* __restrict__ q, __half* __restrict__ k,
    const float* __restrict__ qs, const float* __restrict__ qb,
    const float* __restrict__ ks, const float* __restrict__ kb)
{
    __half* base = blockIdx.y ? k : q;
    const float* sc = blockIdx.y ? ks : qs;
    const float* bi = blockIdx.y ? kb : qb;
    const int gw   = (blockIdx.x * 256 + threadIdx.x) >> 5;
    const int lane = threadIdx.x & 31;
    const int h  = gw & 15;
    const int bs = gw >> 4;
    __half2* p = (__half2*)(base + (size_t)bs * 1024 + h * 64) + lane;
    float2 v = __half22float2(*p);
    float s  = v.x + v.y;
    float ss = v.x * v.x + v.y * v.y;
    #pragma unroll
    for (int o = 16; o; o >>= 1) {
        s  += __shfl_xor_sync(0xffffffffu, s,  o);
        ss += __shfl_xor_sync(0xffffffffu, ss, o);
    }
    const float mean = s * (1.f / 64.f);
    const float var  = ss * (1.f / 64.f) - mean * mean;
    const float inv  = rsqrtf(var + EPSF);
    const float* scp = sc + h * 64 + lane * 2;
    const float* bip = bi + h * 64 + lane * 2;
    *p = __floats2half2_rn((v.x - mean) * inv * scp[0] + bip[0],
                           (v.y - mean) * inv * scp[1] + bip[1]);
}

// ---------------------------------------------------------------------------
// Launch
// ---------------------------------------------------------------------------
extern "C" void kernel_launch(void* const* d_in, const int* in_sizes, int n_in,
                              void* d_out, int out_size)
{
    (void)in_sizes; (void)n_in; (void)out_size;
    const float* x     = (const float*)d_in[0];
    const float* ln1_s = (const float*)d_in[2];
    const float* ln1_b = (const float*)d_in[3];
    const float* Wq    = (const float*)d_in[4];
    const float* bq    = (const float*)d_in[5];
    const float* Wk    = (const float*)d_in[6];
    const float* bk    = (const float*)d_in[7];
    const float* Wv    = (const float*)d_in[8];
    const float* bv    = (const float*)d_in[9];
    const float* qn_s  = (const float*)d_in[10];
    const float* qn_b  = (const float*)d_in[11];
    const float* kn_s  = (const float*)d_in[12];
    const float* kn_b  = (const float*)d_in[13];
    const float* Wo    = (const float*)d_in[14];
    const float* bo    = (const float*)d_in[15];
    const float* ln2_s = (const float*)d_in[16];
    const float* ln2_b = (const float*)d_in[17];
    const float* W1    = (const float*)d_in[18];
    const float* b1    = (const float*)d_in[19];
    const float* W2    = (const float*)d_in[20];
    const float* b2    = (const float*)d_in[21];
    const float* W3    = (const float*)d_in[22];
    const float* b3    = (const float*)d_in[23];

    void *p_xn, *p_qkv, *p_att, *p_res, *p_big, *p_wt, *p_bias;
    cudaGetSymbolAddress(&p_xn,   g_xn);
    cudaGetSymbolAddress(&p_qkv,  g_qkv);
    cudaGetSymbolAddress(&p_att,  g_att);
    cudaGetSymbolAddress(&p_res,  g_res);
    cudaGetSymbolAddress(&p_big,  g_big);
    cudaGetSymbolAddress(&p_wt,   g_wt);
    cudaGetSymbolAddress(&p_bias, g_bias);

    __half* xn  = (__half*)p_xn;
    __half* qkv = (__half*)p_qkv;
    __half* qh  = qkv;
    __half* kh  = qkv + (size_t)4194304;
    __half* vh  = qkv + (size_t)8388608;
    __half* att = (__half*)p_att;
    float*  res = (float*)p_res;
    __half* wt  = (__half*)p_wt;
    __half* hbuf = (__half*)p_big;
    float*  bsc = (float*)p_bias;
    float* out = (float*)d_out;

    cudaFuncSetAttribute(flash_h, cudaFuncAttributeMaxDynamicSharedMemorySize, FL_SMEM);
    cudaFuncSetAttribute(gemm_h<0>, cudaFuncAttributeMaxDynamicSharedMemorySize, GE_SMEM);
    cudaFuncSetAttribute(gemm_h<1>, cudaFuncAttributeMaxDynamicSharedMemorySize, GE_SMEM);
    cudaFuncSetAttribute(ffn_gemm, cudaFuncAttributeMaxDynamicSharedMemorySize, FF_SMEM);

    const size_t MB1 = 1024 * 1024;
    __half* wqkv = wt;                 // [1024][3072]
    __half* wo   = wt + 3 * MB1;       // [1024][1024]
    __half* w12  = wt + 4 * MB1;       // [1024][8192]
    __half* w3   = wt + 12 * MB1;      // [4096][1024]

    // 0. unified prep: 7 weight copies + bias concat, one launch
    prep_all<<<dim3(2048, 1, 8), 256>>>(Wq, Wk, Wv, Wo, W1, W2, W3,
                                        wqkv, wo, w12, w3,
                                        bsc, bq, bk, bv, b1, b2);

    // 1. LN1 -> xn
    ln_kernel<<<4096, 256>>>(x, ln1_s, ln1_b, xn);

    // 2. fused QKV projection
    gemm_h<0><<<dim3(24, 32), 256, GE_SMEM>>>(xn, wqkv, bsc, nullptr, qkv,
                                              1024, 1024, 3072, 1024, 4194304);

    // 3. QK-norm
    qknorm2_kernel<<<dim3(8192, 2), 256>>>(qh, kh, qn_s, qn_b, kn_s, kn_b);

    // 4. flash attention -> att
    flash_h<<<dim3(8, 64), 256, FL_SMEM>>>(qh, kh, vh, att);

    // 5. O projection + residual (f32 out)
    gemm_h<1><<<dim3(8, 32), 256, GE_SMEM>>>(att, wo, bo, x, res, 1024, 1024, 1024, 0, 1024);

    // 6. LN2 -> xn
    ln_kernel<<<4096, 256>>>(res, ln2_s, ln2_b, xn);

    // 7. fused FFN-up + GeGLU -> h (M=4096, N=4096)
    ffn_gemm<<<dim3(64, 32), 256, FF_SMEM>>>(xn, w12, bsc + 4096, hbuf);

    // 8. Down projection + residual -> d_out (M=4096, N=1024, K=4096)
    gemm_h<1><<<dim3(8, 32), 256, GE_SMEM>>>(hbuf, w3, b3, res, out, 4096, 4096, 1024, 0, 1024);
}

// round 16
// speedup vs baseline: 1.0968x; 1.0174x over previous
#include <cuda_runtime.h>
#include <cuda_fp16.h>
#include <math.h>
#include <stdint.h>

#define EPSF 1e-6f

// Problem constants: B=4, S=1024, D=1024, H=16, DH=64, F=4096, M=B*S=4096
__device__ float g_xn  [4096 * 1024 / 2];    // xn (half)
__device__ float g_qkv [6 * 1024 * 1024];    // q|k|v (half, 3 x 4M halves)
__device__ float g_att [2 * 1024 * 1024];    // attn_out (half)
__device__ float g_res [4096 * 1024];        // residual after attention (f32)
__device__ float g_big [16 * 1024 * 1024];   // h (half, 16M halves) + spare
__device__ float g_wt  [8 * 1024 * 1024];    // half weights, native [K][N] (16M halves)
__device__ float g_bias[16384];              // b_qkv (3072) @0, b12 (8192) @4096

// ---------------------------------------------------------------------------
// Helpers
// ---------------------------------------------------------------------------
__device__ __forceinline__ void cp_async16(uint32_t dst, const void* src)
{
    asm volatile("cp.async.cg.shared.global [%0], [%1], 16;\n" :: "r"(dst), "l"(src));
}
__device__ __forceinline__ void cp_commit() { asm volatile("cp.async.commit_group;\n"); }
__device__ __forceinline__ void cp_wait0()  { asm volatile("cp.async.wait_group 0;\n"); }

__device__ __forceinline__ uint32_t smem_u32(const void* p)
{
    uint32_t a;
    asm("{ .reg .u64 t; cvta.to.shared.u64 t, %1; cvt.u32.u64 %0, t; }" : "=r"(a) : "l"(p));
    return a;
}
__device__ __forceinline__ void ldsm4(uint32_t& r0, uint32_t& r1, uint32_t& r2, uint32_t& r3,
                                      uint32_t a)
{
    asm volatile("ldmatrix.sync.aligned.m8n8.x4.shared.b16 {%0,%1,%2,%3}, [%4];"
                 : "=r"(r0), "=r"(r1), "=r"(r2), "=r"(r3) : "r"(a));
}
__device__ __forceinline__ void ldsm4_t(uint32_t& r0, uint32_t& r1, uint32_t& r2, uint32_t& r3,
                                        uint32_t a)
{
    asm volatile("ldmatrix.sync.aligned.m8n8.x4.trans.shared.b16 {%0,%1,%2,%3}, [%4];"
                 : "=r"(r0), "=r"(r1), "=r"(r2), "=r"(r3) : "r"(a));
}
__device__ __forceinline__ void mma_h(float c[4], const uint32_t a[4], const uint32_t b[2])
{
    asm volatile(
        "mma.sync.aligned.m16n8k16.row.col.f32.f16.f16.f32 "
        "{%0,%1,%2,%3}, {%4,%5,%6,%7}, {%8,%9}, {%0,%1,%2,%3};\n"
        : "+f"(c[0]), "+f"(c[1]), "+f"(c[2]), "+f"(c[3])
        : "r"(a[0]), "r"(a[1]), "r"(a[2]), "r"(a[3]), "r"(b[0]), "r"(b[1]));
}

__device__ __forceinline__ float gelu_t(float x)
{
    return 0.5f * x * (1.f + tanhf(0.7978845608028654f * (x + 0.044715f * x * x * x)));
}

// ---------------------------------------------------------------------------
// Dense fp16 GEMM: BM=128 BN=128 BK=64, 8 warps (64x32), double buffer.
// A [M][K] stride-72; B native [K][N] stride-136 + ldsm.trans.
// MODE 0: half out, segmented (QKV). Fused QK-norm: for segments 0/1 the
//         epilogue LayerNorms each 64-wide head before storing.
// MODE 1: float out = acc + bias + Res (ldc = segStride).
// ---------------------------------------------------------------------------
#define GE_A_STAGE (128 * 72 * 2)                // 18432 B
#define GE_B_STAGE (64 * 136 * 2)                // 17408 B
#define GE_SMEM (2 * (GE_A_STAGE + GE_B_STAGE))  // 71680 B

template <int MODE>
__global__ __launch_bounds__(256) void gemm_h(
    const __half* __restrict__ A, const __half* __restrict__ B,
    const float* __restrict__ bias, const float* __restrict__ Res,
    void* __restrict__ Cv, int K, int lda, int ldb, int segW, int segStride,
    const float* __restrict__ qn_s, const float* __restrict__ qn_b,
    const float* __restrict__ kn_s, const float* __restrict__ kn_b)
{
    extern __shared__ __half gsm[];
    const uint32_t sA = smem_u32(gsm);
    const uint32_t sB = sA + 2 * GE_A_STAGE;

    const int t    = threadIdx.x;
    const int lane = t & 31;
    const int warp = t >> 5;
    const size_t m0 = (size_t)blockIdx.y * 128;
    const size_t n0 = (size_t)blockIdx.x * 128;
    const int wm = (warp >> 2) * 64;
    const int wn = (warp & 3) * 32;

    uint32_t dA[4], dB[4];
    const __half* aS[4];
    const __half* bS[4];
    #pragma unroll
    for (int i = 0; i < 4; i++) {
        const int ia = t + 256 * i;
        const int rowA = ia >> 3, cA = ia & 7;
        dA[i] = (uint32_t)(rowA * 72 + cA * 8) * 2;
        aS[i] = A + (m0 + rowA) * lda + cA * 8;
        const int rowB = ia >> 4, cB = ia & 15;
        dB[i] = (uint32_t)(rowB * 136 + cB * 8) * 2;
        bS[i] = B + (size_t)rowB * ldb + n0 + cB * 8;
    }

    const int lq = lane >> 3, lr = lane & 7;
    uint32_t aAddr[4];
    #pragma unroll
    for (int mt = 0; mt < 4; mt++)
        aAddr[mt] = sA + (uint32_t)((wm + mt * 16 + ((lq & 1) << 3) + lr) * 72 + ((lq >> 1) << 3)) * 2;
    const uint32_t bBase = sB + (uint32_t)((((lq & 1) << 3) + lr) * 136 + wn + ((lq >> 1) << 3)) * 2;

    float acc[4][4][4];
    #pragma unroll
    for (int mt = 0; mt < 4; mt++)
        #pragma unroll
        for (int nt = 0; nt < 4; nt++)
            #pragma unroll
            for (int i = 0; i < 4; i++) acc[mt][nt][i] = 0.f;

    #pragma unroll
    for (int i = 0; i < 4; i++) {
        cp_async16(sA + dA[i], aS[i]);
        cp_async16(sB + dB[i], bS[i]);
    }
    cp_commit();

    const int nIter = K >> 6;
    for (int it = 0; it < nIter; ++it) {
        cp_wait0();
        __syncthreads();
        const int buf = it & 1;
        if (it + 1 < nIter) {
            const int k0 = (it + 1) << 6;
            const uint32_t offA = (buf ^ 1) * GE_A_STAGE;
            const uint32_t offB = (buf ^ 1) * GE_B_STAGE;
            #pragma unroll
            for (int i = 0; i < 4; i++) {
                cp_async16(sA + offA + dA[i], aS[i] + k0);
                cp_async16(sB + offB + dB[i], bS[i] + (size_t)k0 * ldb);
            }
            cp_commit();
        }
        const uint32_t offA = buf * GE_A_STAGE;
        const uint32_t offB = buf * GE_B_STAGE;
        #pragma unroll
        for (int ks = 0; ks < 4; ks++) {
            uint32_t af[4][4];
            #pragma unroll
            for (int mt = 0; mt < 4; mt++)
                ldsm4(af[mt][0], af[mt][1], af[mt][2], af[mt][3], aAddr[mt] + offA + ks * 32);
            uint32_t bf[4][2];
            #pragma unroll
            for (int p = 0; p < 2; p++)
                ldsm4_t(bf[2 * p][0], bf[2 * p][1], bf[2 * p + 1][0], bf[2 * p + 1][1],
                        bBase + offB + (uint32_t)(ks * 16 * 136 + p * 16) * 2);
            #pragma unroll
            for (int mt = 0; mt < 4; mt++)
                #pragma unroll
                for (int nt = 0; nt < 4; nt++)
                    mma_h(acc[mt][nt], af[mt], bf[nt]);
        }
        // no trailing barrier: next top barrier orders overwrite
    }

    if (MODE == 0) {
        const int seg  = (int)(n0 / segW);
        const int ncol = (int)(n0 % segW);
        // add bias in f32
        #pragma unroll
        for (int mt = 0; mt < 4; mt++)
            #pragma unroll
            for (int nt = 0; nt < 4; nt++) {
                const int c = wn + nt * 8 + (lane & 3) * 2;
                const float b0 = bias[n0 + c], b1 = bias[n0 + c + 1];
                acc[mt][nt][0] += b0; acc[mt][nt][1] += b1;
                acc[mt][nt][2] += b0; acc[mt][nt][3] += b1;
            }

        if (seg < 2) {
            // Fused QK-norm over each 64-wide head (2 heads per 128-col tile).
            const float* nsc = seg ? kn_s : qn_s;
            const float* nbi = seg ? kn_b : qn_b;
            __syncthreads();                       // safe smem reuse
            float* sred = (float*)gsm;             // [head2][half2][row128][2] = 4KB
            const int head = wn >> 6;              // 0|1
            const int half = (wn >> 5) & 1;        // 0|1
            #pragma unroll
            for (int mt = 0; mt < 4; mt++) {
                float s0 = 0.f, q0 = 0.f, s1 = 0.f, q1 = 0.f;
                #pragma unroll
                for (int nt = 0; nt < 4; nt++) {
                    s0 += acc[mt][nt][0] + acc[mt][nt][1];
                    q0 += acc[mt][nt][0] * acc[mt][nt][0] + acc[mt][nt][1] * acc[mt][nt][1];
                    s1 += acc[mt][nt][2] + acc[mt][nt][3];
                    q1 += acc[mt][nt][2] * acc[mt][nt][2] + acc[mt][nt][3] * acc[mt][nt][3];
                }
                s0 += __shfl_xor_sync(0xffffffffu, s0, 1);
                s0 += __shfl_xor_sync(0xffffffffu, s0, 2);
                q0 += __shfl_xor_sync(0xffffffffu, q0, 1);
                q0 += __shfl_xor_sync(0xffffffffu, q0, 2);
                s1 += __shfl_xor_sync(0xffffffffu, s1, 1);
                s1 += __shfl_xor_sync(0xffffffffu, s1, 2);
                q1 += __shfl_xor_sync(0xffffffffu, q1, 1);
                q1 += __shfl_xor_sync(0xffffffffu, q1, 2);
                if ((lane & 3) == 0) {
                    const int r0 = wm + mt * 16 + (lane >> 2);
                    const int i0 = (((head << 1) + half) * 128 + r0) * 2;
                    sred[i0] = s0; sred[i0 + 1] = q0;
                    const int i1 = (((head << 1) + half) * 128 + r0 + 8) * 2;
                    sred[i1] = s1; sred[i1 + 1] = q1;
                }
            }
            __syncthreads();
            __half* Cb = (__half*)Cv + (size_t)seg * segStride + m0 * segW + ncol;
            #pragma unroll
            for (int mt = 0; mt < 4; mt++) {
                const int r0 = wm + mt * 16 + (lane >> 2);
                const int hb = (head << 1) * 128 * 2;
                float sum0 = sred[hb + r0 * 2]       + sred[hb + 256 + r0 * 2];
                float sq0  = sred[hb + r0 * 2 + 1]   + sred[hb + 256 + r0 * 2 + 1];
                float sum1 = sred[hb + (r0 + 8) * 2]     + sred[hb + 256 + (r0 + 8) * 2];
                float sq1  = sred[hb + (r0 + 8) * 2 + 1] + sred[hb + 256 + (r0 + 8) * 2 + 1];
                const float mean0 = sum0 * (1.f / 64.f);
                const float inv0v = rsqrtf(sq0 * (1.f / 64.f) - mean0 * mean0 + EPSF);
                const float mean1 = sum1 * (1.f / 64.f);
                const float inv1v = rsqrtf(sq1 * (1.f / 64.f) - mean1 * mean1 + EPSF);
                #pragma unroll
                for (int nt = 0; nt < 4; nt++) {
                    const int c = wn + nt * 8 + (lane & 3) * 2;
                    const int cd = ncol + c;      // flat h*64+d index
                    const float sc0 = nsc[cd], sc1 = nsc[cd + 1];
                    const float bi0 = nbi[cd], bi1 = nbi[cd + 1];
                    *(__half2*)(Cb + (size_t)r0 * segW + c) = __floats2half2_rn(
                        (acc[mt][nt][0] - mean0) * inv0v * sc0 + bi0,
                        (acc[mt][nt][1] - mean0) * inv0v * sc1 + bi1);
                    *(__half2*)(Cb + (size_t)(r0 + 8) * segW + c) = __floats2half2_rn(
                        (acc[mt][nt][2] - mean1) * inv1v * sc0 + bi0,
                        (acc[mt][nt][3] - mean1) * inv1v * sc1 + bi1);
                }
            }
        } else {
            __half* Cb = (__half*)Cv + (size_t)seg * segStride + m0 * segW + ncol;
            #pragma unroll
            for (int mt = 0; mt < 4; mt++) {
                const int r0 = wm + mt * 16 + (lane >> 2);
                #pragma unroll
                for (int nt = 0; nt < 4; nt++) {
                    const int c = wn + nt * 8 + (lane & 3) * 2;
                    *(__half2*)(Cb + (size_t)r0 * segW + c) =
                        __floats2half2_rn(acc[mt][nt][0], acc[mt][nt][1]);
                    *(__half2*)(Cb + (size_t)(r0 + 8) * segW + c) =
                        __floats2half2_rn(acc[mt][nt][2], acc[mt][nt][3]);
                }
            }
        }
    } else {
        const int ldc = segStride;
        float* Cb = (float*)Cv + m0 * ldc + n0;
        const float* Rb = Res + m0 * ldc + n0;
        #pragma unroll
        for (int mt = 0; mt < 4; mt++) {
            const int r0 = wm + mt * 16 + (lane >> 2);
            #pragma unroll
            for (int nt = 0; nt < 4; nt++) {
                const int c = wn + nt * 8 + (lane & 3) * 2;
                const float b0 = bias[n0 + c], b1 = bias[n0 + c + 1];
                float2 ra = *(const float2*)(Rb + (size_t)r0 * ldc + c);
                float2 rb = *(const float2*)(Rb + (size_t)(r0 + 8) * ldc + c);
                *(float2*)(Cb + (size_t)r0 * ldc + c) =
                    make_float2(acc[mt][nt][0] + b0 + ra.x, acc[mt][nt][1] + b1 + ra.y);
                *(float2*)(Cb + (size_t)(r0 + 8) * ldc + c) =
                    make_float2(acc[mt][nt][2] + b0 + rb.x, acc[mt][nt][3] + b1 + rb.y);
            }
        }
    }
}

// ---------------------------------------------------------------------------
// Fused FFN-up + GeGLU (round-14/15 proven).
// ---------------------------------------------------------------------------
#define FF_A_STAGE (128 * 72 * 2)                // 18432 B
#define FF_B_STAGE (2 * 64 * 72 * 2)             // 18432 B
#define FF_SMEM (2 * (FF_A_STAGE + FF_B_STAGE))  // 73728 B

__global__ __launch_bounds__(256) void ffn_gemm(
    const __half* __restrict__ A, const __half* __restrict__ W12,
    const float* __restrict__ b12, __half* __restrict__ Hout)
{
    extern __shared__ __half fsm[];
    const uint32_t sA = smem_u32(fsm);
    const uint32_t sB = sA + 2 * FF_A_STAGE;

    const int t    = threadIdx.x;
    const int lane = t & 31;
    const int warp = t >> 5;
    const size_t m0 = (size_t)blockIdx.y * 128;
    const size_t n0 = (size_t)blockIdx.x * 64;
    const int wm = (warp >> 1) * 32;
    const int wn = (warp & 1) * 32;

    uint32_t dA[4], dB[4];
    const __half* aS[4];
    const __half* bS[4];
    #pragma unroll
    for (int i = 0; i < 4; i++) {
        const int ia = t + 256 * i;
        const int rowA = ia >> 3, cA = ia & 7;
        dA[i] = (uint32_t)(rowA * 72 + cA * 8) * 2;
        aS[i] = A + (m0 + rowA) * 1024 + cA * 8;
        const int tile = ia >> 9;
        const int i9 = ia & 511;
        const int rowB = i9 >> 3, cB = i9 & 7;
        dB[i] = (uint32_t)(tile * 64 * 72 + rowB * 72 + cB * 8) * 2;
        bS[i] = W12 + (size_t)rowB * 8192 + n0 + tile * 4096 + cB * 8;
    }

    const int lq = lane >> 3, lr = lane & 7;
    uint32_t aAddr[2];
    #pragma unroll
    for (int mt = 0; mt < 2; mt++)
        aAddr[mt] = sA + (uint32_t)((wm + mt * 16 + ((lq & 1) << 3) + lr) * 72 + ((lq >> 1) << 3)) * 2;
    const uint32_t bB0 = sB + (uint32_t)((((lq & 1) << 3) + lr) * 72 + wn + ((lq >> 1) << 3)) * 2;
    const uint32_t bB1 = bB0 + (uint32_t)(64 * 72) * 2;

    float acc1[2][4][4], acc2[2][4][4];
    #pragma unroll
    for (int mt = 0; mt < 2; mt++)
        #pragma unroll
        for (int nt = 0; nt < 4; nt++)
            #pragma unroll
            for (int i = 0; i < 4; i++) { acc1[mt][nt][i] = 0.f; acc2[mt][nt][i] = 0.f; }

    #pragma unroll
    for (int i = 0; i < 4; i++) {
        cp_async16(sA + dA[i], aS[i]);
        cp_async16(sB + dB[i], bS[i]);
    }
    cp_commit();

    const int nIter = 16;   // K = 1024
    for (int it = 0; it < nIter; ++it) {
        cp_wait0();
        __syncthreads();
        const int buf = it & 1;
        if (it + 1 < nIter) {
            const int k0 = (it + 1) << 6;
            const uint32_t offA = (buf ^ 1) * FF_A_STAGE;
            const uint32_t offB = (buf ^ 1) * FF_B_STAGE;
            #pragma unroll
            for (int i = 0; i < 4; i++) {
                cp_async16(sA + offA + dA[i], aS[i] + k0);
                cp_async16(sB + offB + dB[i], bS[i] + (size_t)k0 * 8192);
            }
            cp_commit();
        }
        const uint32_t offA = buf * FF_A_STAGE;
        const uint32_t offB = buf * FF_B_STAGE;
        #pragma unroll
        for (int ks = 0; ks < 4; ks++) {
            uint32_t af[2][4];
            #pragma unroll
            for (int mt = 0; mt < 2; mt++)
                ldsm4(af[mt][0], af[mt][1], af[mt][2], af[mt][3], aAddr[mt] + offA + ks * 32);
            uint32_t bf1[4][2], bf2[4][2];
            #pragma unroll
            for (int p = 0; p < 2; p++) {
                const uint32_t kOff = (uint32_t)(ks * 16 * 72 + p * 16) * 2;
                ldsm4_t(bf1[2 * p][0], bf1[2 * p][1], bf1[2 * p + 1][0], bf1[2 * p + 1][1],
                        bB0 + offB + kOff);
                ldsm4_t(bf2[2 * p][0], bf2[2 * p][1], bf2[2 * p + 1][0], bf2[2 * p + 1][1],
                        bB1 + offB + kOff);
            }
            #pragma unroll
            for (int mt = 0; mt < 2; mt++)
                #pragma unroll
                for (int nt = 0; nt < 4; nt++) {
                    mma_h(acc1[mt][nt], af[mt], bf1[nt]);
                    mma_h(acc2[mt][nt], af[mt], bf2[nt]);
                }
        }
    }

    __half* Hb = Hout + m0 * 4096 + n0;
    #pragma unroll
    for (int mt = 0; mt < 2; mt++) {
        const int r0 = wm + mt * 16 + (lane >> 2);
        #pragma unroll
        for (int nt = 0; nt < 4; nt++) {
            const int c = wn + nt * 8 + (lane & 3) * 2;
            const float p0 = b12[n0 + c], p1 = b12[n0 + c + 1];
            const float q0 = b12[4096 + n0 + c], q1 = b12[4096 + n0 + c + 1];
            float h00 = (acc1[mt][nt][0] + p0) * gelu_t(acc2[mt][nt][0] + q0);
            float h01 = (acc1[mt][nt][1] + p1) * gelu_t(acc2[mt][nt][1] + q1);
            float h10 = (acc1[mt][nt][2] + p0) * gelu_t(acc2[mt][nt][2] + q0);
            float h11 = (acc1[mt][nt][3] + p1) * gelu_t(acc2[mt][nt][3] + q1);
            *(__half2*)(Hb + (size_t)r0 * 4096 + c)       = __floats2half2_rn(h00, h01);
            *(__half2*)(Hb + (size_t)(r0 + 8) * 4096 + c) = __floats2half2_rn(h10, h11);
        }
    }
}

// ---------------------------------------------------------------------------
// Unified prep: z = 0..6 -> f32->f16 weight copies; z = 7 -> bias concat.
// ---------------------------------------------------------------------------
__global__ __launch_bounds__(256) void prep_all(
    const float* __restrict__ Wq, const float* __restrict__ Wk,
    const float* __restrict__ Wv, const float* __restrict__ Wo,
    const float* __restrict__ W1, const float* __restrict__ W2,
    const float* __restrict__ W3,
    __half* __restrict__ wqkv, __half* __restrict__ wo,
    __half* __restrict__ w12, __half* __restrict__ w3,
    float* __restrict__ bdst,
    const float* __restrict__ bq, const float* __restrict__ bk,
    const float* __restrict__ bv, const float* __restrict__ b1,
    const float* __restrict__ b2)
{
    const int z = blockIdx.z;
    if (z == 7) {
        const int i = blockIdx.x * 256 + threadIdx.x;
        if (i < 1024)       bdst[i] = bq[i];
        else if (i < 2048)  bdst[i] = bk[i - 1024];
        else if (i < 3072)  bdst[i] = bv[i - 2048];
        else if (i < 3072 + 4096) bdst[1024 + i] = b1[i - 3072];
        else if (i < 3072 + 8192) bdst[1024 + i] = b2[i - 7168];
        return;
    }
    const float* src;
    __half* dst;
    int C, ld;
    size_t total;
    switch (z) {
        case 0: src = Wq; dst = wqkv;        C = 1024; ld = 3072; total = 1048576; break;
        case 1: src = Wk; dst = wqkv + 1024; C = 1024; ld = 3072; total = 1048576; break;
        case 2: src = Wv; dst = wqkv + 2048; C = 1024; ld = 3072; total = 1048576; break;
        case 3: src = Wo; dst = wo;          C = 1024; ld = 1024; total = 1048576; break;
        case 4: src = W1; dst = w12;         C = 4096; ld = 8192; total = 4194304; break;
        case 5: src = W2; dst = w12 + 4096;  C = 4096; ld = 8192; total = 4194304; break;
        default: src = W3; dst = w3;         C = 1024; ld = 1024; total = 4194304; break;
    }
    const size_t i = ((size_t)blockIdx.x * 256 + threadIdx.x) * 8;
    if (i >= total) return;
    const int r = (int)(i / C);
    const int c = (int)(i % C);
    float4 v0 = *(const float4*)(src + i);
    float4 v1 = *(const float4*)(src + i + 4);
    __half2 h[4];
    h[0] = __floats2half2_rn(v0.x, v0.y);
    h[1] = __floats2half2_rn(v0.z, v0.w);
    h[2] = __floats2half2_rn(v1.x, v1.y);
    h[3] = __floats2half2_rn(v1.z, v1.w);
    *(uint4*)(dst + (size_t)r * ld + c) = *(uint4*)h;
}

// ---------------------------------------------------------------------------
// Flash attention fp16 (proven).
// ---------------------------------------------------------------------------
#define FL_SMEM ((128 * 72 + 128 * 72 + 128 * 136) * 2)

__global__ __launch_bounds__(256) void flash_h(
    const __half* __restrict__ q, const __half* __restrict__ k,
    const __half* __restrict__ v, __half* __restrict__ out)
{
    extern __shared__ __half smh[];
    const uint32_t sK = smem_u32(smh);
    const uint32_t sV = sK + 128 * 72 * 2;
    const uint32_t sP = sV + 128 * 72 * 2;
    __half* sPh = smh + 128 * 72 + 128 * 72;

    const int t = threadIdx.x;
    const int lane = t & 31, warp = t >> 5;
    const int lq = lane >> 3, lr = lane & 7;
    const int bh = blockIdx.y, b = bh >> 4, h = bh & 15;
    const int q0 = blockIdx.x * 128;
    const int wm = warp * 16;

    const __half* qb = q + ((size_t)b * 1024 + q0) * 1024 + h * 64;
    const __half* kb = k + ((size_t)b << 20) + h * 64;
    const __half* vb = v + ((size_t)b << 20) + h * 64;

    {
        #pragma unroll
        for (int i = 0; i < 4; i++) {
            const int idx = t + 256 * i;
            const int row = idx >> 3, c = idx & 7;
            cp_async16(sP + (uint32_t)(row * 72 + c * 8) * 2, qb + (size_t)row * 1024 + c * 8);
        }
    }
    cp_commit(); cp_wait0(); __syncthreads();

    uint32_t qf[4][4];
    {
        const uint32_t a0 = sP + (uint32_t)((wm + ((lq & 1) << 3) + lr) * 72 + ((lq >> 1) << 3)) * 2;
        #pragma unroll
        for (int ks = 0; ks < 4; ks++)
            ldsm4(qf[ks][0], qf[ks][1], qf[ks][2], qf[ks][3], a0 + ks * 32);
    }
    __syncthreads();

    float o[8][4];
    #pragma unroll
    for (int i = 0; i < 8; i++)
        #pragma unroll
        for (int j = 0; j < 4; j++) o[i][j] = 0.f;
    float m0 = -1e30f, m1 = -1e30f, l0 = 0.f, l1 = 0.f;

    const uint32_t aP = sP + (uint32_t)((wm + ((lq & 1) << 3) + lr) * 136 + ((lq >> 1) << 3)) * 2;

    for (int it = 0; it < 8; ++it) {
        const int kt0 = it * 128;
        #pragma unroll
        for (int i = 0; i < 4; i++) {
            const int idx = t + 256 * i;
            const int row = idx >> 3, c = idx & 7;
            cp_async16(sK + (uint32_t)(row * 72 + c * 8) * 2,
                       kb + (size_t)(kt0 + row) * 1024 + c * 8);
            cp_async16(sV + (uint32_t)(row * 72 + c * 8) * 2,
                       vb + (size_t)(kt0 + row) * 1024 + c * 8);
        }
        cp_commit(); cp_wait0(); __syncthreads();

        float s[16][4];
        #pragma unroll
        for (int i = 0; i < 16; i++)
            #pragma unroll
            for (int j = 0; j < 4; j++) s[i][j] = 0.f;
        #pragma unroll
        for (int ks = 0; ks < 4; ks++) {
            uint32_t bf[16][2];
            #pragma unroll
            for (int p = 0; p < 8; p++) {
                const uint32_t addr =
                    sK + (uint32_t)((p * 16 + ((lq >> 1) << 3) + lr) * 72 + ((lq & 1) << 3)) * 2
                       + ks * 32;
                ldsm4(bf[2 * p][0], bf[2 * p][1], bf[2 * p + 1][0], bf[2 * p + 1][1], addr);
            }
            #pragma unroll
            for (int nt = 0; nt < 16; nt++)
                mma_h(s[nt], qf[ks], bf[nt]);
        }

        float c0v = -1e30f, c1v = -1e30f;
        #pragma unroll
        for (int nt = 0; nt < 16; nt++) {
            c0v = fmaxf(c0v, fmaxf(s[nt][0], s[nt][1]));
            c1v = fmaxf(c1v, fmaxf(s[nt][2], s[nt][3]));
        }
        c0v = fmaxf(c0v, __shfl_xor_sync(0xffffffffu, c0v, 1));
        c0v = fmaxf(c0v, __shfl_xor_sync(0xffffffffu, c0v, 2));
        c1v = fmaxf(c1v, __shfl_xor_sync(0xffffffffu, c1v, 1));
        c1v = fmaxf(c1v, __shfl_xor_sync(0xffffffffu, c1v, 2));
        const float m0n = fmaxf(m0, c0v * 0.125f);
        const float m1n = fmaxf(m1, c1v * 0.125f);
        const float cor0 = __expf(m0 - m0n);
        const float cor1 = __expf(m1 - m1n);
        m0 = m0n; m1 = m1n;
        float sum0 = 0.f, sum1 = 0.f;
        {
            __half* pr0 = sPh + (size_t)(wm + (lane >> 2)) * 136 + 2 * (lane & 3);
            __half* pr1 = pr0 + 8 * 136;
            #pragma unroll
            for (int nt = 0; nt < 16; nt++) {
                float p0 = __expf(fmaf(0.125f, s[nt][0], -m0n));
                float p1 = __expf(fmaf(0.125f, s[nt][1], -m0n));
                float p2 = __expf(fmaf(0.125f, s[nt][2], -m1n));
                float p3 = __expf(fmaf(0.125f, s[nt][3], -m1n));
                sum0 += p0 + p1; sum1 += p2 + p3;
                *(__half2*)(pr0 + nt * 8) = __floats2half2_rn(p0, p1);
                *(__half2*)(pr1 + nt * 8) = __floats2half2_rn(p2, p3);
            }
        }
        sum0 += __shfl_xor_sync(0xffffffffu, sum0, 1);
        sum0 += __shfl_xor_sync(0xffffffffu, sum0, 2);
        sum1 += __shfl_xor_sync(0xffffffffu, sum1, 1);
        sum1 += __shfl_xor_sync(0xffffffffu, sum1, 2);
        l0 = l0 * cor0 + sum0;
        l1 = l1 * cor1 + sum1;
        #pragma unroll
        for (int nt = 0; nt < 8; nt++) {
            o[nt][0] *= cor0; o[nt][1] *= cor0;
            o[nt][2] *= cor1; o[nt][3] *= cor1;
        }
        __syncwarp();

        #pragma unroll
        for (int ks2 = 0; ks2 < 8; ks2++) {
            uint32_t af[4];
            ldsm4(af[0], af[1], af[2], af[3], aP + ks2 * 32);
            uint32_t bf2[8][2];
            #pragma unroll
            for (int p = 0; p < 4; p++) {
                const uint32_t addr =
                    sV + (uint32_t)((ks2 * 16 + ((lq & 1) << 3) + lr) * 72
                                    + p * 16 + ((lq >> 1) << 3)) * 2;
                ldsm4_t(bf2[2 * p][0], bf2[2 * p][1], bf2[2 * p + 1][0], bf2[2 * p + 1][1], addr);
            }
            #pragma unroll
            for (int nt = 0; nt < 8; nt++)
                mma_h(o[nt], af, bf2[nt]);
        }
        __syncthreads();
    }

    const float inv0 = 1.f / l0, inv1 = 1.f / l1;
    __half* ob = out + ((size_t)b * 1024 + q0 + wm + (lane >> 2)) * 1024 + h * 64 + 2 * (lane & 3);
    #pragma unroll
    for (int nt = 0; nt < 8; nt++) {
        *(__half2*)(ob + nt * 8) = __floats2half2_rn(o[nt][0] * inv0, o[nt][1] * inv0);
        *(__half2*)(ob + 8 * 1024 + nt * 8) = __floats2half2_rn(o[nt][2] * inv1, o[nt][3] * inv1);
    }
}

// ---------------------------------------------------------------------------
// LayerNorm over D=1024, f32 in -> half out.
// ---------------------------------------------------------------------------
__global__ __launch_bounds__(256) void ln_kernel(
    const float* __restrict__ in, const float* __restrict__ sc,
    const float* __restrict__ bi, __half* __restrict__ out)
{
    const int row = blockIdx.x;
    const int t = threadIdx.x;
    const float4* x4 = (const float4*)(in + (size_t)row * 1024);
    float4 v = x4[t];
    float s  = v.x + v.y + v.z + v.w;
    float ss = v.x * v.x + v.y * v.y + v.z * v.z + v.w * v.w;
    #pragma unroll
    for (int o = 16; o; o >>= 1) {
        s  += __shfl_xor_sync(0xffffffffu, s,  o);
        ss += __shfl_xor_sync(0xffffffffu, ss, o);
    }
    __shared__ float sred[8], ssred[8];
    if ((t & 31) == 0) { sred[t >> 5] = s; ssred[t >> 5] = ss; }
    __syncthreads();
    float tot = 0.f, tots = 0.f;
    #pragma unroll
    for (int w = 0; w < 8; w++) { tot += sred[w]; tots += ssred[w]; }
    const float mean = tot * (1.f / 1024.f);
    const float var  = tots * (1.f / 1024.f) - mean * mean;
    const float inv  = rsqrtf(var + EPSF);
    float4 sv = ((const float4*)sc)[t];
    float4 bv = ((const float4*)bi)[t];
    __half2* o2 = (__half2*)(out + (size_t)row * 1024);
    o2[t * 2 + 0] = __floats2half2_rn((v.x - mean) * inv * sv.x + bv.x,
                                      (v.y - mean) * inv * sv.y + bv.y);
    o2[t * 2 + 1] = __floats2half2_rn((v.z - mean) * inv * sv.z + bv.z,
                                      (v.w - mean) * inv * sv.w + bv.w);
}

// ---------------------------------------------------------------------------
// Launch
// ---------------------------------------------------------------------------
extern "C" void kernel_launch(void* const* d_in, const int* in_sizes, int n_in,
                              void* d_out, int out_size)
{
    (void)in_sizes; (void)n_in; (void)out_size;
    const float* x     = (const float*)d_in[0];
    const float* ln1_s = (const float*)d_in[2];
    const float* ln1_b = (const float*)d_in[3];
    const float* Wq    = (const float*)d_in[4];
    const float* bq    = (const float*)d_in[5];
    const float* Wk    = (const float*)d_in[6];
    const float* bk    = (const float*)d_in[7];
    const float* Wv    = (const float*)d_in[8];
    const float* bv    = (const float*)d_in[9];
    const float* qn_s  = (const float*)d_in[10];
    const float* qn_b  = (const float*)d_in[11];
    const float* kn_s  = (const float*)d_in[12];
    const float* kn_b  = (const float*)d_in[13];
    const float* Wo    = (const float*)d_in[14];
    const float* bo    = (const float*)d_in[15];
    const float* ln2_s = (const float*)d_in[16];
    const float* ln2_b = (const float*)d_in[17];
    const float* W1    = (const float*)d_in[18];
    const float* b1    = (const float*)d_in[19];
    const float* W2    = (const float*)d_in[20];
    const float* b2    = (const float*)d_in[21];
    const float* W3    = (const float*)d_in[22];
    const float* b3    = (const float*)d_in[23];

    void *p_xn, *p_qkv, *p_att, *p_res, *p_big, *p_wt, *p_bias;
    cudaGetSymbolAddress(&p_xn,   g_xn);
    cudaGetSymbolAddress(&p_qkv,  g_qkv);
    cudaGetSymbolAddress(&p_att,  g_att);
    cudaGetSymbolAddress(&p_res,  g_res);
    cudaGetSymbolAddress(&p_big,  g_big);
    cudaGetSymbolAddress(&p_wt,   g_wt);
    cudaGetSymbolAddress(&p_bias, g_bias);

    __half* xn  = (__half*)p_xn;
    __half* qkv = (__half*)p_qkv;
    __half* qh  = qkv;
    __half* kh  = qkv + (size_t)4194304;
    __half* vh  = qkv + (size_t)8388608;
    __half* att = (__half*)p_att;
    float*  res = (float*)p_res;
    __half* wt  = (__half*)p_wt;
    __half* hbuf = (__half*)p_big;
    float*  bsc = (float*)p_bias;
    float* out = (float*)d_out;

    cudaFuncSetAttribute(flash_h, cudaFuncAttributeMaxDynamicSharedMemorySize, FL_SMEM);
    cudaFuncSetAttribute(gemm_h<0>, cudaFuncAttributeMaxDynamicSharedMemorySize, GE_SMEM);
    cudaFuncSetAttribute(gemm_h<1>, cudaFuncAttributeMaxDynamicSharedMemorySize, GE_SMEM);
    cudaFuncSetAttribute(ffn_gemm, cudaFuncAttributeMaxDynamicSharedMemorySize, FF_SMEM);

    const size_t MB1 = 1024 * 1024;
    __half* wqkv = wt;                 // [1024][3072]
    __half* wo   = wt + 3 * MB1;       // [1024][1024]
    __half* w12  = wt + 4 * MB1;       // [1024][8192]
    __half* w3   = wt + 12 * MB1;      // [4096][1024]

    // 0. unified prep
    prep_all<<<dim3(2048, 1, 8), 256>>>(Wq, Wk, Wv, Wo, W1, W2, W3,
                                        wqkv, wo, w12, w3,
                                        bsc, bq, bk, bv, b1, b2);

    // 1. LN1 -> xn
    ln_kernel<<<4096, 256>>>(x, ln1_s, ln1_b, xn);

    // 2. fused QKV projection + fused QK-norm (seg 0/1)
    gemm_h<0><<<dim3(24, 32), 256, GE_SMEM>>>(xn, wqkv, bsc, nullptr, qkv,
                                              1024, 1024, 3072, 1024, 4194304,
                                              qn_s, qn_b, kn_s, kn_b);

    // 3. flash attention -> att
    flash_h<<<dim3(8, 64), 256, FL_SMEM>>>(qh, kh, vh, att);

    // 4. O projection + residual (f32 out)
    gemm_h<1><<<dim3(8, 32), 256, GE_SMEM>>>(att, wo, bo, x, res, 1024, 1024, 1024, 0, 1024,
                                             nullptr, nullptr, nullptr, nullptr);

    // 5. LN2 -> xn
    ln_kernel<<<4096, 256>>>(res, ln2_s, ln2_b, xn);

    // 6. fused FFN-up + GeGLU -> h (M=4096, N=4096)
    ffn_gemm<<<dim3(64, 32), 256, FF_SMEM>>>(xn, w12, bsc + 4096, hbuf);

    // 7. Down projection + residual -> d_out (M=4096, N=1024, K=4096)
    gemm_h<1><<<dim3(8, 32), 256, GE_SMEM>>>(hbuf, w3, b3, res, out, 4096, 4096, 1024, 0, 1024,
                                             nullptr, nullptr, nullptr, nullptr);
}

// round 17
// speedup vs baseline: 1.1131x; 1.0148x over previous
#include <cuda_runtime.h>
#include <cuda_fp16.h>
#include <math.h>
#include <stdint.h>

#define EPSF 1e-6f

// Problem constants: B=4, S=1024, D=1024, H=16, DH=64, F=4096, M=B*S=4096
__device__ float g_xn  [4096 * 1024 / 2];    // xn (half)
__device__ float g_qkv [6 * 1024 * 1024];    // q|k|v (half, 3 x 4M halves)
__device__ float g_att [2 * 1024 * 1024];    // attn_out (half)
__device__ float g_res [4096 * 1024];        // residual after attention (f32)
__device__ float g_big [16 * 1024 * 1024];   // h (half, 16M halves) + spare
__device__ float g_wt  [8 * 1024 * 1024];    // half weights, native [K][N] (16M halves)
__device__ float g_bias[16384];              // b_qkv (3072) @0, b12 (8192) @4096

// ---------------------------------------------------------------------------
// Helpers
// ---------------------------------------------------------------------------
__device__ __forceinline__ void cp_async16(uint32_t dst, const void* src)
{
    asm volatile("cp.async.cg.shared.global [%0], [%1], 16;\n" :: "r"(dst), "l"(src));
}
__device__ __forceinline__ void cp_commit() { asm volatile("cp.async.commit_group;\n"); }
__device__ __forceinline__ void cp_wait0()  { asm volatile("cp.async.wait_group 0;\n"); }

__device__ __forceinline__ uint32_t smem_u32(const void* p)
{
    uint32_t a;
    asm("{ .reg .u64 t; cvta.to.shared.u64 t, %1; cvt.u32.u64 %0, t; }" : "=r"(a) : "l"(p));
    return a;
}
__device__ __forceinline__ void ldsm4(uint32_t& r0, uint32_t& r1, uint32_t& r2, uint32_t& r3,
                                      uint32_t a)
{
    asm volatile("ldmatrix.sync.aligned.m8n8.x4.shared.b16 {%0,%1,%2,%3}, [%4];"
                 : "=r"(r0), "=r"(r1), "=r"(r2), "=r"(r3) : "r"(a));
}
__device__ __forceinline__ void ldsm4_t(uint32_t& r0, uint32_t& r1, uint32_t& r2, uint32_t& r3,
                                        uint32_t a)
{
    asm volatile("ldmatrix.sync.aligned.m8n8.x4.trans.shared.b16 {%0,%1,%2,%3}, [%4];"
                 : "=r"(r0), "=r"(r1), "=r"(r2), "=r"(r3) : "r"(a));
}
__device__ __forceinline__ void mma_h(float c[4], const uint32_t a[4], const uint32_t b[2])
{
    asm volatile(
        "mma.sync.aligned.m16n8k16.row.col.f32.f16.f16.f32 "
        "{%0,%1,%2,%3}, {%4,%5,%6,%7}, {%8,%9}, {%0,%1,%2,%3};\n"
        : "+f"(c[0]), "+f"(c[1]), "+f"(c[2]), "+f"(c[3])
        : "r"(a[0]), "r"(a[1]), "r"(a[2]), "r"(a[3]), "r"(b[0]), "r"(b[1]));
}

__device__ __forceinline__ float gelu_t(float x)
{
    return 0.5f * x * (1.f + tanhf(0.7978845608028654f * (x + 0.044715f * x * x * x)));
}

// ---------------------------------------------------------------------------
// Dense fp16 GEMM (round-16 proven): BM=128 BN=128 BK=64, 8 warps (64x32),
// double buffer. MODE 0: half out, segmented (QKV) + fused QK-norm for
// segments 0/1. MODE 1: float out = acc + bias + Res.
// ---------------------------------------------------------------------------
#define GE_A_STAGE (128 * 72 * 2)                // 18432 B
#define GE_B_STAGE (64 * 136 * 2)                // 17408 B
#define GE_SMEM (2 * (GE_A_STAGE + GE_B_STAGE))  // 71680 B

template <int MODE>
__global__ __launch_bounds__(256) void gemm_h(
    const __half* __restrict__ A, const __half* __restrict__ B,
    const float* __restrict__ bias, const float* __restrict__ Res,
    void* __restrict__ Cv, int K, int lda, int ldb, int segW, int segStride,
    const float* __restrict__ qn_s, const float* __restrict__ qn_b,
    const float* __restrict__ kn_s, const float* __restrict__ kn_b)
{
    extern __shared__ __half gsm[];
    const uint32_t sA = smem_u32(gsm);
    const uint32_t sB = sA + 2 * GE_A_STAGE;

    const int t    = threadIdx.x;
    const int lane = t & 31;
    const int warp = t >> 5;
    const size_t m0 = (size_t)blockIdx.y * 128;
    const size_t n0 = (size_t)blockIdx.x * 128;
    const int wm = (warp >> 2) * 64;
    const int wn = (warp & 3) * 32;

    uint32_t dA[4], dB[4];
    const __half* aS[4];
    const __half* bS[4];
    #pragma unroll
    for (int i = 0; i < 4; i++) {
        const int ia = t + 256 * i;
        const int rowA = ia >> 3, cA = ia & 7;
        dA[i] = (uint32_t)(rowA * 72 + cA * 8) * 2;
        aS[i] = A + (m0 + rowA) * lda + cA * 8;
        const int rowB = ia >> 4, cB = ia & 15;
        dB[i] = (uint32_t)(rowB * 136 + cB * 8) * 2;
        bS[i] = B + (size_t)rowB * ldb + n0 + cB * 8;
    }

    const int lq = lane >> 3, lr = lane & 7;
    uint32_t aAddr[4];
    #pragma unroll
    for (int mt = 0; mt < 4; mt++)
        aAddr[mt] = sA + (uint32_t)((wm + mt * 16 + ((lq & 1) << 3) + lr) * 72 + ((lq >> 1) << 3)) * 2;
    const uint32_t bBase = sB + (uint32_t)((((lq & 1) << 3) + lr) * 136 + wn + ((lq >> 1) << 3)) * 2;

    float acc[4][4][4];
    #pragma unroll
    for (int mt = 0; mt < 4; mt++)
        #pragma unroll
        for (int nt = 0; nt < 4; nt++)
            #pragma unroll
            for (int i = 0; i < 4; i++) acc[mt][nt][i] = 0.f;

    #pragma unroll
    for (int i = 0; i < 4; i++) {
        cp_async16(sA + dA[i], aS[i]);
        cp_async16(sB + dB[i], bS[i]);
    }
    cp_commit();

    const int nIter = K >> 6;
    for (int it = 0; it < nIter; ++it) {
        cp_wait0();
        __syncthreads();
        const int buf = it & 1;
        if (it + 1 < nIter) {
            const int k0 = (it + 1) << 6;
            const uint32_t offA = (buf ^ 1) * GE_A_STAGE;
            const uint32_t offB = (buf ^ 1) * GE_B_STAGE;
            #pragma unroll
            for (int i = 0; i < 4; i++) {
                cp_async16(sA + offA + dA[i], aS[i] + k0);
                cp_async16(sB + offB + dB[i], bS[i] + (size_t)k0 * ldb);
            }
            cp_commit();
        }
        const uint32_t offA = buf * GE_A_STAGE;
        const uint32_t offB = buf * GE_B_STAGE;
        #pragma unroll
        for (int ks = 0; ks < 4; ks++) {
            uint32_t af[4][4];
            #pragma unroll
            for (int mt = 0; mt < 4; mt++)
                ldsm4(af[mt][0], af[mt][1], af[mt][2], af[mt][3], aAddr[mt] + offA + ks * 32);
            uint32_t bf[4][2];
            #pragma unroll
            for (int p = 0; p < 2; p++)
                ldsm4_t(bf[2 * p][0], bf[2 * p][1], bf[2 * p + 1][0], bf[2 * p + 1][1],
                        bBase + offB + (uint32_t)(ks * 16 * 136 + p * 16) * 2);
            #pragma unroll
            for (int mt = 0; mt < 4; mt++)
                #pragma unroll
                for (int nt = 0; nt < 4; nt++)
                    mma_h(acc[mt][nt], af[mt], bf[nt]);
        }
    }

    if (MODE == 0) {
        const int seg  = (int)(n0 / segW);
        const int ncol = (int)(n0 % segW);
        #pragma unroll
        for (int mt = 0; mt < 4; mt++)
            #pragma unroll
            for (int nt = 0; nt < 4; nt++) {
                const int c = wn + nt * 8 + (lane & 3) * 2;
                const float b0 = bias[n0 + c], b1 = bias[n0 + c + 1];
                acc[mt][nt][0] += b0; acc[mt][nt][1] += b1;
                acc[mt][nt][2] += b0; acc[mt][nt][3] += b1;
            }

        if (seg < 2) {
            const float* nsc = seg ? kn_s : qn_s;
            const float* nbi = seg ? kn_b : qn_b;
            __syncthreads();
            float* sred = (float*)gsm;
            const int head = wn >> 6;
            const int half = (wn >> 5) & 1;
            #pragma unroll
            for (int mt = 0; mt < 4; mt++) {
                float s0 = 0.f, q0 = 0.f, s1 = 0.f, q1 = 0.f;
                #pragma unroll
                for (int nt = 0; nt < 4; nt++) {
                    s0 += acc[mt][nt][0] + acc[mt][nt][1];
                    q0 += acc[mt][nt][0] * acc[mt][nt][0] + acc[mt][nt][1] * acc[mt][nt][1];
                    s1 += acc[mt][nt][2] + acc[mt][nt][3];
                    q1 += acc[mt][nt][2] * acc[mt][nt][2] + acc[mt][nt][3] * acc[mt][nt][3];
                }
                s0 += __shfl_xor_sync(0xffffffffu, s0, 1);
                s0 += __shfl_xor_sync(0xffffffffu, s0, 2);
                q0 += __shfl_xor_sync(0xffffffffu, q0, 1);
                q0 += __shfl_xor_sync(0xffffffffu, q0, 2);
                s1 += __shfl_xor_sync(0xffffffffu, s1, 1);
                s1 += __shfl_xor_sync(0xffffffffu, s1, 2);
                q1 += __shfl_xor_sync(0xffffffffu, q1, 1);
                q1 += __shfl_xor_sync(0xffffffffu, q1, 2);
                if ((lane & 3) == 0) {
                    const int r0 = wm + mt * 16 + (lane >> 2);
                    const int i0 = (((head << 1) + half) * 128 + r0) * 2;
                    sred[i0] = s0; sred[i0 + 1] = q0;
                    const int i1 = (((head << 1) + half) * 128 + r0 + 8) * 2;
                    sred[i1] = s1; sred[i1 + 1] = q1;
                }
            }
            __syncthreads();
            __half* Cb = (__half*)Cv + (size_t)seg * segStride + m0 * segW + ncol;
            #pragma unroll
            for (int mt = 0; mt < 4; mt++) {
                const int r0 = wm + mt * 16 + (lane >> 2);
                const int hb = (head << 1) * 128 * 2;
                float sum0 = sred[hb + r0 * 2]       + sred[hb + 256 + r0 * 2];
                float sq0  = sred[hb + r0 * 2 + 1]   + sred[hb + 256 + r0 * 2 + 1];
                float sum1 = sred[hb + (r0 + 8) * 2]     + sred[hb + 256 + (r0 + 8) * 2];
                float sq1  = sred[hb + (r0 + 8) * 2 + 1] + sred[hb + 256 + (r0 + 8) * 2 + 1];
                const float mean0 = sum0 * (1.f / 64.f);
                const float inv0v = rsqrtf(sq0 * (1.f / 64.f) - mean0 * mean0 + EPSF);
                const float mean1 = sum1 * (1.f / 64.f);
                const float inv1v = rsqrtf(sq1 * (1.f / 64.f) - mean1 * mean1 + EPSF);
                #pragma unroll
                for (int nt = 0; nt < 4; nt++) {
                    const int c = wn + nt * 8 + (lane & 3) * 2;
                    const int cd = ncol + c;
                    const float sc0 = nsc[cd], sc1 = nsc[cd + 1];
                    const float bi0 = nbi[cd], bi1 = nbi[cd + 1];
                    *(__half2*)(Cb + (size_t)r0 * segW + c) = __floats2half2_rn(
                        (acc[mt][nt][0] - mean0) * inv0v * sc0 + bi0,
                        (acc[mt][nt][1] - mean0) * inv0v * sc1 + bi1);
                    *(__half2*)(Cb + (size_t)(r0 + 8) * segW + c) = __floats2half2_rn(
                        (acc[mt][nt][2] - mean1) * inv1v * sc0 + bi0,
                        (acc[mt][nt][3] - mean1) * inv1v * sc1 + bi1);
                }
            }
        } else {
            __half* Cb = (__half*)Cv + (size_t)seg * segStride + m0 * segW + ncol;
            #pragma unroll
            for (int mt = 0; mt < 4; mt++) {
                const int r0 = wm + mt * 16 + (lane >> 2);
                #pragma unroll
                for (int nt = 0; nt < 4; nt++) {
                    const int c = wn + nt * 8 + (lane & 3) * 2;
                    *(__half2*)(Cb + (size_t)r0 * segW + c) =
                        __floats2half2_rn(acc[mt][nt][0], acc[mt][nt][1]);
                    *(__half2*)(Cb + (size_t)(r0 + 8) * segW + c) =
                        __floats2half2_rn(acc[mt][nt][2], acc[mt][nt][3]);
                }
            }
        }
    } else {
        const int ldc = segStride;
        float* Cb = (float*)Cv + m0 * ldc + n0;
        const float* Rb = Res + m0 * ldc + n0;
        #pragma unroll
        for (int mt = 0; mt < 4; mt++) {
            const int r0 = wm + mt * 16 + (lane >> 2);
            #pragma unroll
            for (int nt = 0; nt < 4; nt++) {
                const int c = wn + nt * 8 + (lane & 3) * 2;
                const float b0 = bias[n0 + c], b1 = bias[n0 + c + 1];
                float2 ra = *(const float2*)(Rb + (size_t)r0 * ldc + c);
                float2 rb = *(const float2*)(Rb + (size_t)(r0 + 8) * ldc + c);
                *(float2*)(Cb + (size_t)r0 * ldc + c) =
                    make_float2(acc[mt][nt][0] + b0 + ra.x, acc[mt][nt][1] + b1 + ra.y);
                *(float2*)(Cb + (size_t)(r0 + 8) * ldc + c) =
                    make_float2(acc[mt][nt][2] + b0 + rb.x, acc[mt][nt][3] + b1 + rb.y);
            }
        }
    }
}

// ---------------------------------------------------------------------------
// Fused FFN-up + GeGLU (round-14/15 proven).
// ---------------------------------------------------------------------------
#define FF_A_STAGE (128 * 72 * 2)                // 18432 B
#define FF_B_STAGE (2 * 64 * 72 * 2)             // 18432 B
#define FF_SMEM (2 * (FF_A_STAGE + FF_B_STAGE))  // 73728 B

__global__ __launch_bounds__(256) void ffn_gemm(
    const __half* __restrict__ A, const __half* __restrict__ W12,
    const float* __restrict__ b12, __half* __restrict__ Hout)
{
    extern __shared__ __half fsm[];
    const uint32_t sA = smem_u32(fsm);
    const uint32_t sB = sA + 2 * FF_A_STAGE;

    const int t    = threadIdx.x;
    const int lane = t & 31;
    const int warp = t >> 5;
    const size_t m0 = (size_t)blockIdx.y * 128;
    const size_t n0 = (size_t)blockIdx.x * 64;
    const int wm = (warp >> 1) * 32;
    const int wn = (warp & 1) * 32;

    uint32_t dA[4], dB[4];
    const __half* aS[4];
    const __half* bS[4];
    #pragma unroll
    for (int i = 0; i < 4; i++) {
        const int ia = t + 256 * i;
        const int rowA = ia >> 3, cA = ia & 7;
        dA[i] = (uint32_t)(rowA * 72 + cA * 8) * 2;
        aS[i] = A + (m0 + rowA) * 1024 + cA * 8;
        const int tile = ia >> 9;
        const int i9 = ia & 511;
        const int rowB = i9 >> 3, cB = i9 & 7;
        dB[i] = (uint32_t)(tile * 64 * 72 + rowB * 72 + cB * 8) * 2;
        bS[i] = W12 + (size_t)rowB * 8192 + n0 + tile * 4096 + cB * 8;
    }

    const int lq = lane >> 3, lr = lane & 7;
    uint32_t aAddr[2];
    #pragma unroll
    for (int mt = 0; mt < 2; mt++)
        aAddr[mt] = sA + (uint32_t)((wm + mt * 16 + ((lq & 1) << 3) + lr) * 72 + ((lq >> 1) << 3)) * 2;
    const uint32_t bB0 = sB + (uint32_t)((((lq & 1) << 3) + lr) * 72 + wn + ((lq >> 1) << 3)) * 2;
    const uint32_t bB1 = bB0 + (uint32_t)(64 * 72) * 2;

    float acc1[2][4][4], acc2[2][4][4];
    #pragma unroll
    for (int mt = 0; mt < 2; mt++)
        #pragma unroll
        for (int nt = 0; nt < 4; nt++)
            #pragma unroll
            for (int i = 0; i < 4; i++) { acc1[mt][nt][i] = 0.f; acc2[mt][nt][i] = 0.f; }

    #pragma unroll
    for (int i = 0; i < 4; i++) {
        cp_async16(sA + dA[i], aS[i]);
        cp_async16(sB + dB[i], bS[i]);
    }
    cp_commit();

    const int nIter = 16;   // K = 1024
    for (int it = 0; it < nIter; ++it) {
        cp_wait0();
        __syncthreads();
        const int buf = it & 1;
        if (it + 1 < nIter) {
            const int k0 = (it + 1) << 6;
            const uint32_t offA = (buf ^ 1) * FF_A_STAGE;
            const uint32_t offB = (buf ^ 1) * FF_B_STAGE;
            #pragma unroll
            for (int i = 0; i < 4; i++) {
                cp_async16(sA + offA + dA[i], aS[i] + k0);
                cp_async16(sB + offB + dB[i], bS[i] + (size_t)k0 * 8192);
            }
            cp_commit();
        }
        const uint32_t offA = buf * FF_A_STAGE;
        const uint32_t offB = buf * FF_B_STAGE;
        #pragma unroll
        for (int ks = 0; ks < 4; ks++) {
            uint32_t af[2][4];
            #pragma unroll
            for (int mt = 0; mt < 2; mt++)
                ldsm4(af[mt][0], af[mt][1], af[mt][2], af[mt][3], aAddr[mt] + offA + ks * 32);
            uint32_t bf1[4][2], bf2[4][2];
            #pragma unroll
            for (int p = 0; p < 2; p++) {
                const uint32_t kOff = (uint32_t)(ks * 16 * 72 + p * 16) * 2;
                ldsm4_t(bf1[2 * p][0], bf1[2 * p][1], bf1[2 * p + 1][0], bf1[2 * p + 1][1],
                        bB0 + offB + kOff);
                ldsm4_t(bf2[2 * p][0], bf2[2 * p][1], bf2[2 * p + 1][0], bf2[2 * p + 1][1],
                        bB1 + offB + kOff);
            }
            #pragma unroll
            for (int mt = 0; mt < 2; mt++)
                #pragma unroll
                for (int nt = 0; nt < 4; nt++) {
                    mma_h(acc1[mt][nt], af[mt], bf1[nt]);
                    mma_h(acc2[mt][nt], af[mt], bf2[nt]);
                }
        }
    }

    __half* Hb = Hout + m0 * 4096 + n0;
    #pragma unroll
    for (int mt = 0; mt < 2; mt++) {
        const int r0 = wm + mt * 16 + (lane >> 2);
        #pragma unroll
        for (int nt = 0; nt < 4; nt++) {
            const int c = wn + nt * 8 + (lane & 3) * 2;
            const float p0 = b12[n0 + c], p1 = b12[n0 + c + 1];
            const float q0 = b12[4096 + n0 + c], q1 = b12[4096 + n0 + c + 1];
            float h00 = (acc1[mt][nt][0] + p0) * gelu_t(acc2[mt][nt][0] + q0);
            float h01 = (acc1[mt][nt][1] + p1) * gelu_t(acc2[mt][nt][1] + q1);
            float h10 = (acc1[mt][nt][2] + p0) * gelu_t(acc2[mt][nt][2] + q0);
            float h11 = (acc1[mt][nt][3] + p1) * gelu_t(acc2[mt][nt][3] + q1);
            *(__half2*)(Hb + (size_t)r0 * 4096 + c)       = __floats2half2_rn(h00, h01);
            *(__half2*)(Hb + (size_t)(r0 + 8) * 4096 + c) = __floats2half2_rn(h10, h11);
        }
    }
}

// ---------------------------------------------------------------------------
// Unified prep: z = 0..6 -> f32->f16 weight copies; z = 7 -> bias concat.
// ---------------------------------------------------------------------------
__global__ __launch_bounds__(256) void prep_all(
    const float* __restrict__ Wq, const float* __restrict__ Wk,
    const float* __restrict__ Wv, const float* __restrict__ Wo,
    const float* __restrict__ W1, const float* __restrict__ W2,
    const float* __restrict__ W3,
    __half* __restrict__ wqkv, __half* __restrict__ wo,
    __half* __restrict__ w12, __half* __restrict__ w3,
    float* __restrict__ bdst,
    const float* __restrict__ bq, const float* __restrict__ bk,
    const float* __restrict__ bv, const float* __restrict__ b1,
    const float* __restrict__ b2)
{
    const int z = blockIdx.z;
    if (z == 7) {
        const int i = blockIdx.x * 256 + threadIdx.x;
        if (i < 1024)       bdst[i] = bq[i];
        else if (i < 2048)  bdst[i] = bk[i - 1024];
        else if (i < 3072)  bdst[i] = bv[i - 2048];
        else if (i < 3072 + 4096) bdst[1024 + i] = b1[i - 3072];
        else if (i < 3072 + 8192) bdst[1024 + i] = b2[i - 7168];
        return;
    }
    const float* src;
    __half* dst;
    int C, ld;
    size_t total;
    switch (z) {
        case 0: src = Wq; dst = wqkv;        C = 1024; ld = 3072; total = 1048576; break;
        case 1: src = Wk; dst = wqkv + 1024; C = 1024; ld = 3072; total = 1048576; break;
        case 2: src = Wv; dst = wqkv + 2048; C = 1024; ld = 3072; total = 1048576; break;
        case 3: src = Wo; dst = wo;          C = 1024; ld = 1024; total = 1048576; break;
        case 4: src = W1; dst = w12;         C = 4096; ld = 8192; total = 4194304; break;
        case 5: src = W2; dst = w12 + 4096;  C = 4096; ld = 8192; total = 4194304; break;
        default: src = W3; dst = w3;         C = 1024; ld = 1024; total = 4194304; break;
    }
    const size_t i = ((size_t)blockIdx.x * 256 + threadIdx.x) * 8;
    if (i >= total) return;
    const int r = (int)(i / C);
    const int c = (int)(i % C);
    float4 v0 = *(const float4*)(src + i);
    float4 v1 = *(const float4*)(src + i + 4);
    __half2 h[4];
    h[0] = __floats2half2_rn(v0.x, v0.y);
    h[1] = __floats2half2_rn(v0.z, v0.w);
    h[2] = __floats2half2_rn(v1.x, v1.y);
    h[3] = __floats2half2_rn(v1.z, v1.w);
    *(uint4*)(dst + (size_t)r * ld + c) = *(uint4*)h;
}

// ---------------------------------------------------------------------------
// Flash attention fp16 with DOUBLE-BUFFERED K/V tiles: the next key tile's
// cp.async is issued before computing the current one, hiding tile-load
// latency (flash was 1 CTA/SM, issue 27.9% -> load-latency bound).
// smem: [K0|V0][K1|V1][P]; P doubles as Q staging.
// ---------------------------------------------------------------------------
#define FL_KV    (128 * 72 * 2)                  // 18432 B per K or V tile
#define FL_STAGE (2 * FL_KV)                     // 36864 B per stage
#define FL_SMEM  (2 * FL_STAGE + 128 * 136 * 2)  // 108544 B

__global__ __launch_bounds__(256) void flash_h(
    const __half* __restrict__ q, const __half* __restrict__ k,
    const __half* __restrict__ v, __half* __restrict__ out)
{
    extern __shared__ __half smh[];
    const uint32_t sK = smem_u32(smh);
    const uint32_t sV = sK + FL_KV;
    const uint32_t sP = sK + 2 * FL_STAGE;
    __half* sPh = smh + 2 * FL_STAGE / 2;

    const int t = threadIdx.x;
    const int lane = t & 31, warp = t >> 5;
    const int lq = lane >> 3, lr = lane & 7;
    const int bh = blockIdx.y, b = bh >> 4, h = bh & 15;
    const int q0 = blockIdx.x * 128;
    const int wm = warp * 16;

    const __half* qb = q + ((size_t)b * 1024 + q0) * 1024 + h * 64;
    const __half* kb = k + ((size_t)b << 20) + h * 64;
    const __half* vb = v + ((size_t)b << 20) + h * 64;

    // stage Q into P region
    {
        #pragma unroll
        for (int i = 0; i < 4; i++) {
            const int idx = t + 256 * i;
            const int row = idx >> 3, c = idx & 7;
            cp_async16(sP + (uint32_t)(row * 72 + c * 8) * 2, qb + (size_t)row * 1024 + c * 8);
        }
    }
    cp_commit(); cp_wait0(); __syncthreads();

    uint32_t qf[4][4];
    {
        const uint32_t a0 = sP + (uint32_t)((wm + ((lq & 1) << 3) + lr) * 72 + ((lq >> 1) << 3)) * 2;
        #pragma unroll
        for (int ks = 0; ks < 4; ks++)
            ldsm4(qf[ks][0], qf[ks][1], qf[ks][2], qf[ks][3], a0 + ks * 32);
    }
    __syncthreads();

    // preload K/V tile 0 into stage 0
    #pragma unroll
    for (int i = 0; i < 4; i++) {
        const int idx = t + 256 * i;
        const int row = idx >> 3, c = idx & 7;
        const uint32_t off = (uint32_t)(row * 72 + c * 8) * 2;
        cp_async16(sK + off, kb + (size_t)row * 1024 + c * 8);
        cp_async16(sV + off, vb + (size_t)row * 1024 + c * 8);
    }
    cp_commit();

    float o[8][4];
    #pragma unroll
    for (int i = 0; i < 8; i++)
        #pragma unroll
        for (int j = 0; j < 4; j++) o[i][j] = 0.f;
    float m0 = -1e30f, m1 = -1e30f, l0 = 0.f, l1 = 0.f;

    const uint32_t aP = sP + (uint32_t)((wm + ((lq & 1) << 3) + lr) * 136 + ((lq >> 1) << 3)) * 2;

    for (int it = 0; it < 8; ++it) {
        cp_wait0();
        __syncthreads();
        const uint32_t stg = (uint32_t)(it & 1) * FL_STAGE;
        if (it + 1 < 8) {
            const int kt1 = (it + 1) * 128;
            const uint32_t nstg = (uint32_t)((it + 1) & 1) * FL_STAGE;
            #pragma unroll
            for (int i = 0; i < 4; i++) {
                const int idx = t + 256 * i;
                const int row = idx >> 3, c = idx & 7;
                const uint32_t off = (uint32_t)(row * 72 + c * 8) * 2;
                cp_async16(sK + nstg + off, kb + (size_t)(kt1 + row) * 1024 + c * 8);
                cp_async16(sV + nstg + off, vb + (size_t)(kt1 + row) * 1024 + c * 8);
            }
            cp_commit();
        }

        float s[16][4];
        #pragma unroll
        for (int i = 0; i < 16; i++)
            #pragma unroll
            for (int j = 0; j < 4; j++) s[i][j] = 0.f;
        #pragma unroll
        for (int ks = 0; ks < 4; ks++) {
            uint32_t bf[16][2];
            #pragma unroll
            for (int p = 0; p < 8; p++) {
                const uint32_t addr =
                    sK + stg + (uint32_t)((p * 16 + ((lq >> 1) << 3) + lr) * 72 + ((lq & 1) << 3)) * 2
                       + ks * 32;
                ldsm4(bf[2 * p][0], bf[2 * p][1], bf[2 * p + 1][0], bf[2 * p + 1][1], addr);
            }
            #pragma unroll
            for (int nt = 0; nt < 16; nt++)
                mma_h(s[nt], qf[ks], bf[nt]);
        }

        float c0v = -1e30f, c1v = -1e30f;
        #pragma unroll
        for (int nt = 0; nt < 16; nt++) {
            c0v = fmaxf(c0v, fmaxf(s[nt][0], s[nt][1]));
            c1v = fmaxf(c1v, fmaxf(s[nt][2], s[nt][3]));
        }
        c0v = fmaxf(c0v, __shfl_xor_sync(0xffffffffu, c0v, 1));
        c0v = fmaxf(c0v, __shfl_xor_sync(0xffffffffu, c0v, 2));
        c1v = fmaxf(c1v, __shfl_xor_sync(0xffffffffu, c1v, 1));
        c1v = fmaxf(c1v, __shfl_xor_sync(0xffffffffu, c1v, 2));
        const float m0n = fmaxf(m0, c0v * 0.125f);
        const float m1n = fmaxf(m1, c1v * 0.125f);
        const float cor0 = __expf(m0 - m0n);
        const float cor1 = __expf(m1 - m1n);
        m0 = m0n; m1 = m1n;
        float sum0 = 0.f, sum1 = 0.f;
        {
            __half* pr0 = sPh + (size_t)(wm + (lane >> 2)) * 136 + 2 * (lane & 3);
            __half* pr1 = pr0 + 8 * 136;
            #pragma unroll
            for (int nt = 0; nt < 16; nt++) {
                float p0 = __expf(fmaf(0.125f, s[nt][0], -m0n));
                float p1 = __expf(fmaf(0.125f, s[nt][1], -m0n));
                float p2 = __expf(fmaf(0.125f, s[nt][2], -m1n));
                float p3 = __expf(fmaf(0.125f, s[nt][3], -m1n));
                sum0 += p0 + p1; sum1 += p2 + p3;
                *(__half2*)(pr0 + nt * 8) = __floats2half2_rn(p0, p1);
                *(__half2*)(pr1 + nt * 8) = __floats2half2_rn(p2, p3);
            }
        }
        sum0 += __shfl_xor_sync(0xffffffffu, sum0, 1);
        sum0 += __shfl_xor_sync(0xffffffffu, sum0, 2);
        sum1 += __shfl_xor_sync(0xffffffffu, sum1, 1);
        sum1 += __shfl_xor_sync(0xffffffffu, sum1, 2);
        l0 = l0 * cor0 + sum0;
        l1 = l1 * cor1 + sum1;
        #pragma unroll
        for (int nt = 0; nt < 8; nt++) {
            o[nt][0] *= cor0; o[nt][1] *= cor0;
            o[nt][2] *= cor1; o[nt][3] *= cor1;
        }
        __syncwarp();

        #pragma unroll
        for (int ks2 = 0; ks2 < 8; ks2++) {
            uint32_t af[4];
            ldsm4(af[0], af[1], af[2], af[3], aP + ks2 * 32);
            uint32_t bf2[8][2];
            #pragma unroll
            for (int p = 0; p < 4; p++) {
                const uint32_t addr =
                    sV + stg + (uint32_t)((ks2 * 16 + ((lq & 1) << 3) + lr) * 72
                                          + p * 16 + ((lq >> 1) << 3)) * 2;
                ldsm4_t(bf2[2 * p][0], bf2[2 * p][1], bf2[2 * p + 1][0], bf2[2 * p + 1][1], addr);
            }
            #pragma unroll
            for (int nt = 0; nt < 8; nt++)
                mma_h(o[nt], af, bf2[nt]);
        }
        // no end barrier: double-buffered; next iteration's top barrier orders
        // overwrite, and the P region is warp-private.
    }

    const float inv0 = 1.f / l0, inv1 = 1.f / l1;
    __half* ob = out + ((size_t)b * 1024 + q0 + wm + (lane >> 2)) * 1024 + h * 64 + 2 * (lane & 3);
    #pragma unroll
    for (int nt = 0; nt < 8; nt++) {
        *(__half2*)(ob + nt * 8) = __floats2half2_rn(o[nt][0] * inv0, o[nt][1] * inv0);
        *(__half2*)(ob + 8 * 1024 + nt * 8) = __floats2half2_rn(o[nt][2] * inv1, o[nt][3] * inv1);
    }
}

// ---------------------------------------------------------------------------
// LayerNorm over D=1024, f32 in -> half out.
// ---------------------------------------------------------------------------
__global__ __launch_bounds__(256) void ln_kernel(
    const float* __restrict__ in, const float* __restrict__ sc,
    const float* __restrict__ bi, __half* __restrict__ out)
{
    const int row = blockIdx.x;
    const int t = threadIdx.x;
    const float4* x4 = (const float4*)(in + (size_t)row * 1024);
    float4 v = x4[t];
    float s  = v.x + v.y + v.z + v.w;
    float ss = v.x * v.x + v.y * v.y + v.z * v.z + v.w * v.w;
    #pragma unroll
    for (int o = 16; o; o >>= 1) {
        s  += __shfl_xor_sync(0xffffffffu, s,  o);
        ss += __shfl_xor_sync(0xffffffffu, ss, o);
    }
    __shared__ float sred[8], ssred[8];
    if ((t & 31) == 0) { sred[t >> 5] = s; ssred[t >> 5] = ss; }
    __syncthreads();
    float tot = 0.f, tots = 0.f;
    #pragma unroll
    for (int w = 0; w < 8; w++) { tot += sred[w]; tots += ssred[w]; }
    const float mean = tot * (1.f / 1024.f);
    const float var  = tots * (1.f / 1024.f) - mean * mean;
    const float inv  = rsqrtf(var + EPSF);
    float4 sv = ((const float4*)sc)[t];
    float4 bv = ((const float4*)bi)[t];
    __half2* o2 = (__half2*)(out + (size_t)row * 1024);
    o2[t * 2 + 0] = __floats2half2_rn((v.x - mean) * inv * sv.x + bv.x,
                                      (v.y - mean) * inv * sv.y + bv.y);
    o2[t * 2 + 1] = __floats2half2_rn((v.z - mean) * inv * sv.z + bv.z,
                                      (v.w - mean) * inv * sv.w + bv.w);
}

// ---------------------------------------------------------------------------
// Launch
// ---------------------------------------------------------------------------
extern "C" void kernel_launch(void* const* d_in, const int* in_sizes, int n_in,
                              void* d_out, int out_size)
{
    (void)in_sizes; (void)n_in; (void)out_size;
    const float* x     = (const float*)d_in[0];
    const float* ln1_s = (const float*)d_in[2];
    const float* ln1_b = (const float*)d_in[3];
    const float* Wq    = (const float*)d_in[4];
    const float* bq    = (const float*)d_in[5];
    const float* Wk    = (const float*)d_in[6];
    const float* bk    = (const float*)d_in[7];
    const float* Wv    = (const float*)d_in[8];
    const float* bv    = (const float*)d_in[9];
    const float* qn_s  = (const float*)d_in[10];
    const float* qn_b  = (const float*)d_in[11];
    const float* kn_s  = (const float*)d_in[12];
    const float* kn_b  = (const float*)d_in[13];
    const float* Wo    = (const float*)d_in[14];
    const float* bo    = (const float*)d_in[15];
    const float* ln2_s = (const float*)d_in[16];
    const float* ln2_b = (const float*)d_in[17];
    const float* W1    = (const float*)d_in[18];
    const float* b1    = (const float*)d_in[19];
    const float* W2    = (const float*)d_in[20];
    const float* b2    = (const float*)d_in[21];
    const float* W3    = (const float*)d_in[22];
    const float* b3    = (const float*)d_in[23];

    void *p_xn, *p_qkv, *p_att, *p_res, *p_big, *p_wt, *p_bias;
    cudaGetSymbolAddress(&p_xn,   g_xn);
    cudaGetSymbolAddress(&p_qkv,  g_qkv);
    cudaGetSymbolAddress(&p_att,  g_att);
    cudaGetSymbolAddress(&p_res,  g_res);
    cudaGetSymbolAddress(&p_big,  g_big);
    cudaGetSymbolAddress(&p_wt,   g_wt);
    cudaGetSymbolAddress(&p_bias, g_bias);

    __half* xn  = (__half*)p_xn;
    __half* qkv = (__half*)p_qkv;
    __half* qh  = qkv;
    __half* kh  = qkv + (size_t)4194304;
    __half* vh  = qkv + (size_t)8388608;
    __half* att = (__half*)p_att;
    float*  res = (float*)p_res;
    __half* wt  = (__half*)p_wt;
    __half* hbuf = (__half*)p_big;
    float*  bsc = (float*)p_bias;
    float* out = (float*)d_out;

    cudaFuncSetAttribute(flash_h, cudaFuncAttributeMaxDynamicSharedMemorySize, FL_SMEM);
    cudaFuncSetAttribute(gemm_h<0>, cudaFuncAttributeMaxDynamicSharedMemorySize, GE_SMEM);
    cudaFuncSetAttribute(gemm_h<1>, cudaFuncAttributeMaxDynamicSharedMemorySize, GE_SMEM);
    cudaFuncSetAttribute(ffn_gemm, cudaFuncAttributeMaxDynamicSharedMemorySize, FF_SMEM);

    const size_t MB1 = 1024 * 1024;
    __half* wqkv = wt;                 // [1024][3072]
    __half* wo   = wt + 3 * MB1;       // [1024][1024]
    __half* w12  = wt + 4 * MB1;       // [1024][8192]
    __half* w3   = wt + 12 * MB1;      // [4096][1024]

    // 0. unified prep
    prep_all<<<dim3(2048, 1, 8), 256>>>(Wq, Wk, Wv, Wo, W1, W2, W3,
                                        wqkv, wo, w12, w3,
                                        bsc, bq, bk, bv, b1, b2);

    // 1. LN1 -> xn
    ln_kernel<<<4096, 256>>>(x, ln1_s, ln1_b, xn);

    // 2. fused QKV projection + fused QK-norm (seg 0/1)
    gemm_h<0><<<dim3(24, 32), 256, GE_SMEM>>>(xn, wqkv, bsc, nullptr, qkv,
                                              1024, 1024, 3072, 1024, 4194304,
                                              qn_s, qn_b, kn_s, kn_b);

    // 3. flash attention -> att
    flash_h<<<dim3(8, 64), 256, FL_SMEM>>>(qh, kh, vh, att);

    // 4. O projection + residual (f32 out)
    gemm_h<1><<<dim3(8, 32), 256, GE_SMEM>>>(att, wo, bo, x, res, 1024, 1024, 1024, 0, 1024,
                                             nullptr, nullptr, nullptr, nullptr);

    // 5. LN2 -> xn
    ln_kernel<<<4096, 256>>>(res, ln2_s, ln2_b, xn);

    // 6. fused FFN-up + GeGLU -> h (M=4096, N=4096)
    ffn_gemm<<<dim3(64, 32), 256, FF_SMEM>>>(xn, w12, bsc + 4096, hbuf);

    // 7. Down projection + residual -> d_out (M=4096, N=1024, K=4096)
    gemm_h<1><<<dim3(8, 32), 256, GE_SMEM>>>(hbuf, w3, b3, res, out, 4096, 4096, 1024, 0, 1024,
                                             nullptr, nullptr, nullptr, nullptr);
}